// round 1
// baseline (speedup 1.0000x reference)
#include <cuda_runtime.h>
#include <math.h>

// ---------------------------------------------------------------------------
// CompressiveEncoder forward, fp32.
// Shapes: B=8, T=512, D=512, H=8, DH=64, MEM=512, CMEM=128, LKV=1152, DFF=2048
// Output layout (fp32, 13172738 elems):
//   [0)          x            8*512*512      = 2097152
//   [2097152)    new_mems     4*8*512*512    = 8388608   (== per-layer LN1 out)
//   [10485760)   new_cmems    4*8*128*512    = 2097152   (== per-layer compressed)
//   [12582912)   aux scalar
//   [12582913)   zero scalar
//   [12582914)   attns_mean   512*1152       = 589824
// ---------------------------------------------------------------------------

#define OFF_MEMS   2097152L
#define OFF_CMEMS 10485760L
#define OFF_AUX   12582912L
#define OFF_ZERO  12582913L
#define OFF_ATTN  12582914L
#define ATTN_ELEMS 589824L

// -------------------- device scratch (static, no allocation) ---------------
__device__ float g_q    [8*512*512];          //  [b,t,512]  (heads along cols)
__device__ float g_kv   [8*1152*1024];        //  [b,1152,1024] k|v
__device__ float g_dots [8*8*512*1152];       //  attn logits / probs; reused for aux
__device__ float g_attno[8*512*512];          //  attention output (pre-Wo)
__device__ float g_xn2  [8*512*512];          //  LN2 out
__device__ float g_ffh  [8*512*2048];         //  FFN hidden
__device__ float g_convT[2048*512];           //  transposed conv weight
__device__ float g_ckcv [8*128*1024];         //  compressed @ Wkv
__device__ float g_o1   [8*8*512*64];         //  aux attn out (mem)
__device__ float g_o2   [8*8*512*64];         //  aux attn out (compressed)

// -------------------- small helpers ----------------------------------------
__device__ __forceinline__ float gelu_f(float v) {
    return 0.5f * v * (1.f + erff(v * 0.70710678118654752f));
}

// -------------------- generic batched GEMM ----------------------------------
// C[z] = A[z] @ B[z] (+epilogue).  TB: B stored [N,K] (row-major) -> use B^T.
// Per-operand batch offset: off = (z / zmod)*s1 + (z % zmod)*s2.
// EPI: 0 none, 1 +bias, 2 +bias + C(residual, read-modify-write), 3 gelu(.+bias)
template<int BM,int BN,int BK,int TM,int TN,int EPI,bool TB>
__global__ void __launch_bounds__((BM/TM)*(BN/TN))
gemm_k(const float* __restrict__ A, const float* __restrict__ B,
       float* __restrict__ C, int K, int lda, int ldb, int ldc,
       long sA1, long sA2, long sB1, long sB2, long sC1, long sC2, int zmod,
       const float* __restrict__ bias)
{
    constexpr int TX = BN / TN, TY = BM / TM, NT = TX * TY;
    const int z  = blockIdx.z;
    const int zh = z / zmod, zl = z - zh * zmod;
    A += zh * sA1 + zl * sA2;
    B += zh * sB1 + zl * sB2;
    C += zh * sC1 + zl * sC2;

    const int m0 = blockIdx.y * BM, n0 = blockIdx.x * BN;
    const int tid = threadIdx.x;
    const int tx = tid % TX, ty = tid / TX;

    __shared__ float As[BK][BM];
    __shared__ float Bs[BK][BN];

    float acc[TM][TN];
#pragma unroll
    for (int i = 0; i < TM; i++)
#pragma unroll
        for (int j = 0; j < TN; j++) acc[i][j] = 0.f;

    for (int k0 = 0; k0 < K; k0 += BK) {
#pragma unroll
        for (int i = tid; i < BM * BK; i += NT) {
            int r = i / BK, c = i % BK;
            As[c][r] = A[(long)(m0 + r) * lda + (k0 + c)];
        }
        if (!TB) {
#pragma unroll
            for (int i = tid; i < BK * BN; i += NT) {
                int r = i / BN, c = i % BN;
                Bs[r][c] = B[(long)(k0 + r) * ldb + (n0 + c)];
            }
        } else {
#pragma unroll
            for (int i = tid; i < BK * BN; i += NT) {
                int c = i / BK, r = i % BK;
                Bs[r][c] = B[(long)(n0 + c) * ldb + (k0 + r)];
            }
        }
        __syncthreads();
#pragma unroll
        for (int kk = 0; kk < BK; kk++) {
            float a[TM], b[TN];
#pragma unroll
            for (int i = 0; i < TM; i++) a[i] = As[kk][ty * TM + i];
#pragma unroll
            for (int j = 0; j < TN; j++) b[j] = Bs[kk][tx * TN + j];
#pragma unroll
            for (int i = 0; i < TM; i++)
#pragma unroll
                for (int j = 0; j < TN; j++)
                    acc[i][j] = fmaf(a[i], b[j], acc[i][j]);
        }
        __syncthreads();
    }

#pragma unroll
    for (int i = 0; i < TM; i++) {
        const int m = m0 + ty * TM + i;
#pragma unroll
        for (int j = 0; j < TN; j++) {
            const int n = n0 + tx * TN + j;
            float v = acc[i][j];
            const long idx = (long)m * ldc + n;
            if (EPI >= 1) v += bias[n];
            if (EPI == 2) v += C[idx];
            if (EPI == 3) v = gelu_f(v);
            C[idx] = v;
        }
    }
}

// -------------------- layernorm (row = 512, block = 128) --------------------
__global__ void ln_k(const float* __restrict__ x, const float* __restrict__ g,
                     const float* __restrict__ b, float* __restrict__ out)
{
    const long row = blockIdx.x;
    const float* xr = x + row * 512;
    const int tid = threadIdx.x;
    float v[4];
    float s = 0.f;
#pragma unroll
    for (int j = 0; j < 4; j++) { v[j] = xr[tid + j * 128]; s += v[j]; }
    __shared__ float sh[4];
#pragma unroll
    for (int o = 16; o; o >>= 1) s += __shfl_xor_sync(0xffffffffu, s, o);
    if ((tid & 31) == 0) sh[tid >> 5] = s;
    __syncthreads();
    const float mu = (sh[0] + sh[1] + sh[2] + sh[3]) * (1.f / 512.f);
    float s2 = 0.f;
#pragma unroll
    for (int j = 0; j < 4; j++) { float d = v[j] - mu; s2 += d * d; }
    __syncthreads();
#pragma unroll
    for (int o = 16; o; o >>= 1) s2 += __shfl_xor_sync(0xffffffffu, s2, o);
    if ((tid & 31) == 0) sh[tid >> 5] = s2;
    __syncthreads();
    const float rs = rsqrtf((sh[0] + sh[1] + sh[2] + sh[3]) * (1.f / 512.f) + 1e-5f);
    float* outr = out + row * 512;
#pragma unroll
    for (int j = 0; j < 4; j++) {
        int d = tid + j * 128;
        outr[d] = (v[j] - mu) * rs * g[d] + b[d];
    }
}

// -------------------- softmax (row-wise), optional accumulation -------------
template<int L>
__global__ void softmax_k(float* __restrict__ P, float scale,
                          float* __restrict__ accum, int accMod)
{
    const long row = blockIdx.x;
    float* pr = P + row * (long)L;
    const int tid = threadIdx.x;
    constexpr int NIT = (L + 255) >> 8;
    float v[NIT];
    float mx = -3.0e38f;
#pragma unroll
    for (int j = 0; j < NIT; j++) {
        int i = tid + (j << 8);
        float t = (i < L) ? pr[i] * scale : -3.0e38f;
        v[j] = t;
        mx = fmaxf(mx, t);
    }
    __shared__ float sh[8];
#pragma unroll
    for (int o = 16; o; o >>= 1) mx = fmaxf(mx, __shfl_xor_sync(0xffffffffu, mx, o));
    if ((tid & 31) == 0) sh[tid >> 5] = mx;
    __syncthreads();
    float bm = sh[0];
#pragma unroll
    for (int w = 1; w < 8; w++) bm = fmaxf(bm, sh[w]);
    float s = 0.f;
#pragma unroll
    for (int j = 0; j < NIT; j++) {
        int i = tid + (j << 8);
        if (i < L) { float e = __expf(v[j] - bm); v[j] = e; s += e; }
    }
    __syncthreads();
#pragma unroll
    for (int o = 16; o; o >>= 1) s += __shfl_xor_sync(0xffffffffu, s, o);
    if ((tid & 31) == 0) sh[tid >> 5] = s;
    __syncthreads();
    float tot = 0.f;
#pragma unroll
    for (int w = 0; w < 8; w++) tot += sh[w];
    const float inv = 1.f / tot;
    float* acc = accum ? accum + (long)(row % accMod) * L : (float*)0;
#pragma unroll
    for (int j = 0; j < NIT; j++) {
        int i = tid + (j << 8);
        if (i < L) {
            float p = v[j] * inv;
            pr[i] = p;
            if (accum) atomicAdd(acc + i, p);
        }
    }
}

// -------------------- embedding + sinusoidal PE -----------------------------
__global__ void embed_k(const int* __restrict__ seq, const float* __restrict__ emb,
                        float* __restrict__ x)
{
    long i = (long)blockIdx.x * blockDim.x + threadIdx.x;
    if (i >= 2097152L) return;
    int d = (int)(i & 511);
    long bt = i >> 9;
    int t = (int)(bt & 511);
    int tok = seq[bt];
    int j2 = d & ~1;
    float ang = (float)t * expf(-0.017988946039015984f * (float)j2);
    float pe = (d & 1) ? cosf(ang) : sinf(ang);
    x[i] = emb[(long)tok * 512 + d] + pe;
}

// -------------------- conv weight transpose [o,c,r] -> [(r,c), o] -----------
__global__ void convt_k(const float* __restrict__ w, float* __restrict__ wt)
{
    long i = (long)blockIdx.x * blockDim.x + threadIdx.x;
    if (i >= 1048576L) return;
    int o = (int)(i & 511);
    long rc = i >> 9;
    int c = (int)(rc & 511);
    int r = (int)(rc >> 9);
    wt[i] = w[((long)o * 512 + c) * 4 + r];
}

// -------------------- MSE accumulation --------------------------------------
__global__ void mse_k(const float* __restrict__ a, const float* __restrict__ b,
                      float* __restrict__ outScalar, long n)
{
    long i0 = (long)blockIdx.x * blockDim.x + threadIdx.x;
    long stride = (long)gridDim.x * blockDim.x;
    float s = 0.f;
    for (long i = i0; i < n; i += stride) { float d = a[i] - b[i]; s += d * d; }
    __shared__ float sh[8];
#pragma unroll
    for (int o = 16; o; o >>= 1) s += __shfl_xor_sync(0xffffffffu, s, o);
    int tid = threadIdx.x;
    if ((tid & 31) == 0) sh[tid >> 5] = s;
    __syncthreads();
    if (tid == 0) {
        float tot = 0.f;
#pragma unroll
        for (int w = 0; w < 8; w++) tot += sh[w];
        atomicAdd(outScalar, tot);
    }
}

// -------------------- init / final ------------------------------------------
__global__ void init_k(float* __restrict__ out)
{
    long i = (long)blockIdx.x * blockDim.x + threadIdx.x;
    if (i < ATTN_ELEMS) out[OFF_ATTN + i] = 0.f;
    if (i == ATTN_ELEMS) { out[OFF_AUX] = 0.f; out[OFF_ZERO] = 0.f; }
}
__global__ void final_k(float* __restrict__ out)
{
    long i = (long)blockIdx.x * blockDim.x + threadIdx.x;
    if (i < ATTN_ELEMS) out[OFF_ATTN + i] *= (1.f / 256.f);
    else if (i == ATTN_ELEMS) out[OFF_AUX] *= (1.f / (4.f * 2097152.f));
}

// ---------------------------------------------------------------------------
extern "C" void kernel_launch(void* const* d_in, const int* in_sizes, int n_in,
                              void* d_out, int out_size)
{
    const int*   seq   = (const int*)  d_in[0];
    /* d_in[1] mask: all-true by construction -> no-op */
    const float* mems  = (const float*)d_in[2];
    const float* cmems = (const float*)d_in[3];
    const float* emb   = (const float*)d_in[4];
    const float* ln1g  = (const float*)d_in[5];
    const float* ln1b  = (const float*)d_in[6];
    const float* Wq    = (const float*)d_in[7];
    const float* Wkv   = (const float*)d_in[8];
    const float* Wo    = (const float*)d_in[9];
    const float* bo    = (const float*)d_in[10];
    const float* convw = (const float*)d_in[11];
    const float* convb = (const float*)d_in[12];
    const float* ln2g  = (const float*)d_in[13];
    const float* ln2b  = (const float*)d_in[14];
    const float* W1    = (const float*)d_in[15];
    const float* b1    = (const float*)d_in[16];
    const float* W2    = (const float*)d_in[17];
    const float* b2    = (const float*)d_in[18];
    float* out = (float*)d_out;

    float *q, *kv, *dots, *attno, *xn2, *ffh, *cvT, *ckcv, *o1, *o2;
    cudaGetSymbolAddress((void**)&q,     g_q);
    cudaGetSymbolAddress((void**)&kv,    g_kv);
    cudaGetSymbolAddress((void**)&dots,  g_dots);
    cudaGetSymbolAddress((void**)&attno, g_attno);
    cudaGetSymbolAddress((void**)&xn2,   g_xn2);
    cudaGetSymbolAddress((void**)&ffh,   g_ffh);
    cudaGetSymbolAddress((void**)&cvT,   g_convT);
    cudaGetSymbolAddress((void**)&ckcv,  g_ckcv);
    cudaGetSymbolAddress((void**)&o1,    g_o1);
    cudaGetSymbolAddress((void**)&o2,    g_o2);

    float* x       = out;                 // x region doubles as running state
    float* attnsum = out + OFF_ATTN;
    float* aux     = out + OFF_AUX;

    init_k <<<2306, 256>>>(out);
    embed_k<<<8192, 256>>>(seq, emb, x);

    for (int i = 0; i < 4; i++) {
        const float* Wq_i    = Wq    + (long)i * 262144;
        const float* Wkv_i   = Wkv   + (long)i * 524288;
        const float* Wo_i    = Wo    + (long)i * 262144;
        const float* convw_i = convw + (long)i * 1048576;
        const float* W1_i    = W1    + (long)i * 1048576;
        const float* W2_i    = W2    + (long)i * 1048576;
        const float* mems_i  = mems  + (long)i * 2097152;
        const float* cmems_i = cmems + (long)i * 524288;
        float* xn = out + OFF_MEMS  + (long)i * 2097152;   // == new_mems[i]
        float* cm = out + OFF_CMEMS + (long)i * 524288;    // == new_cmems[i]

        // LN1 -> xn (written straight into new_mems slot)
        ln_k<<<4096, 128>>>(x, ln1g + i * 512, ln1b + i * 512, xn);

        // q = xn @ Wq          [4096,512]x[512,512]
        gemm_k<128,128,8,8,8,0,false><<<dim3(4,32,1),256>>>(
            xn, Wq_i, q, 512, 512,512,512, 0,0,0,0,0,0,1, nullptr);

        // kv = [cmems ; mems ; xn] @ Wkv   (three batched-over-b pieces)
        gemm_k<128,128,8,8,8,0,false><<<dim3(8,1,8),256>>>(
            cmems_i, Wkv_i, kv,          512, 512,1024,1024,
            65536,0,  0,0, 1179648,0, 1, nullptr);
        gemm_k<128,128,8,8,8,0,false><<<dim3(8,4,8),256>>>(
            mems_i,  Wkv_i, kv + 131072, 512, 512,1024,1024,
            262144,0, 0,0, 1179648,0, 1, nullptr);
        gemm_k<128,128,8,8,8,0,false><<<dim3(8,4,8),256>>>(
            xn,      Wkv_i, kv + 655360, 512, 512,1024,1024,
            262144,0, 0,0, 1179648,0, 1, nullptr);

        // dots[b,h] = q[b,h] @ k[b,h]^T     (z = b*8+h, zmod = 8)
        gemm_k<64,64,16,4,4,0,true><<<dim3(18,8,64),256>>>(
            q, kv, dots, 64, 512,1024,1152,
            262144,64, 1179648,64, 4718592,589824, 8, nullptr);

        // softmax(scale) + accumulate attns_mean
        softmax_k<1152><<<32768,256>>>(dots, 0.125f, attnsum, 512);

        // attno[b,:,h*64:..] = P[b,h] @ v[b,h]
        gemm_k<64,64,16,4,4,0,false><<<dim3(1,8,64),256>>>(
            dots, kv + 512, attno, 1152, 1152,1024,512,
            4718592,589824, 1179648,64, 262144,64, 8, nullptr);

        // x = attno @ Wo + bo + x
        gemm_k<128,128,8,8,8,2,false><<<dim3(4,32,1),256>>>(
            attno, Wo_i, x, 512, 512,512,512, 0,0,0,0,0,0,1, bo + i * 512);

        // compressed = mems(blocked) @ conv_w^T + conv_b  -> new_cmems slot
        convt_k<<<4096,256>>>(convw_i, cvT);
        gemm_k<128,128,8,8,8,1,false><<<dim3(4,8,1),256>>>(
            mems_i, cvT, cm, 2048, 2048,512,512, 0,0,0,0,0,0,1, convb + i * 512);

        // ck|cv = compressed @ Wkv
        gemm_k<128,128,8,8,8,0,false><<<dim3(8,8,1),256>>>(
            cm, Wkv_i, ckcv, 512, 512,1024,1024, 0,0,0,0,0,0,1, nullptr);

        // aux attention vs memory keys (reuse dots buffer)
        gemm_k<64,64,16,4,4,0,true><<<dim3(8,8,64),256>>>(
            q, kv + 131072, dots, 64, 512,1024,512,
            262144,64, 1179648,64, 2097152,262144, 8, nullptr);
        softmax_k<512><<<32768,256>>>(dots, 0.125f, nullptr, 1);
        gemm_k<64,64,16,4,4,0,false><<<dim3(1,8,64),256>>>(
            dots, kv + 131584, o1, 512, 512,1024,64,
            2097152,262144, 1179648,64, 262144,32768, 8, nullptr);

        // aux attention vs compressed keys
        gemm_k<64,64,16,4,4,0,true><<<dim3(2,8,64),256>>>(
            q, ckcv, dots + 16777216, 64, 512,1024,128,
            262144,64, 131072,64, 524288,65536, 8, nullptr);
        softmax_k<128><<<32768,256>>>(dots + 16777216, 0.125f, nullptr, 1);
        gemm_k<64,64,16,4,4,0,false><<<dim3(1,8,64),256>>>(
            dots + 16777216, ckcv + 512, o2, 128, 128,1024,64,
            524288,65536, 131072,64, 262144,32768, 8, nullptr);

        // aux += sum((o1-o2)^2)
        mse_k<<<512,256>>>(o1, o2, aux, 2097152L);

        // FFN: x = x + gelu(LN2(x) @ W1 + b1) @ W2 + b2
        ln_k<<<4096,128>>>(x, ln2g + i * 512, ln2b + i * 512, xn2);
        gemm_k<128,128,8,8,8,3,false><<<dim3(16,32,1),256>>>(
            xn2, W1_i, ffh, 512, 512,2048,2048, 0,0,0,0,0,0,1, b1 + i * 2048);
        gemm_k<128,128,8,8,8,2,false><<<dim3(4,32,1),256>>>(
            ffh, W2_i, x, 2048, 2048,512,512, 0,0,0,0,0,0,1, b2 + i * 512);
    }

    final_k<<<2306,256>>>(out);
}

// round 4
// speedup vs baseline: 1.9427x; 1.9427x over previous
#include <cuda_runtime.h>
#include <cstdint>
#include <math.h>

// ---------------------------------------------------------------------------
// CompressiveEncoder forward. mma.sync TF32 GEMMs (HMMA) + SIMT glue.
// B=8, T=512, D=512, H=8, DH=64, MEM=512, CMEM=128, LKV=1152, DFF=2048
// Output: x | new_mems | new_cmems | aux | 0 | attns_mean  (fp32)
// ---------------------------------------------------------------------------

#define OFF_MEMS   2097152L
#define OFF_CMEMS 10485760L
#define OFF_AUX   12582912L
#define OFF_ZERO  12582913L
#define OFF_ATTN  12582914L
#define ATTN_ELEMS 589824L

// -------------------- device scratch ---------------------------------------
__device__ float g_q    [8*512*512];
__device__ float g_kv   [8*1152*1024];
__device__ float g_dots [8*8*512*1152 + 8*8*512*128];
__device__ float g_attno[2097152];
__device__ float g_xn2  [2097152];
__device__ float g_ffh  [8388608];
__device__ float g_ckcv [1048576];
__device__ float g_o1   [2097152];
__device__ float g_o2   [2097152];
__device__ float g_vT   [4718592];          // [b][512][1152]
__device__ float g_cvT  [524288];           // [b][512][128]
__device__ float g_WqT  [4*262144];
__device__ float g_WkvT [4*524288];
__device__ float g_WoT  [4*262144];
__device__ float g_cw   [4*1048576];        // conv as B^T: [o][r*512+c]
__device__ float g_W1T  [4*1048576];
__device__ float g_W2T  [4*1048576];

// -------------------- helpers ----------------------------------------------
__device__ __forceinline__ uint32_t f2tf(float f) {
    uint32_t u;
    asm("cvt.rna.tf32.f32 %0, %1;" : "=r"(u) : "f"(f));
    return u;
}
__device__ __forceinline__ void mma_tf32(float* d, const uint32_t* a, const uint32_t* b) {
    asm volatile("mma.sync.aligned.m16n8k8.row.col.f32.tf32.tf32.f32 "
                 "{%0,%1,%2,%3}, {%4,%5,%6,%7}, {%8,%9}, {%0,%1,%2,%3};"
                 : "+f"(d[0]), "+f"(d[1]), "+f"(d[2]), "+f"(d[3])
                 : "r"(a[0]), "r"(a[1]), "r"(a[2]), "r"(a[3]), "r"(b[0]), "r"(b[1]));
}
__device__ __forceinline__ float gelu_f(float v) {
    return 0.5f * v * (1.f + erff(v * 0.70710678118654752f));
}

// -------------------- TF32 mma batched GEMM ---------------------------------
// C[z] = A[z] @ B[z]^T : A [M,K] row-major, B [N,K] row-major, C [M,N].
// CTA tile: 128 x BN x 16. 8 warps. Batch off = (z/zmod)*s1 + (z%zmod)*s2.
// EPI: 0 none, 1 +bias, 2 +bias+C, 3 gelu(.+bias)
template<int BN, int EPI>
__global__ void __launch_bounds__(256)
mm_gemm(const float* __restrict__ A, const float* __restrict__ B, float* __restrict__ C,
        int K, int lda, int ldb, int ldc,
        long sA1, long sA2, long sB1, long sB2, long sC1, long sC2, int zmod,
        const float* __restrict__ bias)
{
    constexpr int BM = 128, BK = 16, LDS = BK + 4;          // 20-float rows
    constexpr int WN = (BN == 128) ? 4 : 2, WM = 8 / WN;
    constexpr int WTM = BM / WM, WTN = BN / WN;             // (64,32) / (32,32)
    constexpr int MF = WTM / 16, NF = WTN / 8;
    constexpr int NA = (BM * 4) / 256, NB = (BN * 4) / 256; // f4 loads per thread

    __shared__ uint32_t As[2][BM * LDS];
    __shared__ uint32_t Bs[2][BN * LDS];

    const int z = blockIdx.z, zh = z / zmod, zl = z - zh * zmod;
    A += zh * sA1 + zl * sA2;
    B += zh * sB1 + zl * sB2;
    C += zh * sC1 + zl * sC2;
    const int m0 = blockIdx.y * BM, n0 = blockIdx.x * BN;
    const int tid = threadIdx.x, lane = tid & 31, wid = tid >> 5;
    const int wm = wid % WM, wn = wid / WM;
    const int mbase = wm * WTM, nbase = wn * WTN;

    float acc[MF][NF][4];
#pragma unroll
    for (int i = 0; i < MF; i++)
#pragma unroll
        for (int j = 0; j < NF; j++)
#pragma unroll
            for (int r = 0; r < 4; r++) acc[i][j][r] = 0.f;

    float4 ra[NA], rb[NB];
    const int KT = K >> 4;

    auto ldg = [&](int kt) {
        const int k0 = kt << 4;
#pragma unroll
        for (int i = 0; i < NA; i++) {
            int idx = tid + i * 256, r = idx >> 2, c = idx & 3;
            ra[i] = *(const float4*)(A + (long)(m0 + r) * lda + k0 + c * 4);
        }
#pragma unroll
        for (int i = 0; i < NB; i++) {
            int idx = tid + i * 256, r = idx >> 2, c = idx & 3;
            rb[i] = *(const float4*)(B + (long)(n0 + r) * ldb + k0 + c * 4);
        }
    };
    auto sts = [&](int st) {
#pragma unroll
        for (int i = 0; i < NA; i++) {
            int idx = tid + i * 256, r = idx >> 2, c = idx & 3;
            uint32_t* p = &As[st][r * LDS + c * 4];
            p[0] = f2tf(ra[i].x); p[1] = f2tf(ra[i].y);
            p[2] = f2tf(ra[i].z); p[3] = f2tf(ra[i].w);
        }
#pragma unroll
        for (int i = 0; i < NB; i++) {
            int idx = tid + i * 256, r = idx >> 2, c = idx & 3;
            uint32_t* p = &Bs[st][r * LDS + c * 4];
            p[0] = f2tf(rb[i].x); p[1] = f2tf(rb[i].y);
            p[2] = f2tf(rb[i].z); p[3] = f2tf(rb[i].w);
        }
    };
    auto compute = [&](int st) {
#pragma unroll
        for (int ks = 0; ks < 2; ks++) {
            const int kk = ks * 8 + (lane & 3);
            uint32_t a[MF][4], b[NF][2];
#pragma unroll
            for (int mf = 0; mf < MF; mf++) {
                int r = mbase + mf * 16 + (lane >> 2);
                // PTX m16n8k8 tf32 A fragment: a0=(g,t) a1=(g+8,t) a2=(g,t+4) a3=(g+8,t+4)
                a[mf][0] = As[st][r * LDS + kk];
                a[mf][1] = As[st][(r + 8) * LDS + kk];
                a[mf][2] = As[st][r * LDS + kk + 4];
                a[mf][3] = As[st][(r + 8) * LDS + kk + 4];
            }
#pragma unroll
            for (int nf = 0; nf < NF; nf++) {
                int n = nbase + nf * 8 + (lane >> 2);
                b[nf][0] = Bs[st][n * LDS + kk];
                b[nf][1] = Bs[st][n * LDS + kk + 4];
            }
#pragma unroll
            for (int mf = 0; mf < MF; mf++)
#pragma unroll
                for (int nf = 0; nf < NF; nf++)
                    mma_tf32(acc[mf][nf], a[mf], b[nf]);
        }
    };

    ldg(0); sts(0);
    __syncthreads();
    for (int kt = 0; kt < KT; kt++) {
        if (kt + 1 < KT) ldg(kt + 1);
        compute(kt & 1);
        if (kt + 1 < KT) {
            sts((kt + 1) & 1);
            __syncthreads();
        }
    }

    // ---- epilogue: write C fragments directly ----
    const int rbase = m0 + mbase + (lane >> 2);
    const int cbase = n0 + nbase + 2 * (lane & 3);
#pragma unroll
    for (int mf = 0; mf < MF; mf++) {
#pragma unroll
        for (int nf = 0; nf < NF; nf++) {
#pragma unroll
            for (int half = 0; half < 2; half++) {
                const int m = rbase + mf * 16 + half * 8;
                const int n = cbase + nf * 8;
                float2 v = make_float2(acc[mf][nf][half * 2], acc[mf][nf][half * 2 + 1]);
                const long idx = (long)m * ldc + n;
                if (EPI >= 1) { v.x += bias[n]; v.y += bias[n + 1]; }
                if (EPI == 2) { float2 c0 = *(const float2*)(C + idx); v.x += c0.x; v.y += c0.y; }
                if (EPI == 3) { v.x = gelu_f(v.x); v.y = gelu_f(v.y); }
                *(float2*)(C + idx) = v;
            }
        }
    }
}

// -------------------- 32x32 tiled transpose: out[n][k] = in[k][n] -----------
__global__ void tr_k(const float* __restrict__ in, float* __restrict__ out,
                     int ldi, int ldo, long sI, long sO)
{
    __shared__ float t[32][33];
    in += blockIdx.z * sI; out += blockIdx.z * sO;
    const int n0 = blockIdx.x * 32, k0 = blockIdx.y * 32;
    const int tx = threadIdx.x, ty = threadIdx.y;
#pragma unroll
    for (int j = 0; j < 32; j += 8) t[ty + j][tx] = in[(long)(k0 + ty + j) * ldi + n0 + tx];
    __syncthreads();
#pragma unroll
    for (int j = 0; j < 32; j += 8) out[(long)(n0 + ty + j) * ldo + k0 + tx] = t[tx][ty + j];
}

// conv weight: cw[l][o][r*512+c] = conv_w[l][o][c][r]
__global__ void convt2_k(const float* __restrict__ w, float* __restrict__ wt)
{
    long i = (long)blockIdx.x * 256 + threadIdx.x;
    if (i >= 4L * 1048576L) return;
    long l = i >> 20, r0 = i & 1048575L;
    int o = (int)(r0 >> 11), k = (int)(r0 & 2047);
    int r = k >> 9, c = k & 511;
    wt[i] = w[l * 1048576L + ((long)o * 512 + c) * 4 + r];
}

// -------------------- layernorm --------------------------------------------
__global__ void ln_k(const float* __restrict__ x, const float* __restrict__ g,
                     const float* __restrict__ b, float* __restrict__ out)
{
    const long row = blockIdx.x;
    const float* xr = x + row * 512;
    const int tid = threadIdx.x;
    float v[4]; float s = 0.f;
#pragma unroll
    for (int j = 0; j < 4; j++) { v[j] = xr[tid + j * 128]; s += v[j]; }
    __shared__ float sh[4];
#pragma unroll
    for (int o = 16; o; o >>= 1) s += __shfl_xor_sync(0xffffffffu, s, o);
    if ((tid & 31) == 0) sh[tid >> 5] = s;
    __syncthreads();
    const float mu = (sh[0] + sh[1] + sh[2] + sh[3]) * (1.f / 512.f);
    float s2 = 0.f;
#pragma unroll
    for (int j = 0; j < 4; j++) { float d = v[j] - mu; s2 += d * d; }
    __syncthreads();
#pragma unroll
    for (int o = 16; o; o >>= 1) s2 += __shfl_xor_sync(0xffffffffu, s2, o);
    if ((tid & 31) == 0) sh[tid >> 5] = s2;
    __syncthreads();
    const float rs = rsqrtf((sh[0] + sh[1] + sh[2] + sh[3]) * (1.f / 512.f) + 1e-5f);
    float* outr = out + row * 512;
#pragma unroll
    for (int j = 0; j < 4; j++) {
        int d = tid + j * 128;
        outr[d] = (v[j] - mu) * rs * g[d] + b[d];
    }
}

// -------------------- softmax ----------------------------------------------
template<int L>
__global__ void softmax_k(float* __restrict__ P, float scale,
                          float* __restrict__ accum, int accMod)
{
    const long row = blockIdx.x;
    float* pr = P + row * (long)L;
    const int tid = threadIdx.x;
    constexpr int NIT = (L + 255) >> 8;
    float v[NIT]; float mx = -3.0e38f;
#pragma unroll
    for (int j = 0; j < NIT; j++) {
        int i = tid + (j << 8);
        float t = (i < L) ? pr[i] * scale : -3.0e38f;
        v[j] = t; mx = fmaxf(mx, t);
    }
    __shared__ float sh[8];
#pragma unroll
    for (int o = 16; o; o >>= 1) mx = fmaxf(mx, __shfl_xor_sync(0xffffffffu, mx, o));
    if ((tid & 31) == 0) sh[tid >> 5] = mx;
    __syncthreads();
    float bm = sh[0];
#pragma unroll
    for (int w = 1; w < 8; w++) bm = fmaxf(bm, sh[w]);
    float s = 0.f;
#pragma unroll
    for (int j = 0; j < NIT; j++) {
        int i = tid + (j << 8);
        if (i < L) { float e = __expf(v[j] - bm); v[j] = e; s += e; }
    }
    __syncthreads();
#pragma unroll
    for (int o = 16; o; o >>= 1) s += __shfl_xor_sync(0xffffffffu, s, o);
    if ((tid & 31) == 0) sh[tid >> 5] = s;
    __syncthreads();
    float tot = 0.f;
#pragma unroll
    for (int w = 0; w < 8; w++) tot += sh[w];
    const float inv = 1.f / tot;
    float* acc = accum ? accum + (long)(row % accMod) * L : (float*)0;
#pragma unroll
    for (int j = 0; j < NIT; j++) {
        int i = tid + (j << 8);
        if (i < L) {
            float p = v[j] * inv;
            pr[i] = p;
            if (accum) atomicAdd(acc + i, p);
        }
    }
}

// -------------------- embed / mse / init / final ----------------------------
__global__ void embed_k(const int* __restrict__ seq, const float* __restrict__ emb,
                        float* __restrict__ x)
{
    long i = (long)blockIdx.x * blockDim.x + threadIdx.x;
    if (i >= 2097152L) return;
    int d = (int)(i & 511);
    long bt = i >> 9;
    int t = (int)(bt & 511);
    int tok = seq[bt];
    int j2 = d & ~1;
    float ang = (float)t * expf(-0.017988946039015984f * (float)j2);
    float pe = (d & 1) ? cosf(ang) : sinf(ang);
    x[i] = emb[(long)tok * 512 + d] + pe;
}

__global__ void mse_k(const float* __restrict__ a, const float* __restrict__ b,
                      float* __restrict__ outScalar, long n)
{
    long i0 = (long)blockIdx.x * blockDim.x + threadIdx.x;
    long stride = (long)gridDim.x * blockDim.x;
    float s = 0.f;
    for (long i = i0; i < n; i += stride) { float d = a[i] - b[i]; s += d * d; }
    __shared__ float sh[8];
#pragma unroll
    for (int o = 16; o; o >>= 1) s += __shfl_xor_sync(0xffffffffu, s, o);
    int tid = threadIdx.x;
    if ((tid & 31) == 0) sh[tid >> 5] = s;
    __syncthreads();
    if (tid == 0) {
        float tot = 0.f;
#pragma unroll
        for (int w = 0; w < 8; w++) tot += sh[w];
        atomicAdd(outScalar, tot);
    }
}

__global__ void init_k(float* __restrict__ out)
{
    long i = (long)blockIdx.x * blockDim.x + threadIdx.x;
    if (i < ATTN_ELEMS) out[OFF_ATTN + i] = 0.f;
    if (i == ATTN_ELEMS) { out[OFF_AUX] = 0.f; out[OFF_ZERO] = 0.f; }
}
__global__ void final_k(float* __restrict__ out)
{
    long i = (long)blockIdx.x * blockDim.x + threadIdx.x;
    if (i < ATTN_ELEMS) out[OFF_ATTN + i] *= (1.f / 256.f);
    else if (i == ATTN_ELEMS) out[OFF_AUX] *= (1.f / (4.f * 2097152.f));
}

// ---------------------------------------------------------------------------
extern "C" void kernel_launch(void* const* d_in, const int* in_sizes, int n_in,
                              void* d_out, int out_size)
{
    const int*   seq   = (const int*)  d_in[0];
    const float* mems  = (const float*)d_in[2];
    const float* cmems = (const float*)d_in[3];
    const float* emb   = (const float*)d_in[4];
    const float* ln1g  = (const float*)d_in[5];
    const float* ln1b  = (const float*)d_in[6];
    const float* Wq    = (const float*)d_in[7];
    const float* Wkv   = (const float*)d_in[8];
    const float* Wo    = (const float*)d_in[9];
    const float* bo    = (const float*)d_in[10];
    const float* convw = (const float*)d_in[11];
    const float* convb = (const float*)d_in[12];
    const float* ln2g  = (const float*)d_in[13];
    const float* ln2b  = (const float*)d_in[14];
    const float* W1    = (const float*)d_in[15];
    const float* b1    = (const float*)d_in[16];
    const float* W2    = (const float*)d_in[17];
    const float* b2    = (const float*)d_in[18];
    float* out = (float*)d_out;

    float *q, *kv, *dots, *attno, *xn2, *ffh, *ckcv, *o1, *o2, *vT, *cvT;
    float *WqT, *WkvT, *WoT, *cw, *W1T, *W2T;
    cudaGetSymbolAddress((void**)&q, g_q);       cudaGetSymbolAddress((void**)&kv, g_kv);
    cudaGetSymbolAddress((void**)&dots, g_dots); cudaGetSymbolAddress((void**)&attno, g_attno);
    cudaGetSymbolAddress((void**)&xn2, g_xn2);   cudaGetSymbolAddress((void**)&ffh, g_ffh);
    cudaGetSymbolAddress((void**)&ckcv, g_ckcv); cudaGetSymbolAddress((void**)&o1, g_o1);
    cudaGetSymbolAddress((void**)&o2, g_o2);     cudaGetSymbolAddress((void**)&vT, g_vT);
    cudaGetSymbolAddress((void**)&cvT, g_cvT);
    cudaGetSymbolAddress((void**)&WqT, g_WqT);   cudaGetSymbolAddress((void**)&WkvT, g_WkvT);
    cudaGetSymbolAddress((void**)&WoT, g_WoT);   cudaGetSymbolAddress((void**)&cw, g_cw);
    cudaGetSymbolAddress((void**)&W1T, g_W1T);   cudaGetSymbolAddress((void**)&W2T, g_W2T);

    float* x       = out;
    float* attnsum = out + OFF_ATTN;
    float* aux     = out + OFF_AUX;
    float* dots2   = dots + 37748736;   // after 8*8*512*1152

    init_k <<<2306, 256>>>(out);
    embed_k<<<8192, 256>>>(seq, emb, x);

    // ---- weight transposes (once per launch) ----
    dim3 tb(32, 8);
    tr_k<<<dim3(16,16,4), tb>>>(Wq,  WqT,  512,  512,  262144, 262144);
    tr_k<<<dim3(32,16,4), tb>>>(Wkv, WkvT, 1024, 512,  524288, 524288);
    tr_k<<<dim3(16,16,4), tb>>>(Wo,  WoT,  512,  512,  262144, 262144);
    tr_k<<<dim3(64,16,4), tb>>>(W1,  W1T,  2048, 512,  1048576, 1048576);
    tr_k<<<dim3(16,64,4), tb>>>(W2,  W2T,  512,  2048, 1048576, 1048576);
    convt2_k<<<16384, 256>>>(convw, cw);

    for (int i = 0; i < 4; i++) {
        const float* WqT_i  = WqT  + (long)i * 262144;
        const float* WkvT_i = WkvT + (long)i * 524288;
        const float* WoT_i  = WoT  + (long)i * 262144;
        const float* cw_i   = cw   + (long)i * 1048576;
        const float* W1T_i  = W1T  + (long)i * 1048576;
        const float* W2T_i  = W2T  + (long)i * 1048576;
        const float* mems_i  = mems  + (long)i * 2097152;
        const float* cmems_i = cmems + (long)i * 524288;
        float* xn = out + OFF_MEMS  + (long)i * 2097152;
        float* cm = out + OFF_CMEMS + (long)i * 524288;

        ln_k<<<4096, 128>>>(x, ln1g + i * 512, ln1b + i * 512, xn);

        // q = xn @ Wq
        mm_gemm<128,0><<<dim3(4,32,1),256>>>(xn, WqT_i, q, 512, 512,512,512,
            0,0,0,0,0,0,1, nullptr);

        // kv = [cmems ; mems ; xn] @ Wkv   (zmod=1: per-z stride in s1)
        mm_gemm<128,0><<<dim3(8,1,8),256>>>(cmems_i, WkvT_i, kv, 512, 512,512,1024,
            65536,0, 0,0, 1179648,0, 1, nullptr);
        mm_gemm<128,0><<<dim3(8,4,8),256>>>(mems_i, WkvT_i, kv + 131072, 512, 512,512,1024,
            262144,0, 0,0, 1179648,0, 1, nullptr);
        mm_gemm<128,0><<<dim3(8,4,8),256>>>(xn, WkvT_i, kv + 655360, 512, 512,512,1024,
            262144,0, 0,0, 1179648,0, 1, nullptr);

        // dots = q @ k^T   (z = b*8+h)
        mm_gemm<128,0><<<dim3(9,4,64),256>>>(q, kv, dots, 64, 512,1024,1152,
            262144,64, 1179648,64, 4718592,589824, 8, nullptr);

        softmax_k<1152><<<32768,256>>>(dots, 0.125f, attnsum, 512);

        // vT[b][d][j] = v[b][j][d]
        tr_k<<<dim3(16,36,8), tb>>>(kv + 512, vT, 1024, 1152, 1179648, 589824);

        // attno = P @ v
        mm_gemm<64,0><<<dim3(1,4,64),256>>>(dots, vT, attno, 1152, 1152,1152,512,
            4718592,589824, 589824,73728, 262144,64, 8, nullptr);

        // x = attno @ Wo + bo + x
        mm_gemm<128,2><<<dim3(4,32,1),256>>>(attno, WoT_i, x, 512, 512,512,512,
            0,0,0,0,0,0,1, bo + i * 512);

        // compressed = mems(blocked [1024,2048]) @ conv^T + conv_b
        mm_gemm<128,1><<<dim3(4,8,1),256>>>(mems_i, cw_i, cm, 2048, 2048,2048,512,
            0,0,0,0,0,0,1, convb + i * 512);

        // ck|cv = compressed @ Wkv
        mm_gemm<128,0><<<dim3(8,8,1),256>>>(cm, WkvT_i, ckcv, 512, 512,512,1024,
            0,0,0,0,0,0,1, nullptr);

        // aux attention vs memory keys
        mm_gemm<128,0><<<dim3(4,4,64),256>>>(q, kv + 131072, dots, 64, 512,1024,512,
            262144,64, 1179648,64, 2097152,262144, 8, nullptr);
        softmax_k<512><<<32768,256>>>(dots, 0.125f, nullptr, 1);
        mm_gemm<64,0><<<dim3(1,4,64),256>>>(dots, vT + 128, o1, 512, 512,1152,64,
            2097152,262144, 589824,73728, 262144,32768, 8, nullptr);

        // aux attention vs compressed keys
        tr_k<<<dim3(16,4,8), tb>>>(ckcv + 512, cvT, 1024, 128, 131072, 65536);
        mm_gemm<128,0><<<dim3(1,4,64),256>>>(q, ckcv, dots2, 64, 512,1024,128,
            262144,64, 131072,64, 524288,65536, 8, nullptr);
        softmax_k<128><<<32768,256>>>(dots2, 0.125f, nullptr, 1);
        mm_gemm<64,0><<<dim3(1,4,64),256>>>(dots2, cvT, o2, 128, 128,128,64,
            524288,65536, 65536,8192, 262144,32768, 8, nullptr);

        mse_k<<<512,256>>>(o1, o2, aux, 2097152L);

        // FFN
        ln_k<<<4096,128>>>(x, ln2g + i * 512, ln2b + i * 512, xn2);
        mm_gemm<128,3><<<dim3(16,32,1),256>>>(xn2, W1T_i, ffh, 512, 512,512,2048,
            0,0,0,0,0,0,1, b1 + i * 2048);
        mm_gemm<128,2><<<dim3(4,32,1),256>>>(ffh, W2T_i, x, 2048, 2048,2048,512,
            0,0,0,0,0,0,1, b2 + i * 512);
    }

    final_k<<<2306,256>>>(out);
}

// round 5
// speedup vs baseline: 2.6232x; 1.3503x over previous
#include <cuda_runtime.h>
#include <cstdint>
#include <math.h>

// ---------------------------------------------------------------------------
// CompressiveEncoder forward. mma.sync TF32 (HMMA) + SIMT glue.
// B=8, T=512, D=512, H=8, DH=64, MEM=512, CMEM=128, LKV=1152, DFF=2048
// Output: x | new_mems | new_cmems | aux | 0 | attns_mean  (fp32)
// ---------------------------------------------------------------------------

#define OFF_MEMS   2097152L
#define OFF_CMEMS 10485760L
#define OFF_AUX   12582912L
#define OFF_ZERO  12582913L
#define OFF_ATTN  12582914L
#define ATTN_ELEMS 589824L

// -------------------- device scratch ---------------------------------------
__device__ float g_q    [2097152];       // [b][512][512]
__device__ float g_k    [4718592];       // [b][1152][512]  (k only)
__device__ float g_vT   [4718592];       // [b][512 d][1152 j]
__device__ float g_dots [37748736];      // [b][h][512][1152]
__device__ float g_dotsA[16777216];      // [b][h][512][512]  aux-mem probs
__device__ float g_dots2[4194304];       // [b][h][512][128]  aux-cmem logits/probs
__device__ float g_attno[2097152];
__device__ float g_xn2  [2097152];
__device__ float g_ffh  [8388608];
__device__ float g_ck   [524288];        // [b][128][512]
__device__ float g_cvT  [524288];        // [b][512 d][128 j]
__device__ float g_o1   [2097152];
__device__ float g_o2   [2097152];
__device__ float g_WqT  [1048576];
__device__ float g_WkvT [2097152];
__device__ float g_WoT  [1048576];
__device__ float g_cw   [4194304];       // conv as B^T: [l][o][r*512+c]
__device__ float g_W1T  [4194304];
__device__ float g_W2T  [4194304];

// -------------------- helpers ----------------------------------------------
__device__ __forceinline__ uint32_t f2tf(float f) {
    uint32_t u;
    asm("cvt.rna.tf32.f32 %0, %1;" : "=r"(u) : "f"(f));
    return u;
}
__device__ __forceinline__ void mma_tf32(float* d, const uint32_t* a, const uint32_t* b) {
    asm volatile("mma.sync.aligned.m16n8k8.row.col.f32.tf32.tf32.f32 "
                 "{%0,%1,%2,%3}, {%4,%5,%6,%7}, {%8,%9}, {%0,%1,%2,%3};"
                 : "+f"(d[0]), "+f"(d[1]), "+f"(d[2]), "+f"(d[3])
                 : "r"(a[0]), "r"(a[1]), "r"(a[2]), "r"(a[3]), "r"(b[0]), "r"(b[1]));
}
__device__ __forceinline__ float gelu_f(float v) {
    return 0.5f * v * (1.f + erff(v * 0.70710678118654752f));
}

// -------------------- TF32 mma batched GEMM ---------------------------------
// C[z] = A[z] @ B[z]^T : A [M,K] row-major, B [N,K] row-major, C [M,N].
// CTA tile 128 x BN x 32, 8 warps. Batch off = (z/zmod)*s1 + (z%zmod)*s2.
// Smem K layout per 8-group: slot(k) = 2*(k&3) + ((k>>2)&1)  -> fragment pairs
// (k, k+4) are adjacent, enabling LDS.64 fragment gathers.
// EPI: 0 none, 1 +bias, 2 +bias+C, 3 gelu(.+bias)
template<int BN, int EPI>
__global__ void __launch_bounds__(256)
mm_gemm(const float* __restrict__ A, const float* __restrict__ B, float* __restrict__ C,
        int K, int lda, int ldb, int ldc,
        long sA1, long sA2, long sB1, long sB2, long sC1, long sC2, int zmod,
        const float* __restrict__ bias)
{
    constexpr int BM = 128, LDSW = 36;                      // 32 k + 4 pad words
    constexpr int WN = (BN == 128) ? 4 : 2, WM = 8 / WN;
    constexpr int WTM = BM / WM, WTN = BN / WN;
    constexpr int MF = WTM / 16, NF = WTN / 8;
    constexpr int NA = (BM * 32) / 4 / 256;                 // f4 per thread (A)
    constexpr int NB = (BN * 32) / 4 / 256;

    extern __shared__ uint32_t sm[];
    uint32_t* As = sm;                                      // [2][BM*LDSW]
    uint32_t* Bs = sm + 2 * BM * LDSW;                      // [2][BN*LDSW]

    const int z = blockIdx.z, zh = z / zmod, zl = z - zh * zmod;
    A += zh * sA1 + zl * sA2;
    B += zh * sB1 + zl * sB2;
    C += zh * sC1 + zl * sC2;
    const int m0 = blockIdx.y * BM, n0 = blockIdx.x * BN;
    const int tid = threadIdx.x, lane = tid & 31, wid = tid >> 5;
    const int wm = wid % WM, wn = wid / WM;
    const int mbase = wm * WTM, nbase = wn * WTN;

    float acc[MF][NF][4];
#pragma unroll
    for (int i = 0; i < MF; i++)
#pragma unroll
        for (int j = 0; j < NF; j++)
#pragma unroll
            for (int r = 0; r < 4; r++) acc[i][j][r] = 0.f;

    float4 ra[NA], rb[NB];
    const int KT = K >> 5;

    auto ldg = [&](int kt) {
        const int k0 = kt << 5;
#pragma unroll
        for (int i = 0; i < NA; i++) {
            int idx = tid + i * 256, r = idx >> 3, c4 = idx & 7;
            ra[i] = *(const float4*)(A + (long)(m0 + r) * lda + k0 + c4 * 4);
        }
#pragma unroll
        for (int i = 0; i < NB; i++) {
            int idx = tid + i * 256, r = idx >> 3, c4 = idx & 7;
            rb[i] = *(const float4*)(B + (long)(n0 + r) * ldb + k0 + c4 * 4);
        }
    };
    auto sts = [&](int st) {
        uint32_t* as = As + st * BM * LDSW;
        uint32_t* bs = Bs + st * BN * LDSW;
#pragma unroll
        for (int i = 0; i < NA; i++) {
            int idx = tid + i * 256, r = idx >> 3, c4 = idx & 7;
            uint32_t* p = &as[r * LDSW + (c4 >> 1) * 8 + (c4 & 1)];
            p[0] = f2tf(ra[i].x); p[2] = f2tf(ra[i].y);
            p[4] = f2tf(ra[i].z); p[6] = f2tf(ra[i].w);
        }
#pragma unroll
        for (int i = 0; i < NB; i++) {
            int idx = tid + i * 256, r = idx >> 3, c4 = idx & 7;
            uint32_t* p = &bs[r * LDSW + (c4 >> 1) * 8 + (c4 & 1)];
            p[0] = f2tf(rb[i].x); p[2] = f2tf(rb[i].y);
            p[4] = f2tf(rb[i].z); p[6] = f2tf(rb[i].w);
        }
    };
    auto compute = [&](int st) {
        const uint32_t* as = As + st * BM * LDSW;
        const uint32_t* bs = Bs + st * BN * LDSW;
#pragma unroll
        for (int ks = 0; ks < 4; ks++) {
            const int ko = ks * 8 + 2 * (lane & 3);
            uint32_t a[MF][4], b[NF][2];
#pragma unroll
            for (int mf = 0; mf < MF; mf++) {
                int r = mbase + mf * 16 + (lane >> 2);
                uint2 p0 = *(const uint2*)&as[r * LDSW + ko];
                uint2 p1 = *(const uint2*)&as[(r + 8) * LDSW + ko];
                a[mf][0] = p0.x; a[mf][1] = p1.x; a[mf][2] = p0.y; a[mf][3] = p1.y;
            }
#pragma unroll
            for (int nf = 0; nf < NF; nf++) {
                int n = nbase + nf * 8 + (lane >> 2);
                uint2 p = *(const uint2*)&bs[n * LDSW + ko];
                b[nf][0] = p.x; b[nf][1] = p.y;
            }
#pragma unroll
            for (int mf = 0; mf < MF; mf++)
#pragma unroll
                for (int nf = 0; nf < NF; nf++)
                    mma_tf32(acc[mf][nf], a[mf], b[nf]);
        }
    };

    ldg(0); sts(0);
    __syncthreads();
    for (int kt = 0; kt < KT; kt++) {
        if (kt + 1 < KT) ldg(kt + 1);
        compute(kt & 1);
        if (kt + 1 < KT) {
            sts((kt + 1) & 1);
            __syncthreads();
        }
    }

    // ---- epilogue ----
    const int rbase = m0 + mbase + (lane >> 2);
    const int cbase = n0 + nbase + 2 * (lane & 3);
#pragma unroll
    for (int mf = 0; mf < MF; mf++) {
#pragma unroll
        for (int nf = 0; nf < NF; nf++) {
#pragma unroll
            for (int half = 0; half < 2; half++) {
                const int m = rbase + mf * 16 + half * 8;
                const int n = cbase + nf * 8;
                float2 v = make_float2(acc[mf][nf][half * 2], acc[mf][nf][half * 2 + 1]);
                const long idx = (long)m * ldc + n;
                if (EPI >= 1) { v.x += bias[n]; v.y += bias[n + 1]; }
                if (EPI == 2) { float2 c0 = *(const float2*)(C + idx); v.x += c0.x; v.y += c0.y; }
                if (EPI == 3) { v.x = gelu_f(v.x); v.y = gelu_f(v.y); }
                *(float2*)(C + idx) = v;
            }
        }
    }
}

// -------------------- 32x32 tiled transpose (weights only) ------------------
__global__ void tr_k(const float* __restrict__ in, float* __restrict__ out,
                     int ldi, int ldo, long sI, long sO)
{
    __shared__ float t[32][33];
    in += blockIdx.z * sI; out += blockIdx.z * sO;
    const int n0 = blockIdx.x * 32, k0 = blockIdx.y * 32;
    const int tx = threadIdx.x, ty = threadIdx.y;
#pragma unroll
    for (int j = 0; j < 32; j += 8) t[ty + j][tx] = in[(long)(k0 + ty + j) * ldi + n0 + tx];
    __syncthreads();
#pragma unroll
    for (int j = 0; j < 32; j += 8) out[(long)(n0 + ty + j) * ldo + k0 + tx] = t[tx][ty + j];
}

// conv weight: cw[l][o][r*512+c] = conv_w[l][o][c][r]
__global__ void convt2_k(const float* __restrict__ w, float* __restrict__ wt)
{
    long i = (long)blockIdx.x * 256 + threadIdx.x;
    if (i >= 4L * 1048576L) return;
    long l = i >> 20, r0 = i & 1048575L;
    int o = (int)(r0 >> 11), k = (int)(r0 & 2047);
    int r = k >> 9, c = k & 511;
    wt[i] = w[l * 1048576L + ((long)o * 512 + c) * 4 + r];
}

// -------------------- layernorm --------------------------------------------
__global__ void ln_k(const float* __restrict__ x, const float* __restrict__ g,
                     const float* __restrict__ b, float* __restrict__ out)
{
    const long row = blockIdx.x;
    const float* xr = x + row * 512;
    const int tid = threadIdx.x;
    float v[4]; float s = 0.f;
#pragma unroll
    for (int j = 0; j < 4; j++) { v[j] = xr[tid + j * 128]; s += v[j]; }
    __shared__ float sh[4];
#pragma unroll
    for (int o = 16; o; o >>= 1) s += __shfl_xor_sync(0xffffffffu, s, o);
    if ((tid & 31) == 0) sh[tid >> 5] = s;
    __syncthreads();
    const float mu = (sh[0] + sh[1] + sh[2] + sh[3]) * (1.f / 512.f);
    float s2 = 0.f;
#pragma unroll
    for (int j = 0; j < 4; j++) { float d = v[j] - mu; s2 += d * d; }
    __syncthreads();
#pragma unroll
    for (int o = 16; o; o >>= 1) s2 += __shfl_xor_sync(0xffffffffu, s2, o);
    if ((tid & 31) == 0) sh[tid >> 5] = s2;
    __syncthreads();
    const float rs = rsqrtf((sh[0] + sh[1] + sh[2] + sh[3]) * (1.f / 512.f) + 1e-5f);
    float* outr = out + row * 512;
#pragma unroll
    for (int j = 0; j < 4; j++) {
        int d = tid + j * 128;
        outr[d] = (v[j] - mu) * rs * g[d] + b[d];
    }
}

// -------------------- softmax (src may be strided; dst contiguous) ----------
template<int L>
__global__ void softmax_k(const float* __restrict__ In, float* __restrict__ Out,
                          long inStride, float scale,
                          float* __restrict__ accum, int accMod)
{
    const long row = blockIdx.x;
    const float* ir = In + row * inStride;
    float* orow = Out + row * (long)L;
    const int tid = threadIdx.x;
    constexpr int NIT = (L + 255) >> 8;
    float v[NIT]; float mx = -3.0e38f;
#pragma unroll
    for (int j = 0; j < NIT; j++) {
        int i = tid + (j << 8);
        float t = (i < L) ? ir[i] * scale : -3.0e38f;
        v[j] = t; mx = fmaxf(mx, t);
    }
    __shared__ float sh[8];
#pragma unroll
    for (int o = 16; o; o >>= 1) mx = fmaxf(mx, __shfl_xor_sync(0xffffffffu, mx, o));
    if ((tid & 31) == 0) sh[tid >> 5] = mx;
    __syncthreads();
    float bm = sh[0];
#pragma unroll
    for (int w = 1; w < 8; w++) bm = fmaxf(bm, sh[w]);
    float s = 0.f;
#pragma unroll
    for (int j = 0; j < NIT; j++) {
        int i = tid + (j << 8);
        if (i < L) { float e = __expf(v[j] - bm); v[j] = e; s += e; }
    }
    __syncthreads();
#pragma unroll
    for (int o = 16; o; o >>= 1) s += __shfl_xor_sync(0xffffffffu, s, o);
    if ((tid & 31) == 0) sh[tid >> 5] = s;
    __syncthreads();
    float tot = 0.f;
#pragma unroll
    for (int w = 0; w < 8; w++) tot += sh[w];
    const float inv = 1.f / tot;
    float* acc = accum ? accum + (long)(row % accMod) * L : (float*)0;
#pragma unroll
    for (int j = 0; j < NIT; j++) {
        int i = tid + (j << 8);
        if (i < L) {
            float p = v[j] * inv;
            orow[i] = p;
            if (accum) atomicAdd(acc + i, p);
        }
    }
}

// -------------------- embed / mse / init / final ----------------------------
__global__ void embed_k(const int* __restrict__ seq, const float* __restrict__ emb,
                        float* __restrict__ x)
{
    long i = (long)blockIdx.x * blockDim.x + threadIdx.x;
    if (i >= 2097152L) return;
    int d = (int)(i & 511);
    long bt = i >> 9;
    int t = (int)(bt & 511);
    int tok = seq[bt];
    int j2 = d & ~1;
    float ang = (float)t * expf(-0.017988946039015984f * (float)j2);
    float pe = (d & 1) ? cosf(ang) : sinf(ang);
    x[i] = emb[(long)tok * 512 + d] + pe;
}

__global__ void mse_k(const float* __restrict__ a, const float* __restrict__ b,
                      float* __restrict__ outScalar, long n)
{
    long i0 = (long)blockIdx.x * blockDim.x + threadIdx.x;
    long stride = (long)gridDim.x * blockDim.x;
    float s = 0.f;
    for (long i = i0; i < n; i += stride) { float d = a[i] - b[i]; s += d * d; }
    __shared__ float sh[8];
#pragma unroll
    for (int o = 16; o; o >>= 1) s += __shfl_xor_sync(0xffffffffu, s, o);
    int tid = threadIdx.x;
    if ((tid & 31) == 0) sh[tid >> 5] = s;
    __syncthreads();
    if (tid == 0) {
        float tot = 0.f;
#pragma unroll
        for (int w = 0; w < 8; w++) tot += sh[w];
        atomicAdd(outScalar, tot);
    }
}

__global__ void init_k(float* __restrict__ out)
{
    long i = (long)blockIdx.x * blockDim.x + threadIdx.x;
    if (i < ATTN_ELEMS) out[OFF_ATTN + i] = 0.f;
    if (i == ATTN_ELEMS) { out[OFF_AUX] = 0.f; out[OFF_ZERO] = 0.f; }
}
__global__ void final_k(float* __restrict__ out)
{
    long i = (long)blockIdx.x * blockDim.x + threadIdx.x;
    if (i < ATTN_ELEMS) out[OFF_ATTN + i] *= (1.f / 256.f);
    else if (i == ATTN_ELEMS) out[OFF_AUX] *= (1.f / (4.f * 2097152.f));
}

// ---------------------------------------------------------------------------
extern "C" void kernel_launch(void* const* d_in, const int* in_sizes, int n_in,
                              void* d_out, int out_size)
{
    const int*   seq   = (const int*)  d_in[0];
    const float* mems  = (const float*)d_in[2];
    const float* cmems = (const float*)d_in[3];
    const float* emb   = (const float*)d_in[4];
    const float* ln1g  = (const float*)d_in[5];
    const float* ln1b  = (const float*)d_in[6];
    const float* Wq    = (const float*)d_in[7];
    const float* Wkv   = (const float*)d_in[8];
    const float* Wo    = (const float*)d_in[9];
    const float* bo    = (const float*)d_in[10];
    const float* convw = (const float*)d_in[11];
    const float* convb = (const float*)d_in[12];
    const float* ln2g  = (const float*)d_in[13];
    const float* ln2b  = (const float*)d_in[14];
    const float* W1    = (const float*)d_in[15];
    const float* b1    = (const float*)d_in[16];
    const float* W2    = (const float*)d_in[17];
    const float* b2    = (const float*)d_in[18];
    float* out = (float*)d_out;

    float *q, *k, *vT, *dots, *dotsA, *dots2, *attno, *xn2, *ffh, *ck, *cvT, *o1, *o2;
    float *WqT, *WkvT, *WoT, *cw, *W1T, *W2T;
    cudaGetSymbolAddress((void**)&q, g_q);        cudaGetSymbolAddress((void**)&k, g_k);
    cudaGetSymbolAddress((void**)&vT, g_vT);      cudaGetSymbolAddress((void**)&dots, g_dots);
    cudaGetSymbolAddress((void**)&dotsA, g_dotsA);cudaGetSymbolAddress((void**)&dots2, g_dots2);
    cudaGetSymbolAddress((void**)&attno, g_attno);cudaGetSymbolAddress((void**)&xn2, g_xn2);
    cudaGetSymbolAddress((void**)&ffh, g_ffh);    cudaGetSymbolAddress((void**)&ck, g_ck);
    cudaGetSymbolAddress((void**)&cvT, g_cvT);    cudaGetSymbolAddress((void**)&o1, g_o1);
    cudaGetSymbolAddress((void**)&o2, g_o2);
    cudaGetSymbolAddress((void**)&WqT, g_WqT);    cudaGetSymbolAddress((void**)&WkvT, g_WkvT);
    cudaGetSymbolAddress((void**)&WoT, g_WoT);    cudaGetSymbolAddress((void**)&cw, g_cw);
    cudaGetSymbolAddress((void**)&W1T, g_W1T);    cudaGetSymbolAddress((void**)&W2T, g_W2T);

    const int SM128 = (2 * 128 * 36 + 2 * 128 * 36) * 4;   // 73728
    const int SM64  = (2 * 128 * 36 + 2 * 64 * 36) * 4;    // 55296
    cudaFuncSetAttribute(mm_gemm<128,0>, cudaFuncAttributeMaxDynamicSharedMemorySize, SM128);
    cudaFuncSetAttribute(mm_gemm<128,1>, cudaFuncAttributeMaxDynamicSharedMemorySize, SM128);
    cudaFuncSetAttribute(mm_gemm<128,2>, cudaFuncAttributeMaxDynamicSharedMemorySize, SM128);
    cudaFuncSetAttribute(mm_gemm<128,3>, cudaFuncAttributeMaxDynamicSharedMemorySize, SM128);
    cudaFuncSetAttribute(mm_gemm<64,0>,  cudaFuncAttributeMaxDynamicSharedMemorySize, SM64);

    float* x       = out;
    float* attnsum = out + OFF_ATTN;
    float* aux     = out + OFF_AUX;

    init_k <<<2306, 256>>>(out);
    embed_k<<<8192, 256>>>(seq, emb, x);

    // ---- weight transposes (once) ----
    dim3 tb(32, 8);
    tr_k<<<dim3(16,16,4), tb>>>(Wq,  WqT,  512,  512,  262144, 262144);
    tr_k<<<dim3(32,16,4), tb>>>(Wkv, WkvT, 1024, 512,  524288, 524288);
    tr_k<<<dim3(16,16,4), tb>>>(Wo,  WoT,  512,  512,  262144, 262144);
    tr_k<<<dim3(64,16,4), tb>>>(W1,  W1T,  2048, 512,  1048576, 1048576);
    tr_k<<<dim3(16,64,4), tb>>>(W2,  W2T,  512,  2048, 1048576, 1048576);
    convt2_k<<<16384, 256>>>(convw, cw);

    for (int i = 0; i < 4; i++) {
        const float* WqT_i  = WqT  + (long)i * 262144;
        const float* WkvT_i = WkvT + (long)i * 524288;     // rows 0..511 = k, 512..1023 = v
        const float* WvT_i  = WkvT_i + 262144;
        const float* WoT_i  = WoT  + (long)i * 262144;
        const float* cw_i   = cw   + (long)i * 1048576;
        const float* W1T_i  = W1T  + (long)i * 1048576;
        const float* W2T_i  = W2T  + (long)i * 1048576;
        const float* mems_i  = mems  + (long)i * 2097152;
        const float* cmems_i = cmems + (long)i * 524288;
        float* xn = out + OFF_MEMS  + (long)i * 2097152;
        float* cm = out + OFF_CMEMS + (long)i * 524288;

        ln_k<<<4096, 128>>>(x, ln1g + i * 512, ln1b + i * 512, xn);

        // q = xn @ Wq
        mm_gemm<128,0><<<dim3(4,32,1),256,SM128>>>(xn, WqT_i, q, 512, 512,512,512,
            0,0,0,0,0,0,1, nullptr);

        // k[b] = [cmems;mems;xn][b] @ Wkv_k   (rows 0/128/640)
        mm_gemm<128,0><<<dim3(4,1,8),256,SM128>>>(cmems_i, WkvT_i, k, 512, 512,512,512,
            65536,0, 0,0, 589824,0, 1, nullptr);
        mm_gemm<128,0><<<dim3(4,4,8),256,SM128>>>(mems_i, WkvT_i, k + 65536, 512, 512,512,512,
            262144,0, 0,0, 589824,0, 1, nullptr);
        mm_gemm<128,0><<<dim3(4,4,8),256,SM128>>>(xn, WkvT_i, k + 327680, 512, 512,512,512,
            262144,0, 0,0, 589824,0, 1, nullptr);

        // vT[b][d][j] = Wv^T @ in^T  (columns 0/128/640)
        mm_gemm<128,0><<<dim3(1,4,8),256,SM128>>>(WvT_i, cmems_i, vT, 512, 512,512,1152,
            0,0, 65536,0, 589824,0, 1, nullptr);
        mm_gemm<128,0><<<dim3(4,4,8),256,SM128>>>(WvT_i, mems_i, vT + 128, 512, 512,512,1152,
            0,0, 262144,0, 589824,0, 1, nullptr);
        mm_gemm<128,0><<<dim3(4,4,8),256,SM128>>>(WvT_i, xn, vT + 640, 512, 512,512,1152,
            0,0, 262144,0, 589824,0, 1, nullptr);

        // dots = q @ k^T   (z = b*8+h)
        mm_gemm<128,0><<<dim3(9,4,64),256,SM128>>>(q, k, dots, 64, 512,512,1152,
            262144,64, 589824,64, 4718592,589824, 8, nullptr);

        // aux-mem probs from the 128:640 sub-block (BEFORE in-place main softmax)
        softmax_k<512><<<32768,256>>>(dots + 128, dotsA, 1152, 0.125f, nullptr, 1);
        // main softmax (in-place) + attns_mean accumulation
        softmax_k<1152><<<32768,256>>>(dots, dots, 1152, 0.125f, attnsum, 512);

        // attno = P @ v
        mm_gemm<64,0><<<dim3(1,4,64),256,SM64>>>(dots, vT, attno, 1152, 1152,1152,512,
            4718592,589824, 589824,73728, 262144,64, 8, nullptr);

        // x = attno @ Wo + bo + x
        mm_gemm<128,2><<<dim3(4,32,1),256,SM128>>>(attno, WoT_i, x, 512, 512,512,512,
            0,0,0,0,0,0,1, bo + i * 512);

        // compressed = mems(blocked [1024,2048]) @ conv^T + conv_b
        mm_gemm<128,1><<<dim3(4,8,1),256,SM128>>>(mems_i, cw_i, cm, 2048, 2048,2048,512,
            0,0,0,0,0,0,1, convb + i * 512);

        // ck = cm @ Wkv_k ; cvT = Wv^T @ cm^T
        mm_gemm<128,0><<<dim3(4,8,1),256,SM128>>>(cm, WkvT_i, ck, 512, 512,512,512,
            0,0,0,0,0,0,1, nullptr);
        mm_gemm<128,0><<<dim3(1,4,8),256,SM128>>>(WvT_i, cm, cvT, 512, 512,512,128,
            0,0, 65536,0, 65536,0, 1, nullptr);

        // o1 = softmax(dots[...,128:640]) @ v_mem
        mm_gemm<64,0><<<dim3(1,4,64),256,SM64>>>(dotsA, vT + 128, o1, 512, 512,1152,64,
            2097152,262144, 589824,73728, 262144,32768, 8, nullptr);

        // aux-cmem: dots2 = q @ ck^T ; softmax ; o2 = P2 @ cv
        mm_gemm<128,0><<<dim3(1,4,64),256,SM128>>>(q, ck, dots2, 64, 512,512,128,
            262144,64, 65536,64, 524288,65536, 8, nullptr);
        softmax_k<128><<<32768,256>>>(dots2, dots2, 128, 0.125f, nullptr, 1);
        mm_gemm<64,0><<<dim3(1,4,64),256,SM64>>>(dots2, cvT, o2, 128, 128,128,64,
            524288,65536, 65536,8192, 262144,32768, 8, nullptr);

        mse_k<<<512,256>>>(o1, o2, aux, 2097152L);

        // FFN
        ln_k<<<4096,128>>>(x, ln2g + i * 512, ln2b + i * 512, xn2);
        mm_gemm<128,3><<<dim3(16,32,1),256,SM128>>>(xn2, W1T_i, ffh, 512, 512,512,2048,
            0,0,0,0,0,0,1, b1 + i * 2048);
        mm_gemm<128,2><<<dim3(4,32,1),256,SM128>>>(ffh, W2T_i, x, 2048, 2048,2048,512,
            0,0,0,0,0,0,1, b2 + i * 512);
    }

    final_k<<<2306,256>>>(out);
}

// round 6
// speedup vs baseline: 3.5359x; 1.3479x over previous
#include <cuda_runtime.h>
#include <cuda_fp16.h>
#include <cstdint>
#include <math.h>

// ---------------------------------------------------------------------------
// CompressiveEncoder forward. mma.sync FP16 (m16n8k16, fp32 accum) + SIMT glue.
// B=8, T=512, D=512, H=8, DH=64, MEM=512, CMEM=128, LKV=1152, DFF=2048
// Output: x | new_mems | new_cmems | aux | 0 | attns_mean  (fp32)
// ---------------------------------------------------------------------------

#define OFF_MEMS   2097152L
#define OFF_CMEMS 10485760L
#define OFF_AUX   12582912L
#define OFF_ZERO  12582913L
#define OFF_ATTN  12582914L
#define ATTN_ELEMS 589824L

// -------------------- device scratch ---------------------------------------
__device__ float g_q    [2097152];        // [b][512][512]
__device__ float g_k    [4718592];        // [b][1152][512]
__device__ float g_vT   [4718592];        // [b][512 d][1152 j]
__device__ float g_dots [4*37748736];     // per-layer [l][z=64][512][1152]
__device__ float g_dots2[4194304];        // [z][512][128] aux-cmem
__device__ float g_S    [32768];          // per-row sub-block prob mass
__device__ float g_attno[2097152];
__device__ float g_xn2  [2097152];
__device__ float g_ffh  [8388608];
__device__ float g_ck   [524288];
__device__ float g_cvT  [524288];
__device__ float g_o1   [2097152];
__device__ float g_o2   [2097152];
__device__ float g_WqT  [1048576];
__device__ float g_WkvT [2097152];
__device__ float g_WoT  [1048576];
__device__ float g_cw   [4194304];
__device__ float g_W1T  [4194304];
__device__ float g_W2T  [4194304];

// -------------------- helpers ----------------------------------------------
__device__ __forceinline__ uint32_t f2h2(float lo, float hi) {
    __half2 h = __floats2half2_rn(lo, hi);   // .x = lo, .y = hi
    return *(uint32_t*)&h;
}
__device__ __forceinline__ void mma_f16(float* d, uint32_t a0, uint32_t a1,
                                        uint32_t a2, uint32_t a3,
                                        uint32_t b0, uint32_t b1) {
    asm volatile("mma.sync.aligned.m16n8k16.row.col.f32.f16.f16.f32 "
                 "{%0,%1,%2,%3}, {%4,%5,%6,%7}, {%8,%9}, {%0,%1,%2,%3};"
                 : "+f"(d[0]), "+f"(d[1]), "+f"(d[2]), "+f"(d[3])
                 : "r"(a0), "r"(a1), "r"(a2), "r"(a3), "r"(b0), "r"(b1));
}
__device__ __forceinline__ float gelu_f(float v) {
    return 0.5f * v * (1.f + erff(v * 0.70710678118654752f));
}

// -------------------- FP16 mma batched GEMM ---------------------------------
// C[z] = A[z] @ B[z]^T. A [M,K], B [N,K] row-major fp32 in, fp32 out.
// CTA tile 128 x BN x 32, 8 warps, double-buffered smem (half2 words).
// Row stride LDSW=24 words (16 data + 8 pad): fragment LDS.64 conflict-free.
// Word layout per 16-k group: pairs [k01][k89][k23][k10,11][k45][k12,13][k67][k14,15]
// so fragment (2t..2t+1, 2t+8..2t+9) = one LDS.64 at word 2t.
// EPI: 0 none, 1 +bias, 2 +bias+C, 3 gelu(.+bias)
template<int BN, int EPI>
__global__ void __launch_bounds__(256)
hm_gemm(const float* __restrict__ A, const float* __restrict__ B, float* __restrict__ C,
        int K, int lda, int ldb, int ldc,
        long sA1, long sA2, long sB1, long sB2, long sC1, long sC2, int zmod,
        const float* __restrict__ bias)
{
    constexpr int BM = 128, LDSW = 24;
    constexpr int WN = (BN == 128) ? 4 : 2, WM = 8 / WN;
    constexpr int WTM = BM / WM, WTN = BN / WN;
    constexpr int MF = WTM / 16, NF = WTN / 8;
    constexpr int NA = (BM * 32) / 4 / 256, NB = (BN * 32) / 4 / 256;

    extern __shared__ uint32_t sm[];
    uint32_t* As = sm;                       // [2][BM*LDSW]
    uint32_t* Bs = sm + 2 * BM * LDSW;       // [2][BN*LDSW]

    const int z = blockIdx.z, zh = z / zmod, zl = z - zh * zmod;
    A += zh * sA1 + zl * sA2;
    B += zh * sB1 + zl * sB2;
    C += zh * sC1 + zl * sC2;
    const int m0 = blockIdx.y * BM, n0 = blockIdx.x * BN;
    const int tid = threadIdx.x, lane = tid & 31, wid = tid >> 5;
    const int wm = wid % WM, wn = wid / WM;
    const int mbase = wm * WTM, nbase = wn * WTN;

    float acc[MF][NF][4];
#pragma unroll
    for (int i = 0; i < MF; i++)
#pragma unroll
        for (int j = 0; j < NF; j++)
#pragma unroll
            for (int r = 0; r < 4; r++) acc[i][j][r] = 0.f;

    float4 ra[NA], rb[NB];
    const int KT = K >> 5;

    auto ldg = [&](int kt) {
        const int k0 = kt << 5;
#pragma unroll
        for (int i = 0; i < NA; i++) {
            int idx = tid + i * 256, r = idx >> 3, c4 = idx & 7;
            ra[i] = *(const float4*)(A + (long)(m0 + r) * lda + k0 + c4 * 4);
        }
#pragma unroll
        for (int i = 0; i < NB; i++) {
            int idx = tid + i * 256, r = idx >> 3, c4 = idx & 7;
            rb[i] = *(const float4*)(B + (long)(n0 + r) * ldb + k0 + c4 * 4);
        }
    };
    auto sts = [&](int st) {
        uint32_t* as = As + st * BM * LDSW;
        uint32_t* bs = Bs + st * BN * LDSW;
#pragma unroll
        for (int i = 0; i < NA; i++) {
            int idx = tid + i * 256, r = idx >> 3, c4 = idx & 7;
            int t4 = c4 & 3;
            int w0 = ((c4 >> 2) << 3) + (t4 & 1) * 4 + (t4 >> 1);
            uint32_t* p = &as[r * LDSW + w0];
            p[0] = f2h2(ra[i].x, ra[i].y);
            p[2] = f2h2(ra[i].z, ra[i].w);
        }
#pragma unroll
        for (int i = 0; i < NB; i++) {
            int idx = tid + i * 256, r = idx >> 3, c4 = idx & 7;
            int t4 = c4 & 3;
            int w0 = ((c4 >> 2) << 3) + (t4 & 1) * 4 + (t4 >> 1);
            uint32_t* p = &bs[r * LDSW + w0];
            p[0] = f2h2(rb[i].x, rb[i].y);
            p[2] = f2h2(rb[i].z, rb[i].w);
        }
    };
    auto compute = [&](int st) {
        const uint32_t* as = As + st * BM * LDSW;
        const uint32_t* bs = Bs + st * BN * LDSW;
#pragma unroll
        for (int ks = 0; ks < 2; ks++) {
            const int ko = ks * 8 + 2 * (lane & 3);
            uint2 a0[MF], a1[MF], b[NF];
#pragma unroll
            for (int mf = 0; mf < MF; mf++) {
                int r = mbase + mf * 16 + (lane >> 2);
                a0[mf] = *(const uint2*)&as[r * LDSW + ko];
                a1[mf] = *(const uint2*)&as[(r + 8) * LDSW + ko];
            }
#pragma unroll
            for (int nf = 0; nf < NF; nf++) {
                int n = nbase + nf * 8 + (lane >> 2);
                b[nf] = *(const uint2*)&bs[n * LDSW + ko];
            }
#pragma unroll
            for (int mf = 0; mf < MF; mf++)
#pragma unroll
                for (int nf = 0; nf < NF; nf++)
                    mma_f16(acc[mf][nf], a0[mf].x, a1[mf].x, a0[mf].y, a1[mf].y,
                            b[nf].x, b[nf].y);
        }
    };

    ldg(0); sts(0);
    __syncthreads();
    for (int kt = 0; kt < KT; kt++) {
        if (kt + 1 < KT) ldg(kt + 1);
        compute(kt & 1);
        if (kt + 1 < KT) {
            sts((kt + 1) & 1);
            __syncthreads();
        }
    }

    // ---- epilogue ----
    const int rbase = m0 + mbase + (lane >> 2);
    const int cbase = n0 + nbase + 2 * (lane & 3);
#pragma unroll
    for (int mf = 0; mf < MF; mf++) {
#pragma unroll
        for (int nf = 0; nf < NF; nf++) {
#pragma unroll
            for (int half = 0; half < 2; half++) {
                const int m = rbase + mf * 16 + half * 8;
                const int n = cbase + nf * 8;
                float2 v = make_float2(acc[mf][nf][half * 2], acc[mf][nf][half * 2 + 1]);
                const long idx = (long)m * ldc + n;
                if (EPI >= 1) { v.x += bias[n]; v.y += bias[n + 1]; }
                if (EPI == 2) { float2 c0 = *(const float2*)(C + idx); v.x += c0.x; v.y += c0.y; }
                if (EPI == 3) { v.x = gelu_f(v.x); v.y = gelu_f(v.y); }
                *(float2*)(C + idx) = v;
            }
        }
    }
}

// -------------------- 32x32 tiled transpose (weights only) ------------------
__global__ void tr_k(const float* __restrict__ in, float* __restrict__ out,
                     int ldi, int ldo, long sI, long sO)
{
    __shared__ float t[32][33];
    in += blockIdx.z * sI; out += blockIdx.z * sO;
    const int n0 = blockIdx.x * 32, k0 = blockIdx.y * 32;
    const int tx = threadIdx.x, ty = threadIdx.y;
#pragma unroll
    for (int j = 0; j < 32; j += 8) t[ty + j][tx] = in[(long)(k0 + ty + j) * ldi + n0 + tx];
    __syncthreads();
#pragma unroll
    for (int j = 0; j < 32; j += 8) out[(long)(n0 + ty + j) * ldo + k0 + tx] = t[tx][ty + j];
}

__global__ void convt2_k(const float* __restrict__ w, float* __restrict__ wt)
{
    long i = (long)blockIdx.x * 256 + threadIdx.x;
    if (i >= 4L * 1048576L) return;
    long l = i >> 20, r0 = i & 1048575L;
    int o = (int)(r0 >> 11), k = (int)(r0 & 2047);
    int r = k >> 9, c = k & 511;
    wt[i] = w[l * 1048576L + ((long)o * 512 + c) * 4 + r];
}

// -------------------- layernorm --------------------------------------------
__global__ void ln_k(const float* __restrict__ x, const float* __restrict__ g,
                     const float* __restrict__ b, float* __restrict__ out)
{
    const long row = blockIdx.x;
    const float* xr = x + row * 512;
    const int tid = threadIdx.x;
    float v[4]; float s = 0.f;
#pragma unroll
    for (int j = 0; j < 4; j++) { v[j] = xr[tid + j * 128]; s += v[j]; }
    __shared__ float sh[4];
#pragma unroll
    for (int o = 16; o; o >>= 1) s += __shfl_xor_sync(0xffffffffu, s, o);
    if ((tid & 31) == 0) sh[tid >> 5] = s;
    __syncthreads();
    const float mu = (sh[0] + sh[1] + sh[2] + sh[3]) * (1.f / 512.f);
    float s2 = 0.f;
#pragma unroll
    for (int j = 0; j < 4; j++) { float d = v[j] - mu; s2 += d * d; }
    __syncthreads();
#pragma unroll
    for (int o = 16; o; o >>= 1) s2 += __shfl_xor_sync(0xffffffffu, s2, o);
    if ((tid & 31) == 0) sh[tid >> 5] = s2;
    __syncthreads();
    const float rs = rsqrtf((sh[0] + sh[1] + sh[2] + sh[3]) * (1.f / 512.f) + 1e-5f);
    float* outr = out + row * 512;
#pragma unroll
    for (int j = 0; j < 4; j++) {
        int d = tid + j * 128;
        outr[d] = (v[j] - mu) * rs * g[d] + b[d];
    }
}

// -------------------- softmax; optional sub-range mass [128,640) -----------
template<int L, bool SUB>
__global__ void softmax_k(float* __restrict__ P, float scale,
                          float* __restrict__ subsum)
{
    const long row = blockIdx.x;
    float* pr = P + row * (long)L;
    const int tid = threadIdx.x;
    constexpr int NIT = (L + 255) >> 8;
    float v[NIT]; float mx = -3.0e38f;
#pragma unroll
    for (int j = 0; j < NIT; j++) {
        int i = tid + (j << 8);
        float t = (i < L) ? pr[i] * scale : -3.0e38f;
        v[j] = t; mx = fmaxf(mx, t);
    }
    __shared__ float sh[8];
#pragma unroll
    for (int o = 16; o; o >>= 1) mx = fmaxf(mx, __shfl_xor_sync(0xffffffffu, mx, o));
    if ((tid & 31) == 0) sh[tid >> 5] = mx;
    __syncthreads();
    float bm = sh[0];
#pragma unroll
    for (int w = 1; w < 8; w++) bm = fmaxf(bm, sh[w]);
    float s = 0.f, ssub = 0.f;
#pragma unroll
    for (int j = 0; j < NIT; j++) {
        int i = tid + (j << 8);
        if (i < L) {
            float e = __expf(v[j] - bm); v[j] = e; s += e;
            if (SUB && i >= 128 && i < 640) ssub += e;
        }
    }
    __syncthreads();
#pragma unroll
    for (int o = 16; o; o >>= 1) s += __shfl_xor_sync(0xffffffffu, s, o);
    if ((tid & 31) == 0) sh[tid >> 5] = s;
    __syncthreads();
    float tot = 0.f;
#pragma unroll
    for (int w = 0; w < 8; w++) tot += sh[w];
    const float inv = 1.f / tot;
    if (SUB) {
        __syncthreads();
#pragma unroll
        for (int o = 16; o; o >>= 1) ssub += __shfl_xor_sync(0xffffffffu, ssub, o);
        if ((tid & 31) == 0) sh[tid >> 5] = ssub;
        __syncthreads();
        if (tid == 0) {
            float st = 0.f;
#pragma unroll
            for (int w = 0; w < 8; w++) st += sh[w];
            subsum[row] = st * inv;
        }
    }
#pragma unroll
    for (int j = 0; j < NIT; j++) {
        int i = tid + (j << 8);
        if (i < L) pr[i] = v[j] * inv;
    }
}

// -------------------- embed / mse / attnsum / init / final ------------------
__global__ void embed_k(const int* __restrict__ seq, const float* __restrict__ emb,
                        float* __restrict__ x)
{
    long i = (long)blockIdx.x * blockDim.x + threadIdx.x;
    if (i >= 2097152L) return;
    int d = (int)(i & 511);
    long bt = i >> 9;
    int t = (int)(bt & 511);
    int tok = seq[bt];
    int j2 = d & ~1;
    float ang = (float)t * expf(-0.017988946039015984f * (float)j2);
    float pe = (d & 1) ? cosf(ang) : sinf(ang);
    x[i] = emb[(long)tok * 512 + d] + pe;
}

// aux += sum((o1/S - o2)^2);  S indexed by i>>6
__global__ void mse_k(const float* __restrict__ a, const float* __restrict__ b,
                      const float* __restrict__ S, float* __restrict__ outScalar, long n)
{
    long i0 = (long)blockIdx.x * blockDim.x + threadIdx.x;
    long stride = (long)gridDim.x * blockDim.x;
    float s = 0.f;
    for (long i = i0; i < n; i += stride) {
        float d = a[i] / S[i >> 6] - b[i];
        s += d * d;
    }
    __shared__ float sh[8];
#pragma unroll
    for (int o = 16; o; o >>= 1) s += __shfl_xor_sync(0xffffffffu, s, o);
    int tid = threadIdx.x;
    if ((tid & 31) == 0) sh[tid >> 5] = s;
    __syncthreads();
    if (tid == 0) {
        float tot = 0.f;
#pragma unroll
        for (int w = 0; w < 8; w++) tot += sh[w];
        atomicAdd(outScalar, tot);
    }
}

// attns_mean: out[i] = mean over 256 slices of dots[s*589824 + i]
__global__ void attnsum_k(const float* __restrict__ dots, float* __restrict__ out)
{
    long i = (long)blockIdx.x * 256 + threadIdx.x;
    if (i >= ATTN_ELEMS) return;
    float s = 0.f;
    const float* p = dots + i;
#pragma unroll 8
    for (int sl = 0; sl < 256; sl++) s += p[(long)sl * 589824L];
    out[OFF_ATTN + i] = s * (1.f / 256.f);
}

__global__ void init_k(float* __restrict__ out)
{
    if (blockIdx.x == 0 && threadIdx.x == 0) { out[OFF_AUX] = 0.f; out[OFF_ZERO] = 0.f; }
}
__global__ void final_k(float* __restrict__ out)
{
    if (blockIdx.x == 0 && threadIdx.x == 0) out[OFF_AUX] *= (1.f / (4.f * 2097152.f));
}

// ---------------------------------------------------------------------------
extern "C" void kernel_launch(void* const* d_in, const int* in_sizes, int n_in,
                              void* d_out, int out_size)
{
    const int*   seq   = (const int*)  d_in[0];
    const float* mems  = (const float*)d_in[2];
    const float* cmems = (const float*)d_in[3];
    const float* emb   = (const float*)d_in[4];
    const float* ln1g  = (const float*)d_in[5];
    const float* ln1b  = (const float*)d_in[6];
    const float* Wq    = (const float*)d_in[7];
    const float* Wkv   = (const float*)d_in[8];
    const float* Wo    = (const float*)d_in[9];
    const float* bo    = (const float*)d_in[10];
    const float* convw = (const float*)d_in[11];
    const float* convb = (const float*)d_in[12];
    const float* ln2g  = (const float*)d_in[13];
    const float* ln2b  = (const float*)d_in[14];
    const float* W1    = (const float*)d_in[15];
    const float* b1    = (const float*)d_in[16];
    const float* W2    = (const float*)d_in[17];
    const float* b2    = (const float*)d_in[18];
    float* out = (float*)d_out;

    float *q, *k, *vT, *dots, *dots2, *Ssub, *attno, *xn2, *ffh, *ck, *cvT, *o1, *o2;
    float *WqT, *WkvT, *WoT, *cw, *W1T, *W2T;
    cudaGetSymbolAddress((void**)&q, g_q);        cudaGetSymbolAddress((void**)&k, g_k);
    cudaGetSymbolAddress((void**)&vT, g_vT);      cudaGetSymbolAddress((void**)&dots, g_dots);
    cudaGetSymbolAddress((void**)&dots2, g_dots2);cudaGetSymbolAddress((void**)&Ssub, g_S);
    cudaGetSymbolAddress((void**)&attno, g_attno);cudaGetSymbolAddress((void**)&xn2, g_xn2);
    cudaGetSymbolAddress((void**)&ffh, g_ffh);    cudaGetSymbolAddress((void**)&ck, g_ck);
    cudaGetSymbolAddress((void**)&cvT, g_cvT);    cudaGetSymbolAddress((void**)&o1, g_o1);
    cudaGetSymbolAddress((void**)&o2, g_o2);
    cudaGetSymbolAddress((void**)&WqT, g_WqT);    cudaGetSymbolAddress((void**)&WkvT, g_WkvT);
    cudaGetSymbolAddress((void**)&WoT, g_WoT);    cudaGetSymbolAddress((void**)&cw, g_cw);
    cudaGetSymbolAddress((void**)&W1T, g_W1T);    cudaGetSymbolAddress((void**)&W2T, g_W2T);

    const int SM128 = 2 * (128 + 128) * 24 * 4;   // 49152
    const int SM64  = 2 * (128 + 64) * 24 * 4;    // 36864
    cudaFuncSetAttribute(hm_gemm<128,0>, cudaFuncAttributeMaxDynamicSharedMemorySize, SM128);
    cudaFuncSetAttribute(hm_gemm<128,1>, cudaFuncAttributeMaxDynamicSharedMemorySize, SM128);
    cudaFuncSetAttribute(hm_gemm<128,2>, cudaFuncAttributeMaxDynamicSharedMemorySize, SM128);
    cudaFuncSetAttribute(hm_gemm<128,3>, cudaFuncAttributeMaxDynamicSharedMemorySize, SM128);
    cudaFuncSetAttribute(hm_gemm<64,0>,  cudaFuncAttributeMaxDynamicSharedMemorySize, SM64);

    float* x   = out;
    float* aux = out + OFF_AUX;

    init_k <<<1, 32>>>(out);
    embed_k<<<8192, 256>>>(seq, emb, x);

    dim3 tb(32, 8);
    tr_k<<<dim3(16,16,4), tb>>>(Wq,  WqT,  512,  512,  262144, 262144);
    tr_k<<<dim3(32,16,4), tb>>>(Wkv, WkvT, 1024, 512,  524288, 524288);
    tr_k<<<dim3(16,16,4), tb>>>(Wo,  WoT,  512,  512,  262144, 262144);
    tr_k<<<dim3(64,16,4), tb>>>(W1,  W1T,  2048, 512,  1048576, 1048576);
    tr_k<<<dim3(16,64,4), tb>>>(W2,  W2T,  512,  2048, 1048576, 1048576);
    convt2_k<<<16384, 256>>>(convw, cw);

    for (int i = 0; i < 4; i++) {
        const float* WqT_i  = WqT  + (long)i * 262144;
        const float* WkvT_i = WkvT + (long)i * 524288;
        const float* WvT_i  = WkvT_i + 262144;
        const float* WoT_i  = WoT  + (long)i * 262144;
        const float* cw_i   = cw   + (long)i * 1048576;
        const float* W1T_i  = W1T  + (long)i * 1048576;
        const float* W2T_i  = W2T  + (long)i * 1048576;
        const float* mems_i  = mems  + (long)i * 2097152;
        const float* cmems_i = cmems + (long)i * 524288;
        float* xn = out + OFF_MEMS  + (long)i * 2097152;
        float* cm = out + OFF_CMEMS + (long)i * 524288;
        float* dots_l = dots + (long)i * 37748736;

        ln_k<<<4096, 128>>>(x, ln1g + i * 512, ln1b + i * 512, xn);

        // q = xn @ Wq
        hm_gemm<128,0><<<dim3(4,32,1),256,SM128>>>(xn, WqT_i, q, 512, 512,512,512,
            0,0,0,0,0,0,1, nullptr);

        // k[b] = [cmems;mems;xn][b] @ Wkv_k
        hm_gemm<128,0><<<dim3(4,1,8),256,SM128>>>(cmems_i, WkvT_i, k, 512, 512,512,512,
            65536,0, 0,0, 589824,0, 1, nullptr);
        hm_gemm<128,0><<<dim3(4,4,8),256,SM128>>>(mems_i, WkvT_i, k + 65536, 512, 512,512,512,
            262144,0, 0,0, 589824,0, 1, nullptr);
        hm_gemm<128,0><<<dim3(4,4,8),256,SM128>>>(xn, WkvT_i, k + 327680, 512, 512,512,512,
            262144,0, 0,0, 589824,0, 1, nullptr);

        // vT[b][d][j] = Wv^T @ in^T
        hm_gemm<128,0><<<dim3(1,4,8),256,SM128>>>(WvT_i, cmems_i, vT, 512, 512,512,1152,
            0,0, 65536,0, 589824,0, 1, nullptr);
        hm_gemm<128,0><<<dim3(4,4,8),256,SM128>>>(WvT_i, mems_i, vT + 128, 512, 512,512,1152,
            0,0, 262144,0, 589824,0, 1, nullptr);
        hm_gemm<128,0><<<dim3(4,4,8),256,SM128>>>(WvT_i, xn, vT + 640, 512, 512,512,1152,
            0,0, 262144,0, 589824,0, 1, nullptr);

        // dots = q @ k^T  (z = b*8+h)
        hm_gemm<128,0><<<dim3(9,4,64),256,SM128>>>(q, k, dots_l, 64, 512,512,1152,
            262144,64, 589824,64, 4718592,589824, 8, nullptr);

        // softmax in place; also emit sub-block mass S for aux-mem rescale
        softmax_k<1152,true><<<32768,256>>>(dots_l, 0.125f, Ssub);

        // attno = P @ v
        hm_gemm<64,0><<<dim3(1,4,64),256,SM64>>>(dots_l, vT, attno, 1152, 1152,1152,512,
            4718592,589824, 589824,73728, 262144,64, 8, nullptr);

        // x = attno @ Wo + bo + x
        hm_gemm<128,2><<<dim3(4,32,1),256,SM128>>>(attno, WoT_i, x, 512, 512,512,512,
            0,0,0,0,0,0,1, bo + i * 512);

        // compressed = mems(blocked) @ conv^T + conv_b
        hm_gemm<128,1><<<dim3(4,8,1),256,SM128>>>(mems_i, cw_i, cm, 2048, 2048,2048,512,
            0,0,0,0,0,0,1, convb + i * 512);

        // ck = cm @ Wkv_k ; cvT = Wv^T @ cm^T
        hm_gemm<128,0><<<dim3(4,8,1),256,SM128>>>(cm, WkvT_i, ck, 512, 512,512,512,
            0,0,0,0,0,0,1, nullptr);
        hm_gemm<128,0><<<dim3(1,4,8),256,SM128>>>(WvT_i, cm, cvT, 512, 512,512,128,
            0,0, 65536,0, 65536,0, 1, nullptr);

        // o1_raw = P[:,128:640] @ v_mem   (rescaled by 1/S inside mse)
        hm_gemm<64,0><<<dim3(1,4,64),256,SM64>>>(dots_l + 128, vT + 128, o1, 512, 1152,1152,64,
            4718592,589824, 589824,73728, 262144,32768, 8, nullptr);

        // aux-cmem branch
        hm_gemm<128,0><<<dim3(1,4,64),256,SM128>>>(q, ck, dots2, 64, 512,512,128,
            262144,64, 65536,64, 524288,65536, 8, nullptr);
        softmax_k<128,false><<<32768,256>>>(dots2, 0.125f, nullptr);
        hm_gemm<64,0><<<dim3(1,4,64),256,SM64>>>(dots2, cvT, o2, 128, 128,128,64,
            524288,65536, 65536,8192, 262144,32768, 8, nullptr);

        mse_k<<<512,256>>>(o1, o2, Ssub, aux, 2097152L);

        // FFN
        ln_k<<<4096,128>>>(x, ln2g + i * 512, ln2b + i * 512, xn2);
        hm_gemm<128,3><<<dim3(16,32,1),256,SM128>>>(xn2, W1T_i, ffh, 512, 512,512,2048,
            0,0,0,0,0,0,1, b1 + i * 2048);
        hm_gemm<128,2><<<dim3(4,32,1),256,SM128>>>(ffh, W2T_i, x, 2048, 2048,2048,512,
            0,0,0,0,0,0,1, b2 + i * 512);
    }

    attnsum_k<<<2304,256>>>(dots, out);
    final_k<<<1,32>>>(out);
}

// round 8
// speedup vs baseline: 4.4906x; 1.2700x over previous
#include <cuda_runtime.h>
#include <cuda_fp16.h>
#include <cstdint>
#include <math.h>

// ---------------------------------------------------------------------------
// CompressiveEncoder forward. FP16-storage mma.sync GEMMs (m16n8k16, fp32 acc).
// B=8, T=512, D=512, H=8, DH=64, MEM=512, CMEM=128, LKV=1152, DFF=2048
// Output: x | new_mems | new_cmems | aux | 0 | attns_mean  (fp32)
// ---------------------------------------------------------------------------

#define OFF_MEMS   2097152L
#define OFF_CMEMS 10485760L
#define OFF_AUX   12582912L
#define OFF_ZERO  12582913L
#define OFF_ATTN  12582914L
#define ATTN_ELEMS 589824L

// -------------------- device scratch ---------------------------------------
// fp16 operands
__device__ __half g_hmems [8388608];      // mems cvt
__device__ __half g_hcmems[2097152];
__device__ __half g_hxn   [2097152];
__device__ __half g_hxn2  [2097152];
__device__ __half g_kvin  [4718592];      // [b][1152][512]
__device__ __half g_qh    [2097152];
__device__ __half g_kh    [4718592];      // [b][1152][512]
__device__ __half g_vTh   [4718592];      // [b][512 d][1152 j]
__device__ __half g_dotsH [150994944];    // per-layer probs [l][64][512][1152]
__device__ __half g_dots2H[4194304];
__device__ __half g_attnoh[2097152];
__device__ __half g_ffhh  [8388608];
__device__ __half g_cmh   [524288];
__device__ __half g_ckh   [524288];
__device__ __half g_cvTh  [524288];
__device__ __half g_WqTh  [1048576];
__device__ __half g_WkvTh [2097152];
__device__ __half g_WoTh  [1048576];
__device__ __half g_cwh   [4194304];
__device__ __half g_W1Th  [4194304];
__device__ __half g_W2Th  [4194304];
// fp32
__device__ float g_dots [37748736];       // logits (reused per layer)
__device__ float g_dots2[4194304];
__device__ float g_o1   [2097152];
__device__ float g_o2   [2097152];
__device__ float g_S    [32768];

// -------------------- helpers ----------------------------------------------
__device__ __forceinline__ void mma_f16(float* d, uint32_t a0, uint32_t a1,
                                        uint32_t a2, uint32_t a3,
                                        uint32_t b0, uint32_t b1) {
    asm volatile("mma.sync.aligned.m16n8k16.row.col.f32.f16.f16.f32 "
                 "{%0,%1,%2,%3}, {%4,%5,%6,%7}, {%8,%9}, {%0,%1,%2,%3};"
                 : "+f"(d[0]), "+f"(d[1]), "+f"(d[2]), "+f"(d[3])
                 : "r"(a0), "r"(a1), "r"(a2), "r"(a3), "r"(b0), "r"(b1));
}
__device__ __forceinline__ float gelu_f(float v) {
    return 0.5f * v * (1.f + erff(v * 0.70710678118654752f));
}

// -------------------- FP16 mma batched GEMM ---------------------------------
// C[z] = A[z] @ B[z]^T. A [M,K], B [N,K] row-major __half. fp32 accum.
// CTA tile 128 x BN x 32, 8 warps, double-buffered smem.
// Row = 16 data words (32 halves), LDSW=24 (8 pad) -> LDS.64 conflict-free.
// Word permutation per 16-k group: slot(wg) = 2*(wg&3)+(wg>>2), so fragment
// (k:2t,2t+1 | 2t+8,2t+9) is one LDS.64 at word 2t.
// EPI: 0 none, 1 +bias, 2 +bias+Cf, 3 gelu(.+bias)
// OUT: 0 fp32 Cf, 1 fp16 Ch, 2 both
template<int BN, int EPI, int OUT>
__global__ void __launch_bounds__(256)
hm_gemm(const __half* __restrict__ A, const __half* __restrict__ B,
        float* __restrict__ Cf, __half* __restrict__ Ch,
        int K, int lda, int ldb, int ldc,
        long sA1, long sA2, long sB1, long sB2, long sC1, long sC2, int zmod,
        const float* __restrict__ bias)
{
    constexpr int BM = 128, LDSW = 24;
    constexpr int WN = (BN == 128) ? 4 : 2, WM = 8 / WN;
    constexpr int WTM = BM / WM, WTN = BN / WN;
    constexpr int MF = WTM / 16, NF = WTN / 8;
    constexpr int NA = (BM * 4) / 256, NB = (BN * 4) / 256;   // uint4 per thread

    extern __shared__ uint32_t sm[];
    uint32_t* As = sm;                       // [2][BM*LDSW]
    uint32_t* Bs = sm + 2 * BM * LDSW;       // [2][BN*LDSW]

    const int z = blockIdx.z, zh = z / zmod, zl = z - zh * zmod;
    A += zh * sA1 + zl * sA2;
    B += zh * sB1 + zl * sB2;
    const long coff = zh * sC1 + zl * sC2;
    if (OUT != 1) Cf += coff;
    if (OUT >= 1) Ch += coff;
    const int m0 = blockIdx.y * BM, n0 = blockIdx.x * BN;
    const int tid = threadIdx.x, lane = tid & 31, wid = tid >> 5;
    const int wm = wid % WM, wn = wid / WM;
    const int mbase = wm * WTM, nbase = wn * WTN;

    float acc[MF][NF][4];
#pragma unroll
    for (int i = 0; i < MF; i++)
#pragma unroll
        for (int j = 0; j < NF; j++)
#pragma unroll
            for (int r = 0; r < 4; r++) acc[i][j][r] = 0.f;

    uint4 ra[NA], rb[NB];
    const int KT = K >> 5;

    auto ldg = [&](int kt) {
        const int k0 = kt << 5;
#pragma unroll
        for (int i = 0; i < NA; i++) {
            int idx = tid + i * 256, r = idx >> 2, c = idx & 3;
            ra[i] = *(const uint4*)(A + (long)(m0 + r) * lda + k0 + c * 8);
        }
#pragma unroll
        for (int i = 0; i < NB; i++) {
            int idx = tid + i * 256, r = idx >> 2, c = idx & 3;
            rb[i] = *(const uint4*)(B + (long)(n0 + r) * ldb + k0 + c * 8);
        }
    };
    auto sts = [&](int st) {
        uint32_t* as = As + st * BM * LDSW;
        uint32_t* bs = Bs + st * BN * LDSW;
#pragma unroll
        for (int i = 0; i < NA; i++) {
            int idx = tid + i * 256, r = idx >> 2, c = idx & 3;
            uint32_t* p = &as[r * LDSW + ((c >> 1) << 3) + (c & 1)];
            p[0] = ra[i].x; p[2] = ra[i].y; p[4] = ra[i].z; p[6] = ra[i].w;
        }
#pragma unroll
        for (int i = 0; i < NB; i++) {
            int idx = tid + i * 256, r = idx >> 2, c = idx & 3;
            uint32_t* p = &bs[r * LDSW + ((c >> 1) << 3) + (c & 1)];
            p[0] = rb[i].x; p[2] = rb[i].y; p[4] = rb[i].z; p[6] = rb[i].w;
        }
    };
    auto compute = [&](int st) {
        const uint32_t* as = As + st * BM * LDSW;
        const uint32_t* bs = Bs + st * BN * LDSW;
#pragma unroll
        for (int ks = 0; ks < 2; ks++) {
            const int ko = ks * 8 + 2 * (lane & 3);
            uint2 a0[MF], a1[MF], b[NF];
#pragma unroll
            for (int mf = 0; mf < MF; mf++) {
                int r = mbase + mf * 16 + (lane >> 2);
                a0[mf] = *(const uint2*)&as[r * LDSW + ko];
                a1[mf] = *(const uint2*)&as[(r + 8) * LDSW + ko];
            }
#pragma unroll
            for (int nf = 0; nf < NF; nf++) {
                int n = nbase + nf * 8 + (lane >> 2);
                b[nf] = *(const uint2*)&bs[n * LDSW + ko];
            }
#pragma unroll
            for (int mf = 0; mf < MF; mf++)
#pragma unroll
                for (int nf = 0; nf < NF; nf++)
                    mma_f16(acc[mf][nf], a0[mf].x, a1[mf].x, a0[mf].y, a1[mf].y,
                            b[nf].x, b[nf].y);
        }
    };

    ldg(0); sts(0);
    __syncthreads();
    for (int kt = 0; kt < KT; kt++) {
        if (kt + 1 < KT) ldg(kt + 1);
        compute(kt & 1);
        if (kt + 1 < KT) {
            sts((kt + 1) & 1);
            __syncthreads();
        }
    }

    // ---- epilogue ----
    const int rbase = m0 + mbase + (lane >> 2);
    const int cbase = n0 + nbase + 2 * (lane & 3);
#pragma unroll
    for (int mf = 0; mf < MF; mf++) {
#pragma unroll
        for (int nf = 0; nf < NF; nf++) {
#pragma unroll
            for (int half = 0; half < 2; half++) {
                const int m = rbase + mf * 16 + half * 8;
                const int n = cbase + nf * 8;
                float2 v = make_float2(acc[mf][nf][half * 2], acc[mf][nf][half * 2 + 1]);
                const long idx = (long)m * ldc + n;
                if (EPI >= 1) { v.x += bias[n]; v.y += bias[n + 1]; }
                if (EPI == 2) { float2 c0 = *(const float2*)(Cf + idx); v.x += c0.x; v.y += c0.y; }
                if (EPI == 3) { v.x = gelu_f(v.x); v.y = gelu_f(v.y); }
                if (OUT != 1) *(float2*)(Cf + idx) = v;
                if (OUT >= 1) *(__half2*)(Ch + idx) = __floats2half2_rn(v.x, v.y);
            }
        }
    }
}

// -------------------- weight transpose fp32 -> fp16 -------------------------
__global__ void tr_k(const float* __restrict__ in, __half* __restrict__ out,
                     int ldi, int ldo, long sI, long sO)
{
    __shared__ float t[32][33];
    in += blockIdx.z * sI; out += blockIdx.z * sO;
    const int n0 = blockIdx.x * 32, k0 = blockIdx.y * 32;
    const int tx = threadIdx.x, ty = threadIdx.y;
#pragma unroll
    for (int j = 0; j < 32; j += 8) t[ty + j][tx] = in[(long)(k0 + ty + j) * ldi + n0 + tx];
    __syncthreads();
#pragma unroll
    for (int j = 0; j < 32; j += 8)
        out[(long)(n0 + ty + j) * ldo + k0 + tx] = __float2half(t[tx][ty + j]);
}

// conv weight: cwh[l][o][r*512+c] = conv_w[l][o][c][r]  (fp16)
__global__ void convt2_k(const float* __restrict__ w, __half* __restrict__ wt)
{
    long i = (long)blockIdx.x * 256 + threadIdx.x;
    if (i >= 4L * 1048576L) return;
    long l = i >> 20, r0 = i & 1048575L;
    int o = (int)(r0 >> 11), k = (int)(r0 & 2047);
    int r = k >> 9, c = k & 511;
    wt[i] = __float2half(w[l * 1048576L + ((long)o * 512 + c) * 4 + r]);
}

// fp32 -> fp16 bulk convert (n4 float4 groups)
__global__ void cvt16_k(const float* __restrict__ in, __half* __restrict__ out, long n4)
{
    long i = (long)blockIdx.x * 256 + threadIdx.x;
    if (i >= n4) return;
    float4 v = ((const float4*)in)[i];
    ((__half2*)out)[2 * i]     = __floats2half2_rn(v.x, v.y);
    ((__half2*)out)[2 * i + 1] = __floats2half2_rn(v.z, v.w);
}

// kvin[b][j][c] assemble from cmems|mems|xn (fp16, uint4 granularity)
__global__ void kvin_k(const __half* __restrict__ hc, const __half* __restrict__ hm,
                       const __half* __restrict__ hx, __half* __restrict__ kvin)
{
    long u = (long)blockIdx.x * 256 + threadIdx.x;
    if (u >= 589824L) return;
    int c8 = (int)(u & 63);
    long bj = u >> 6;
    int j = (int)(bj % 1152);
    int b = (int)(bj / 1152);
    const uint4* src;
    if (j < 128)      src = (const uint4*)hc + ((long)b * 128 + j) * 64 + c8;
    else if (j < 640) src = (const uint4*)hm + ((long)b * 512 + (j - 128)) * 64 + c8;
    else              src = (const uint4*)hx + ((long)b * 512 + (j - 640)) * 64 + c8;
    ((uint4*)kvin)[u] = *src;
}

// -------------------- layernorm (fp32 + optional fp16 out) ------------------
__global__ void ln_k(const float* __restrict__ x, const float* __restrict__ g,
                     const float* __restrict__ b, float* __restrict__ out,
                     __half* __restrict__ outh)
{
    const long row = blockIdx.x;
    const float* xr = x + row * 512;
    const int tid = threadIdx.x;
    float v[4]; float s = 0.f;
#pragma unroll
    for (int j = 0; j < 4; j++) { v[j] = xr[tid + j * 128]; s += v[j]; }
    __shared__ float sh[4];
#pragma unroll
    for (int o = 16; o; o >>= 1) s += __shfl_xor_sync(0xffffffffu, s, o);
    if ((tid & 31) == 0) sh[tid >> 5] = s;
    __syncthreads();
    const float mu = (sh[0] + sh[1] + sh[2] + sh[3]) * (1.f / 512.f);
    float s2 = 0.f;
#pragma unroll
    for (int j = 0; j < 4; j++) { float d = v[j] - mu; s2 += d * d; }
    __syncthreads();
#pragma unroll
    for (int o = 16; o; o >>= 1) s2 += __shfl_xor_sync(0xffffffffu, s2, o);
    if ((tid & 31) == 0) sh[tid >> 5] = s2;
    __syncthreads();
    const float rs = rsqrtf((sh[0] + sh[1] + sh[2] + sh[3]) * (1.f / 512.f) + 1e-5f);
#pragma unroll
    for (int j = 0; j < 4; j++) {
        int d = tid + j * 128;
        float val = (v[j] - mu) * rs * g[d] + b[d];
        if (out)  out[row * 512 + d] = val;
        outh[row * 512 + d] = __float2half(val);
    }
}

// -------------------- softmax fp32 -> fp16; optional sub-mass [128,640) ----
template<int L, bool SUB>
__global__ void softmax_k(const float* __restrict__ In, __half* __restrict__ Out,
                          float scale, float* __restrict__ subsum)
{
    const long row = blockIdx.x;
    const float* ir = In + row * (long)L;
    __half* orow = Out + row * (long)L;
    const int tid = threadIdx.x;
    constexpr int NIT = (L + 255) >> 8;
    float v[NIT]; float mx = -3.0e38f;
#pragma unroll
    for (int j = 0; j < NIT; j++) {
        int i = tid + (j << 8);
        float t = (i < L) ? ir[i] * scale : -3.0e38f;
        v[j] = t; mx = fmaxf(mx, t);
    }
    __shared__ float sh[8];
#pragma unroll
    for (int o = 16; o; o >>= 1) mx = fmaxf(mx, __shfl_xor_sync(0xffffffffu, mx, o));
    if ((tid & 31) == 0) sh[tid >> 5] = mx;
    __syncthreads();
    float bm = sh[0];
#pragma unroll
    for (int w = 1; w < 8; w++) bm = fmaxf(bm, sh[w]);
    float s = 0.f, ssub = 0.f;
#pragma unroll
    for (int j = 0; j < NIT; j++) {
        int i = tid + (j << 8);
        if (i < L) {
            float e = __expf(v[j] - bm); v[j] = e; s += e;
            if (SUB && i >= 128 && i < 640) ssub += e;
        }
    }
    __syncthreads();
#pragma unroll
    for (int o = 16; o; o >>= 1) s += __shfl_xor_sync(0xffffffffu, s, o);
    if ((tid & 31) == 0) sh[tid >> 5] = s;
    __syncthreads();
    float tot = 0.f;
#pragma unroll
    for (int w = 0; w < 8; w++) tot += sh[w];
    const float inv = 1.f / tot;
    if (SUB) {
        __syncthreads();
#pragma unroll
        for (int o = 16; o; o >>= 1) ssub += __shfl_xor_sync(0xffffffffu, ssub, o);
        if ((tid & 31) == 0) sh[tid >> 5] = ssub;
        __syncthreads();
        if (tid == 0) {
            float st = 0.f;
#pragma unroll
            for (int w = 0; w < 8; w++) st += sh[w];
            subsum[row] = st * inv;
        }
    }
#pragma unroll
    for (int j = 0; j < NIT; j++) {
        int i = tid + (j << 8);
        if (i < L) orow[i] = __float2half(v[j] * inv);
    }
}

// -------------------- embed / mse / attnsum / init / final ------------------
__global__ void embed_k(const int* __restrict__ seq, const float* __restrict__ emb,
                        float* __restrict__ x)
{
    long i = (long)blockIdx.x * blockDim.x + threadIdx.x;
    if (i >= 2097152L) return;
    int d = (int)(i & 511);
    long bt = i >> 9;
    int t = (int)(bt & 511);
    int tok = seq[bt];
    int j2 = d & ~1;
    float ang = (float)t * expf(-0.017988946039015984f * (float)j2);
    float pe = (d & 1) ? cosf(ang) : sinf(ang);
    x[i] = emb[(long)tok * 512 + d] + pe;
}

__global__ void mse_k(const float* __restrict__ a, const float* __restrict__ b,
                      const float* __restrict__ S, float* __restrict__ outScalar, long n)
{
    long i0 = (long)blockIdx.x * blockDim.x + threadIdx.x;
    long stride = (long)gridDim.x * blockDim.x;
    float s = 0.f;
    for (long i = i0; i < n; i += stride) {
        float d = a[i] / S[i >> 6] - b[i];
        s += d * d;
    }
    __shared__ float sh[8];
#pragma unroll
    for (int o = 16; o; o >>= 1) s += __shfl_xor_sync(0xffffffffu, s, o);
    int tid = threadIdx.x;
    if ((tid & 31) == 0) sh[tid >> 5] = s;
    __syncthreads();
    if (tid == 0) {
        float tot = 0.f;
#pragma unroll
        for (int w = 0; w < 8; w++) tot += sh[w];
        atomicAdd(outScalar, tot);
    }
}

// attns_mean from fp16 probs: mean over 256 slices
__global__ void attnsum_k(const __half* __restrict__ dotsH, float* __restrict__ out)
{
    long i = (long)blockIdx.x * 256 + threadIdx.x;    // half2 index
    if (i >= 294912L) return;
    const __half2* p = (const __half2*)dotsH + i;
    float sx = 0.f, sy = 0.f;
#pragma unroll 8
    for (int sl = 0; sl < 256; sl++) {
        float2 f = __half22float2(p[(long)sl * 294912L]);
        sx += f.x; sy += f.y;
    }
    *(float2*)(out + OFF_ATTN + 2 * i) = make_float2(sx * (1.f / 256.f), sy * (1.f / 256.f));
}

__global__ void init_k(float* __restrict__ out)
{
    if (threadIdx.x == 0) { out[OFF_AUX] = 0.f; out[OFF_ZERO] = 0.f; }
}
__global__ void final_k(float* __restrict__ out)
{
    if (threadIdx.x == 0) out[OFF_AUX] *= (1.f / (4.f * 2097152.f));
}

// ---------------------------------------------------------------------------
extern "C" void kernel_launch(void* const* d_in, const int* in_sizes, int n_in,
                              void* d_out, int out_size)
{
    const int*   seq   = (const int*)  d_in[0];
    const float* mems  = (const float*)d_in[2];
    const float* cmems = (const float*)d_in[3];
    const float* emb   = (const float*)d_in[4];
    const float* ln1g  = (const float*)d_in[5];
    const float* ln1b  = (const float*)d_in[6];
    const float* Wq    = (const float*)d_in[7];
    const float* Wkv   = (const float*)d_in[8];
    const float* Wo    = (const float*)d_in[9];
    const float* bo    = (const float*)d_in[10];
    const float* convw = (const float*)d_in[11];
    const float* convb = (const float*)d_in[12];
    const float* ln2g  = (const float*)d_in[13];
    const float* ln2b  = (const float*)d_in[14];
    const float* W1    = (const float*)d_in[15];
    const float* b1    = (const float*)d_in[16];
    const float* W2    = (const float*)d_in[17];
    const float* b2    = (const float*)d_in[18];
    float* out = (float*)d_out;

    __half *hmems, *hcmems, *hxn, *hxn2, *kvin, *qh, *kh, *vTh, *dotsH, *dots2H;
    __half *attnoh, *ffhh, *cmh, *ckh, *cvTh;
    __half *WqTh, *WkvTh, *WoTh, *cwh, *W1Th, *W2Th;
    float *dots, *dots2, *o1, *o2, *Ssub;
    cudaGetSymbolAddress((void**)&hmems, g_hmems);   cudaGetSymbolAddress((void**)&hcmems, g_hcmems);
    cudaGetSymbolAddress((void**)&hxn, g_hxn);       cudaGetSymbolAddress((void**)&hxn2, g_hxn2);
    cudaGetSymbolAddress((void**)&kvin, g_kvin);     cudaGetSymbolAddress((void**)&qh, g_qh);
    cudaGetSymbolAddress((void**)&kh, g_kh);         cudaGetSymbolAddress((void**)&vTh, g_vTh);
    cudaGetSymbolAddress((void**)&dotsH, g_dotsH);   cudaGetSymbolAddress((void**)&dots2H, g_dots2H);
    cudaGetSymbolAddress((void**)&attnoh, g_attnoh); cudaGetSymbolAddress((void**)&ffhh, g_ffhh);
    cudaGetSymbolAddress((void**)&cmh, g_cmh);       cudaGetSymbolAddress((void**)&ckh, g_ckh);
    cudaGetSymbolAddress((void**)&cvTh, g_cvTh);
    cudaGetSymbolAddress((void**)&WqTh, g_WqTh);     cudaGetSymbolAddress((void**)&WkvTh, g_WkvTh);
    cudaGetSymbolAddress((void**)&WoTh, g_WoTh);     cudaGetSymbolAddress((void**)&cwh, g_cwh);
    cudaGetSymbolAddress((void**)&W1Th, g_W1Th);     cudaGetSymbolAddress((void**)&W2Th, g_W2Th);
    cudaGetSymbolAddress((void**)&dots, g_dots);     cudaGetSymbolAddress((void**)&dots2, g_dots2);
    cudaGetSymbolAddress((void**)&o1, g_o1);         cudaGetSymbolAddress((void**)&o2, g_o2);
    cudaGetSymbolAddress((void**)&Ssub, g_S);

    const int SM128 = 2 * (128 + 128) * 24 * 4;   // 49152
    const int SM64  = 2 * (128 + 64) * 24 * 4;    // 36864
    cudaFuncSetAttribute(hm_gemm<128,0,0>, cudaFuncAttributeMaxDynamicSharedMemorySize, SM128);
    cudaFuncSetAttribute(hm_gemm<128,0,1>, cudaFuncAttributeMaxDynamicSharedMemorySize, SM128);
    cudaFuncSetAttribute(hm_gemm<128,1,2>, cudaFuncAttributeMaxDynamicSharedMemorySize, SM128);
    cudaFuncSetAttribute(hm_gemm<128,2,0>, cudaFuncAttributeMaxDynamicSharedMemorySize, SM128);
    cudaFuncSetAttribute(hm_gemm<128,3,1>, cudaFuncAttributeMaxDynamicSharedMemorySize, SM128);
    cudaFuncSetAttribute(hm_gemm<64,0,0>,  cudaFuncAttributeMaxDynamicSharedMemorySize, SM64);
    cudaFuncSetAttribute(hm_gemm<64,0,1>,  cudaFuncAttributeMaxDynamicSharedMemorySize, SM64);

    float* x   = out;
    float* aux = out + OFF_AUX;

    init_k <<<1, 32>>>(out);
    embed_k<<<8192, 256>>>(seq, emb, x);

    // ---- one-time conversions ----
    dim3 tb(32, 8);
    tr_k<<<dim3(16,16,4), tb>>>(Wq,  WqTh,  512,  512,  262144, 262144);
    tr_k<<<dim3(32,16,4), tb>>>(Wkv, WkvTh, 1024, 512,  524288, 524288);
    tr_k<<<dim3(16,16,4), tb>>>(Wo,  WoTh,  512,  512,  262144, 262144);
    tr_k<<<dim3(64,16,4), tb>>>(W1,  W1Th,  2048, 512,  1048576, 1048576);
    tr_k<<<dim3(16,64,4), tb>>>(W2,  W2Th,  512,  2048, 1048576, 1048576);
    convt2_k<<<16384, 256>>>(convw, cwh);
    cvt16_k<<<8192, 256>>>(mems,  hmems,  2097152L);
    cvt16_k<<<2048, 256>>>(cmems, hcmems, 524288L);

    for (int i = 0; i < 4; i++) {
        const __half* WqTh_i  = WqTh  + (long)i * 262144;
        const __half* WkvTh_i = WkvTh + (long)i * 524288;
        const __half* WvTh_i  = WkvTh_i + 262144;
        const __half* WoTh_i  = WoTh  + (long)i * 262144;
        const __half* cwh_i   = cwh   + (long)i * 1048576;
        const __half* W1Th_i  = W1Th  + (long)i * 1048576;
        const __half* W2Th_i  = W2Th  + (long)i * 1048576;
        const __half* hmems_i  = hmems  + (long)i * 2097152;
        const __half* hcmems_i = hcmems + (long)i * 524288;
        float* xn = out + OFF_MEMS  + (long)i * 2097152;
        float* cm = out + OFF_CMEMS + (long)i * 524288;
        __half* dotsH_l = dotsH + (long)i * 37748736;

        // LN1: fp32 -> new_mems slot, fp16 -> hxn
        ln_k<<<4096, 128>>>(x, ln1g + i * 512, ln1b + i * 512, xn, hxn);
        // assemble kv input [b][1152][512]
        kvin_k<<<2304, 256>>>(hcmems_i, hmems_i, hxn, kvin);

        // q = xn @ Wq
        hm_gemm<128,0,1><<<dim3(4,32,1),256,SM128>>>(hxn, WqTh_i, nullptr, qh, 512,
            512,512,512, 0,0,0,0,0,0,1, nullptr);
        // k = kvin @ Wk
        hm_gemm<128,0,1><<<dim3(4,9,8),256,SM128>>>(kvin, WkvTh_i, nullptr, kh, 512,
            512,512,512, 589824,0, 0,0, 589824,0, 1, nullptr);
        // vT = Wv^T @ kvin^T
        hm_gemm<128,0,1><<<dim3(9,4,8),256,SM128>>>(WvTh_i, kvin, nullptr, vTh, 512,
            512,512,1152, 0,0, 589824,0, 589824,0, 1, nullptr);

        // dots = q @ k^T   (z = b*8+h)
        hm_gemm<128,0,0><<<dim3(9,4,64),256,SM128>>>(qh, kh, dots, nullptr, 64,
            512,512,1152, 262144,64, 589824,64, 4718592,589824, 8, nullptr);

        // softmax fp32 -> fp16 probs + sub-block mass
        softmax_k<1152,true><<<32768,256>>>(dots, dotsH_l, 0.125f, Ssub);

        // attno = P @ v
        hm_gemm<64,0,1><<<dim3(1,4,64),256,SM64>>>(dotsH_l, vTh, nullptr, attnoh, 1152,
            1152,1152,512, 4718592,589824, 589824,73728, 262144,64, 8, nullptr);

        // x = attno @ Wo + bo + x
        hm_gemm<128,2,0><<<dim3(4,32,1),256,SM128>>>(attnoh, WoTh_i, x, nullptr, 512,
            512,512,512, 0,0,0,0,0,0,1, bo + i * 512);

        // compressed -> new_cmems (fp32) + fp16 copy
        hm_gemm<128,1,2><<<dim3(4,8,1),256,SM128>>>(hmems_i, cwh_i, cm, cmh, 2048,
            2048,2048,512, 0,0,0,0,0,0,1, convb + i * 512);

        // ck = cm @ Wk ; cvT = Wv^T @ cm^T
        hm_gemm<128,0,1><<<dim3(4,8,1),256,SM128>>>(cmh, WkvTh_i, nullptr, ckh, 512,
            512,512,512, 0,0,0,0,0,0,1, nullptr);
        hm_gemm<128,0,1><<<dim3(1,4,8),256,SM128>>>(WvTh_i, cmh, nullptr, cvTh, 512,
            512,512,128, 0,0, 65536,0, 65536,0, 1, nullptr);

        // o1_raw = P[:,128:640] @ v_mem
        hm_gemm<64,0,0><<<dim3(1,4,64),256,SM64>>>(dotsH_l + 128, vTh + 128, o1, nullptr, 512,
            1152,1152,64, 4718592,589824, 589824,73728, 262144,32768, 8, nullptr);

        // aux-cmem branch
        hm_gemm<128,0,0><<<dim3(1,4,64),256,SM128>>>(qh, ckh, dots2, nullptr, 64,
            512,512,128, 262144,64, 65536,64, 524288,65536, 8, nullptr);
        softmax_k<128,false><<<32768,256>>>(dots2, dots2H, 0.125f, nullptr);
        hm_gemm<64,0,0><<<dim3(1,4,64),256,SM64>>>(dots2H, cvTh, o2, nullptr, 128,
            128,128,64, 524288,65536, 65536,8192, 262144,32768, 8, nullptr);

        mse_k<<<512,256>>>(o1, o2, Ssub, aux, 2097152L);

        // FFN
        ln_k<<<4096,128>>>(x, ln2g + i * 512, ln2b + i * 512, nullptr, hxn2);
        hm_gemm<128,3,1><<<dim3(16,32,1),256,SM128>>>(hxn2, W1Th_i, nullptr, ffhh, 512,
            512,512,2048, 0,0,0,0,0,0,1, b1 + i * 2048);
        hm_gemm<128,2,0><<<dim3(4,32,1),256,SM128>>>(ffhh, W2Th_i, x, nullptr, 2048,
            2048,2048,512, 0,0,0,0,0,0,1, b2 + i * 512);
    }

    attnsum_k<<<1152,256>>>(dotsH, out);
    final_k<<<1,32>>>(out);
}

// round 9
// speedup vs baseline: 5.2119x; 1.1606x over previous
#include <cuda_runtime.h>
#include <cuda_fp16.h>
#include <cstdint>
#include <math.h>

// ---------------------------------------------------------------------------
// CompressiveEncoder forward. FP16 mma.sync GEMMs with ldmatrix + cp.async
// 3-stage pipeline. B=8, T=512, D=512, H=8, MEM=512, CMEM=128, DFF=2048.
// Output: x | new_mems | new_cmems | aux | 0 | attns_mean  (fp32)
// ---------------------------------------------------------------------------

#define OFF_MEMS   2097152L
#define OFF_CMEMS 10485760L
#define OFF_AUX   12582912L
#define OFF_ZERO  12582913L
#define OFF_ATTN  12582914L
#define ATTN_ELEMS 589824L

// -------------------- device scratch ---------------------------------------
__device__ __half g_hmems [8388608];
__device__ __half g_hcmems[2097152];
__device__ __half g_hxn   [2097152];
__device__ __half g_hxn2  [2097152];
__device__ __half g_kvin  [4718592];
__device__ __half g_qh    [2097152];
__device__ __half g_kh    [4718592];
__device__ __half g_vTh   [4718592];
__device__ __half g_dotsH [150994944];
__device__ __half g_dots2H[4194304];
__device__ __half g_attnoh[2097152];
__device__ __half g_ffhh  [8388608];
__device__ __half g_cmh   [524288];
__device__ __half g_ckh   [524288];
__device__ __half g_cvTh  [524288];
__device__ __half g_WqTh  [1048576];
__device__ __half g_WkvTh [2097152];
__device__ __half g_WoTh  [1048576];
__device__ __half g_cwh   [4194304];
__device__ __half g_W1Th  [4194304];
__device__ __half g_W2Th  [4194304];
__device__ float g_dots [37748736];
__device__ float g_dots2[4194304];
__device__ float g_o1   [2097152];
__device__ float g_o2   [2097152];
__device__ float g_S    [32768];

// -------------------- helpers ----------------------------------------------
__device__ __forceinline__ void mma_f16(float* d, uint32_t a0, uint32_t a1,
                                        uint32_t a2, uint32_t a3,
                                        uint32_t b0, uint32_t b1) {
    asm volatile("mma.sync.aligned.m16n8k16.row.col.f32.f16.f16.f32 "
                 "{%0,%1,%2,%3}, {%4,%5,%6,%7}, {%8,%9}, {%0,%1,%2,%3};"
                 : "+f"(d[0]), "+f"(d[1]), "+f"(d[2]), "+f"(d[3])
                 : "r"(a0), "r"(a1), "r"(a2), "r"(a3), "r"(b0), "r"(b1));
}
#define LDSM_X4(r0, r1, r2, r3, addr) \
    asm volatile("ldmatrix.sync.aligned.m8n8.x4.shared.b16 {%0,%1,%2,%3}, [%4];" \
                 : "=r"(r0), "=r"(r1), "=r"(r2), "=r"(r3) : "r"(addr))
#define CP16(saddr, gaddr) \
    asm volatile("cp.async.cg.shared.global [%0], [%1], 16;" :: "r"(saddr), "l"(gaddr))
#define CP_COMMIT() asm volatile("cp.async.commit_group;" ::: "memory")
#define CP_WAIT1()  asm volatile("cp.async.wait_group 1;" ::: "memory")

__device__ __forceinline__ float gelu_f(float v) {
    return 0.5f * v * (1.f + erff(v * 0.70710678118654752f));
}

// -------------------- FP16 GEMM: ldmatrix + cp.async 3-stage ----------------
// C[z] = A[z] @ B[z]^T. A [M,K], B [N,K] row-major __half, fp32 accum.
// CTA tile 128 x BN x 32, 8 warps. Smem rows: 32 halves data @ 80-byte pitch
// (stride 20 words -> 8-row ldmatrix phases conflict-free).
// EPI: 0 none, 1 +bias, 2 +bias+Cf, 3 gelu(.+bias).  OUT: 0 f32, 1 f16, 2 both
template<int BN, int EPI, int OUT>
__global__ void __launch_bounds__(256)
hm_gemm(const __half* __restrict__ A, const __half* __restrict__ B,
        float* __restrict__ Cf, __half* __restrict__ Ch,
        int K, int lda, int ldb, int ldc,
        long sA1, long sA2, long sB1, long sB2, long sC1, long sC2, int zmod,
        const float* __restrict__ bias)
{
    constexpr int BM = 128, NST = 3;
    constexpr int STGB = (BM + BN) * 80;                 // bytes per stage
    constexpr int WN = (BN == 128) ? 4 : 2, WM = 8 / WN;
    constexpr int WTM = BM / WM;                          // 64 or 32
    constexpr int MF = WTM / 16;                          // 4 or 2
    constexpr int NA = 2, NB = (BN == 128) ? 2 : 1;

    extern __shared__ char smc[];
    uint32_t sbase;
    asm("{ .reg .u64 t; cvta.to.shared.u64 t, %1; cvt.u32.u64 %0, t; }"
        : "=r"(sbase) : "l"(smc));

    const int z = blockIdx.z, zh = z / zmod, zl = z - zh * zmod;
    A += zh * sA1 + zl * sA2;
    B += zh * sB1 + zl * sB2;
    const long coff = zh * sC1 + zl * sC2;
    if (OUT != 1) Cf += coff;
    if (OUT >= 1) Ch += coff;
    const int m0 = blockIdx.y * BM, n0 = blockIdx.x * BN;
    const int tid = threadIdx.x, lane = tid & 31, wid = tid >> 5;
    const int wm = wid % WM, wn = wid / WM;
    const int mbase = wm * WTM, nbase = wn * 32;

    float acc[MF][4][4];
#pragma unroll
    for (int i = 0; i < MF; i++)
#pragma unroll
        for (int j = 0; j < 4; j++)
#pragma unroll
            for (int r = 0; r < 4; r++) acc[i][j][r] = 0.f;

    const int KT = K >> 5;

    // per-thread cp.async source/dest precompute
    auto issue = [&](int kt, int st) {
        const int k0 = kt << 5;
        const uint32_t s0 = sbase + st * STGB;
#pragma unroll
        for (int i = 0; i < NA; i++) {
            int idx = tid + i * 256, r = idx >> 2, c = idx & 3;
            CP16(s0 + r * 80 + c * 16, A + (long)(m0 + r) * lda + k0 + c * 8);
        }
#pragma unroll
        for (int i = 0; i < NB; i++) {
            int idx = tid + i * 256, r = idx >> 2, c = idx & 3;
            CP16(s0 + BM * 80 + r * 80 + c * 16, B + (long)(n0 + r) * ldb + k0 + c * 8);
        }
    };

    // ldmatrix address offsets (bytes, stage-relative)
    const int g2 = lane >> 3, t7 = lane & 7;
    const uint32_t khalf = ((g2 >> 1) << 4);              // 0 or 16 bytes
    uint32_t aoff[MF], boff[2];
#pragma unroll
    for (int mf = 0; mf < MF; mf++)
        aoff[mf] = (uint32_t)(mbase + mf * 16 + ((g2 & 1) << 3) + t7) * 80 + khalf;
#pragma unroll
    for (int np = 0; np < 2; np++)
        boff[np] = (uint32_t)BM * 80 +
                   (uint32_t)(nbase + np * 16 + ((g2 & 1) << 3) + t7) * 80 + khalf;

    auto compute = [&](int st) {
        const uint32_t s0 = sbase + st * STGB;
#pragma unroll
        for (int ks = 0; ks < 2; ks++) {
            const uint32_t kb = ks * 32;
            uint32_t a[MF][4], b[2][4];
#pragma unroll
            for (int mf = 0; mf < MF; mf++)
                LDSM_X4(a[mf][0], a[mf][1], a[mf][2], a[mf][3], s0 + aoff[mf] + kb);
#pragma unroll
            for (int np = 0; np < 2; np++)
                LDSM_X4(b[np][0], b[np][1], b[np][2], b[np][3], s0 + boff[np] + kb);
#pragma unroll
            for (int mf = 0; mf < MF; mf++)
#pragma unroll
                for (int np = 0; np < 2; np++) {
                    mma_f16(acc[mf][2 * np],     a[mf][0], a[mf][1], a[mf][2], a[mf][3],
                            b[np][0], b[np][2]);
                    mma_f16(acc[mf][2 * np + 1], a[mf][0], a[mf][1], a[mf][2], a[mf][3],
                            b[np][1], b[np][3]);
                }
        }
    };

    int ldi = 0;
#pragma unroll
    for (int s = 0; s < NST - 1; s++) {
        if (ldi < KT) issue(ldi, s);
        CP_COMMIT();
        ldi++;
    }
    for (int kt = 0; kt < KT; kt++) {
        CP_WAIT1();
        __syncthreads();
        compute(kt % NST);
        if (ldi < KT) issue(ldi, ldi % NST);
        CP_COMMIT();
        ldi++;
    }

    // ---- epilogue ----
    const int rbase = m0 + mbase + (lane >> 2);
    const int cbase = n0 + nbase + 2 * (lane & 3);
#pragma unroll
    for (int mf = 0; mf < MF; mf++) {
#pragma unroll
        for (int nf = 0; nf < 4; nf++) {
#pragma unroll
            for (int half = 0; half < 2; half++) {
                const int m = rbase + mf * 16 + half * 8;
                const int n = cbase + nf * 8;
                float2 v = make_float2(acc[mf][nf][half * 2], acc[mf][nf][half * 2 + 1]);
                const long idx = (long)m * ldc + n;
                if (EPI >= 1) { v.x += bias[n]; v.y += bias[n + 1]; }
                if (EPI == 2) { float2 c0 = *(const float2*)(Cf + idx); v.x += c0.x; v.y += c0.y; }
                if (EPI == 3) { v.x = gelu_f(v.x); v.y = gelu_f(v.y); }
                if (OUT != 1) *(float2*)(Cf + idx) = v;
                if (OUT >= 1) *(__half2*)(Ch + idx) = __floats2half2_rn(v.x, v.y);
            }
        }
    }
}

// -------------------- weight transpose fp32 -> fp16 -------------------------
__global__ void tr_k(const float* __restrict__ in, __half* __restrict__ out,
                     int ldi, int ldo, long sI, long sO)
{
    __shared__ float t[32][33];
    in += blockIdx.z * sI; out += blockIdx.z * sO;
    const int n0 = blockIdx.x * 32, k0 = blockIdx.y * 32;
    const int tx = threadIdx.x, ty = threadIdx.y;
#pragma unroll
    for (int j = 0; j < 32; j += 8) t[ty + j][tx] = in[(long)(k0 + ty + j) * ldi + n0 + tx];
    __syncthreads();
#pragma unroll
    for (int j = 0; j < 32; j += 8)
        out[(long)(n0 + ty + j) * ldo + k0 + tx] = __float2half(t[tx][ty + j]);
}

__global__ void convt2_k(const float* __restrict__ w, __half* __restrict__ wt)
{
    long i = (long)blockIdx.x * 256 + threadIdx.x;
    if (i >= 4L * 1048576L) return;
    long l = i >> 20, r0 = i & 1048575L;
    int o = (int)(r0 >> 11), k = (int)(r0 & 2047);
    int r = k >> 9, c = k & 511;
    wt[i] = __float2half(w[l * 1048576L + ((long)o * 512 + c) * 4 + r]);
}

__global__ void cvt16_k(const float* __restrict__ in, __half* __restrict__ out, long n4)
{
    long i = (long)blockIdx.x * 256 + threadIdx.x;
    if (i >= n4) return;
    float4 v = ((const float4*)in)[i];
    ((__half2*)out)[2 * i]     = __floats2half2_rn(v.x, v.y);
    ((__half2*)out)[2 * i + 1] = __floats2half2_rn(v.z, v.w);
}

__global__ void kvin_k(const __half* __restrict__ hc, const __half* __restrict__ hm,
                       const __half* __restrict__ hx, __half* __restrict__ kvin)
{
    long u = (long)blockIdx.x * 256 + threadIdx.x;
    if (u >= 589824L) return;
    int c8 = (int)(u & 63);
    long bj = u >> 6;
    int j = (int)(bj % 1152);
    int b = (int)(bj / 1152);
    const uint4* src;
    if (j < 128)      src = (const uint4*)hc + ((long)b * 128 + j) * 64 + c8;
    else if (j < 640) src = (const uint4*)hm + ((long)b * 512 + (j - 128)) * 64 + c8;
    else              src = (const uint4*)hx + ((long)b * 512 + (j - 640)) * 64 + c8;
    ((uint4*)kvin)[u] = *src;
}

// -------------------- layernorm --------------------------------------------
__global__ void ln_k(const float* __restrict__ x, const float* __restrict__ g,
                     const float* __restrict__ b, float* __restrict__ out,
                     __half* __restrict__ outh)
{
    const long row = blockIdx.x;
    const float* xr = x + row * 512;
    const int tid = threadIdx.x;
    float v[4]; float s = 0.f;
#pragma unroll
    for (int j = 0; j < 4; j++) { v[j] = xr[tid + j * 128]; s += v[j]; }
    __shared__ float sh[4];
#pragma unroll
    for (int o = 16; o; o >>= 1) s += __shfl_xor_sync(0xffffffffu, s, o);
    if ((tid & 31) == 0) sh[tid >> 5] = s;
    __syncthreads();
    const float mu = (sh[0] + sh[1] + sh[2] + sh[3]) * (1.f / 512.f);
    float s2 = 0.f;
#pragma unroll
    for (int j = 0; j < 4; j++) { float d = v[j] - mu; s2 += d * d; }
    __syncthreads();
#pragma unroll
    for (int o = 16; o; o >>= 1) s2 += __shfl_xor_sync(0xffffffffu, s2, o);
    if ((tid & 31) == 0) sh[tid >> 5] = s2;
    __syncthreads();
    const float rs = rsqrtf((sh[0] + sh[1] + sh[2] + sh[3]) * (1.f / 512.f) + 1e-5f);
#pragma unroll
    for (int j = 0; j < 4; j++) {
        int d = tid + j * 128;
        float val = (v[j] - mu) * rs * g[d] + b[d];
        if (out)  out[row * 512 + d] = val;
        outh[row * 512 + d] = __float2half(val);
    }
}

// -------------------- softmax fp32 -> fp16; optional sub-mass [128,640) ----
template<int L, bool SUB>
__global__ void softmax_k(const float* __restrict__ In, __half* __restrict__ Out,
                          float scale, float* __restrict__ subsum)
{
    const long row = blockIdx.x;
    const float* ir = In + row * (long)L;
    __half* orow = Out + row * (long)L;
    const int tid = threadIdx.x;
    constexpr int NIT = (L + 255) >> 8;
    float v[NIT]; float mx = -3.0e38f;
#pragma unroll
    for (int j = 0; j < NIT; j++) {
        int i = tid + (j << 8);
        float t = (i < L) ? ir[i] * scale : -3.0e38f;
        v[j] = t; mx = fmaxf(mx, t);
    }
    __shared__ float sh[8];
#pragma unroll
    for (int o = 16; o; o >>= 1) mx = fmaxf(mx, __shfl_xor_sync(0xffffffffu, mx, o));
    if ((tid & 31) == 0) sh[tid >> 5] = mx;
    __syncthreads();
    float bm = sh[0];
#pragma unroll
    for (int w = 1; w < 8; w++) bm = fmaxf(bm, sh[w]);
    float s = 0.f, ssub = 0.f;
#pragma unroll
    for (int j = 0; j < NIT; j++) {
        int i = tid + (j << 8);
        if (i < L) {
            float e = __expf(v[j] - bm); v[j] = e; s += e;
            if (SUB && i >= 128 && i < 640) ssub += e;
        }
    }
    __syncthreads();
#pragma unroll
    for (int o = 16; o; o >>= 1) s += __shfl_xor_sync(0xffffffffu, s, o);
    if ((tid & 31) == 0) sh[tid >> 5] = s;
    __syncthreads();
    float tot = 0.f;
#pragma unroll
    for (int w = 0; w < 8; w++) tot += sh[w];
    const float inv = 1.f / tot;
    if (SUB) {
        __syncthreads();
#pragma unroll
        for (int o = 16; o; o >>= 1) ssub += __shfl_xor_sync(0xffffffffu, ssub, o);
        if ((tid & 31) == 0) sh[tid >> 5] = ssub;
        __syncthreads();
        if (tid == 0) {
            float st = 0.f;
#pragma unroll
            for (int w = 0; w < 8; w++) st += sh[w];
            subsum[row] = st * inv;
        }
    }
#pragma unroll
    for (int j = 0; j < NIT; j++) {
        int i = tid + (j << 8);
        if (i < L) orow[i] = __float2half(v[j] * inv);
    }
}

// -------------------- embed / mse / attnsum / init / final ------------------
__global__ void embed_k(const int* __restrict__ seq, const float* __restrict__ emb,
                        float* __restrict__ x)
{
    long i = (long)blockIdx.x * blockDim.x + threadIdx.x;
    if (i >= 2097152L) return;
    int d = (int)(i & 511);
    long bt = i >> 9;
    int t = (int)(bt & 511);
    int tok = seq[bt];
    int j2 = d & ~1;
    float ang = (float)t * expf(-0.017988946039015984f * (float)j2);
    float pe = (d & 1) ? cosf(ang) : sinf(ang);
    x[i] = emb[(long)tok * 512 + d] + pe;
}

__global__ void mse_k(const float* __restrict__ a, const float* __restrict__ b,
                      const float* __restrict__ S, float* __restrict__ outScalar, long n)
{
    long i0 = (long)blockIdx.x * blockDim.x + threadIdx.x;
    long stride = (long)gridDim.x * blockDim.x;
    float s = 0.f;
    for (long i = i0; i < n; i += stride) {
        float d = a[i] / S[i >> 6] - b[i];
        s += d * d;
    }
    __shared__ float sh[8];
#pragma unroll
    for (int o = 16; o; o >>= 1) s += __shfl_xor_sync(0xffffffffu, s, o);
    int tid = threadIdx.x;
    if ((tid & 31) == 0) sh[tid >> 5] = s;
    __syncthreads();
    if (tid == 0) {
        float tot = 0.f;
#pragma unroll
        for (int w = 0; w < 8; w++) tot += sh[w];
        atomicAdd(outScalar, tot);
    }
}

__global__ void attnsum_k(const __half* __restrict__ dotsH, float* __restrict__ out)
{
    long i = (long)blockIdx.x * 256 + threadIdx.x;
    if (i >= 294912L) return;
    const __half2* p = (const __half2*)dotsH + i;
    float sx = 0.f, sy = 0.f;
#pragma unroll 8
    for (int sl = 0; sl < 256; sl++) {
        float2 f = __half22float2(p[(long)sl * 294912L]);
        sx += f.x; sy += f.y;
    }
    *(float2*)(out + OFF_ATTN + 2 * i) = make_float2(sx * (1.f / 256.f), sy * (1.f / 256.f));
}

__global__ void init_k(float* __restrict__ out)
{
    if (threadIdx.x == 0) { out[OFF_AUX] = 0.f; out[OFF_ZERO] = 0.f; }
}
__global__ void final_k(float* __restrict__ out)
{
    if (threadIdx.x == 0) out[OFF_AUX] *= (1.f / (4.f * 2097152.f));
}

// ---------------------------------------------------------------------------
extern "C" void kernel_launch(void* const* d_in, const int* in_sizes, int n_in,
                              void* d_out, int out_size)
{
    const int*   seq   = (const int*)  d_in[0];
    const float* mems  = (const float*)d_in[2];
    const float* cmems = (const float*)d_in[3];
    const float* emb   = (const float*)d_in[4];
    const float* ln1g  = (const float*)d_in[5];
    const float* ln1b  = (const float*)d_in[6];
    const float* Wq    = (const float*)d_in[7];
    const float* Wkv   = (const float*)d_in[8];
    const float* Wo    = (const float*)d_in[9];
    const float* bo    = (const float*)d_in[10];
    const float* convw = (const float*)d_in[11];
    const float* convb = (const float*)d_in[12];
    const float* ln2g  = (const float*)d_in[13];
    const float* ln2b  = (const float*)d_in[14];
    const float* W1    = (const float*)d_in[15];
    const float* b1    = (const float*)d_in[16];
    const float* W2    = (const float*)d_in[17];
    const float* b2    = (const float*)d_in[18];
    float* out = (float*)d_out;

    __half *hmems, *hcmems, *hxn, *hxn2, *kvin, *qh, *kh, *vTh, *dotsH, *dots2H;
    __half *attnoh, *ffhh, *cmh, *ckh, *cvTh;
    __half *WqTh, *WkvTh, *WoTh, *cwh, *W1Th, *W2Th;
    float *dots, *dots2, *o1, *o2, *Ssub;
    cudaGetSymbolAddress((void**)&hmems, g_hmems);   cudaGetSymbolAddress((void**)&hcmems, g_hcmems);
    cudaGetSymbolAddress((void**)&hxn, g_hxn);       cudaGetSymbolAddress((void**)&hxn2, g_hxn2);
    cudaGetSymbolAddress((void**)&kvin, g_kvin);     cudaGetSymbolAddress((void**)&qh, g_qh);
    cudaGetSymbolAddress((void**)&kh, g_kh);         cudaGetSymbolAddress((void**)&vTh, g_vTh);
    cudaGetSymbolAddress((void**)&dotsH, g_dotsH);   cudaGetSymbolAddress((void**)&dots2H, g_dots2H);
    cudaGetSymbolAddress((void**)&attnoh, g_attnoh); cudaGetSymbolAddress((void**)&ffhh, g_ffhh);
    cudaGetSymbolAddress((void**)&cmh, g_cmh);       cudaGetSymbolAddress((void**)&ckh, g_ckh);
    cudaGetSymbolAddress((void**)&cvTh, g_cvTh);
    cudaGetSymbolAddress((void**)&WqTh, g_WqTh);     cudaGetSymbolAddress((void**)&WkvTh, g_WkvTh);
    cudaGetSymbolAddress((void**)&WoTh, g_WoTh);     cudaGetSymbolAddress((void**)&cwh, g_cwh);
    cudaGetSymbolAddress((void**)&W1Th, g_W1Th);     cudaGetSymbolAddress((void**)&W2Th, g_W2Th);
    cudaGetSymbolAddress((void**)&dots, g_dots);     cudaGetSymbolAddress((void**)&dots2, g_dots2);
    cudaGetSymbolAddress((void**)&o1, g_o1);         cudaGetSymbolAddress((void**)&o2, g_o2);
    cudaGetSymbolAddress((void**)&Ssub, g_S);

    const int SM128 = 3 * (128 + 128) * 80;   // 61440
    const int SM64  = 3 * (128 + 64) * 80;    // 46080
    cudaFuncSetAttribute(hm_gemm<128,0,0>, cudaFuncAttributeMaxDynamicSharedMemorySize, SM128);
    cudaFuncSetAttribute(hm_gemm<128,0,1>, cudaFuncAttributeMaxDynamicSharedMemorySize, SM128);
    cudaFuncSetAttribute(hm_gemm<128,1,2>, cudaFuncAttributeMaxDynamicSharedMemorySize, SM128);
    cudaFuncSetAttribute(hm_gemm<128,2,0>, cudaFuncAttributeMaxDynamicSharedMemorySize, SM128);
    cudaFuncSetAttribute(hm_gemm<128,3,1>, cudaFuncAttributeMaxDynamicSharedMemorySize, SM128);
    cudaFuncSetAttribute(hm_gemm<64,0,0>,  cudaFuncAttributeMaxDynamicSharedMemorySize, SM64);
    cudaFuncSetAttribute(hm_gemm<64,0,1>,  cudaFuncAttributeMaxDynamicSharedMemorySize, SM64);

    float* x   = out;
    float* aux = out + OFF_AUX;

    init_k <<<1, 32>>>(out);
    embed_k<<<8192, 256>>>(seq, emb, x);

    dim3 tb(32, 8);
    tr_k<<<dim3(16,16,4), tb>>>(Wq,  WqTh,  512,  512,  262144, 262144);
    tr_k<<<dim3(32,16,4), tb>>>(Wkv, WkvTh, 1024, 512,  524288, 524288);
    tr_k<<<dim3(16,16,4), tb>>>(Wo,  WoTh,  512,  512,  262144, 262144);
    tr_k<<<dim3(64,16,4), tb>>>(W1,  W1Th,  2048, 512,  1048576, 1048576);
    tr_k<<<dim3(16,64,4), tb>>>(W2,  W2Th,  512,  2048, 1048576, 1048576);
    convt2_k<<<16384, 256>>>(convw, cwh);
    cvt16_k<<<8192, 256>>>(mems,  hmems,  2097152L);
    cvt16_k<<<2048, 256>>>(cmems, hcmems, 524288L);

    for (int i = 0; i < 4; i++) {
        const __half* WqTh_i  = WqTh  + (long)i * 262144;
        const __half* WkvTh_i = WkvTh + (long)i * 524288;
        const __half* WvTh_i  = WkvTh_i + 262144;
        const __half* WoTh_i  = WoTh  + (long)i * 262144;
        const __half* cwh_i   = cwh   + (long)i * 1048576;
        const __half* W1Th_i  = W1Th  + (long)i * 1048576;
        const __half* W2Th_i  = W2Th  + (long)i * 1048576;
        const __half* hmems_i  = hmems  + (long)i * 2097152;
        const __half* hcmems_i = hcmems + (long)i * 524288;
        float* xn = out + OFF_MEMS  + (long)i * 2097152;
        float* cm = out + OFF_CMEMS + (long)i * 524288;
        __half* dotsH_l = dotsH + (long)i * 37748736;

        ln_k<<<4096, 128>>>(x, ln1g + i * 512, ln1b + i * 512, xn, hxn);
        kvin_k<<<2304, 256>>>(hcmems_i, hmems_i, hxn, kvin);

        hm_gemm<128,0,1><<<dim3(4,32,1),256,SM128>>>(hxn, WqTh_i, nullptr, qh, 512,
            512,512,512, 0,0,0,0,0,0,1, nullptr);
        hm_gemm<128,0,1><<<dim3(4,9,8),256,SM128>>>(kvin, WkvTh_i, nullptr, kh, 512,
            512,512,512, 589824,0, 0,0, 589824,0, 1, nullptr);
        hm_gemm<128,0,1><<<dim3(9,4,8),256,SM128>>>(WvTh_i, kvin, nullptr, vTh, 512,
            512,512,1152, 0,0, 589824,0, 589824,0, 1, nullptr);

        hm_gemm<128,0,0><<<dim3(9,4,64),256,SM128>>>(qh, kh, dots, nullptr, 64,
            512,512,1152, 262144,64, 589824,64, 4718592,589824, 8, nullptr);

        softmax_k<1152,true><<<32768,256>>>(dots, dotsH_l, 0.125f, Ssub);

        hm_gemm<64,0,1><<<dim3(1,4,64),256,SM64>>>(dotsH_l, vTh, nullptr, attnoh, 1152,
            1152,1152,512, 4718592,589824, 589824,73728, 262144,64, 8, nullptr);

        hm_gemm<128,2,0><<<dim3(4,32,1),256,SM128>>>(attnoh, WoTh_i, x, nullptr, 512,
            512,512,512, 0,0,0,0,0,0,1, bo + i * 512);

        hm_gemm<128,1,2><<<dim3(4,8,1),256,SM128>>>(hmems_i, cwh_i, cm, cmh, 2048,
            2048,2048,512, 0,0,0,0,0,0,1, convb + i * 512);

        hm_gemm<128,0,1><<<dim3(4,8,1),256,SM128>>>(cmh, WkvTh_i, nullptr, ckh, 512,
            512,512,512, 0,0,0,0,0,0,1, nullptr);
        hm_gemm<128,0,1><<<dim3(1,4,8),256,SM128>>>(WvTh_i, cmh, nullptr, cvTh, 512,
            512,512,128, 0,0, 65536,0, 65536,0, 1, nullptr);

        hm_gemm<64,0,0><<<dim3(1,4,64),256,SM64>>>(dotsH_l + 128, vTh + 128, o1, nullptr, 512,
            1152,1152,64, 4718592,589824, 589824,73728, 262144,32768, 8, nullptr);

        hm_gemm<128,0,0><<<dim3(1,4,64),256,SM128>>>(qh, ckh, dots2, nullptr, 64,
            512,512,128, 262144,64, 65536,64, 524288,65536, 8, nullptr);
        softmax_k<128,false><<<32768,256>>>(dots2, dots2H, 0.125f, nullptr);
        hm_gemm<64,0,0><<<dim3(1,4,64),256,SM64>>>(dots2H, cvTh, o2, nullptr, 128,
            128,128,64, 524288,65536, 65536,8192, 262144,32768, 8, nullptr);

        mse_k<<<512,256>>>(o1, o2, Ssub, aux, 2097152L);

        ln_k<<<4096,128>>>(x, ln2g + i * 512, ln2b + i * 512, nullptr, hxn2);
        hm_gemm<128,3,1><<<dim3(16,32,1),256,SM128>>>(hxn2, W1Th_i, nullptr, ffhh, 512,
            512,512,2048, 0,0,0,0,0,0,1, b1 + i * 2048);
        hm_gemm<128,2,0><<<dim3(4,32,1),256,SM128>>>(ffhh, W2Th_i, x, nullptr, 2048,
            2048,2048,512, 0,0,0,0,0,0,1, b2 + i * 512);
    }

    attnsum_k<<<1152,256>>>(dotsH, out);
    final_k<<<1,32>>>(out);
}

// round 11
// speedup vs baseline: 6.0942x; 1.1693x over previous
#include <cuda_runtime.h>
#include <cuda_fp16.h>
#include <cstdint>
#include <math.h>

// ---------------------------------------------------------------------------
// CompressiveEncoder forward. FP16 mma.sync + ldmatrix(.trans) + cp.async.
// B=8, T=512, D=512, H=8, MEM=512, CMEM=128, DFF=2048.
// Output: x | new_mems | new_cmems | aux | 0 | attns_mean  (fp32)
// ---------------------------------------------------------------------------

#define OFF_MEMS   2097152L
#define OFF_CMEMS 10485760L
#define OFF_AUX   12582912L
#define OFF_ZERO  12582913L
#define OFF_ATTN  12582914L
#define ATTN_ELEMS 589824L

// -------------------- device scratch ---------------------------------------
__device__ __half g_hmems [8388608];     // [l][b][512][512]
__device__ __half g_hcmems[2097152];     // [l][b][128][512]
__device__ __half g_hxn   [2097152];
__device__ __half g_hxn2  [2097152];
__device__ __half g_qh    [2097152];     // [b][512][512]
__device__ __half g_kvh   [37748736];    // [l][b][1152][1024]  k|v per row
__device__ __half g_ckvh  [4194304];     // [l][b][128][1024]   ck|cv
__device__ __half g_dotsH [150994944];   // [l][64][512][1152]  logits->probs
__device__ __half g_dots2H[4194304];     // [64][512][128]
__device__ __half g_attnoh[2097152];
__device__ __half g_ffhh  [8388608];
__device__ __half g_cmh   [2097152];     // [l][b][128][512]
__device__ __half g_WqTh  [1048576];
__device__ __half g_WkvTh [2097152];
__device__ __half g_WoTh  [1048576];
__device__ __half g_cwh   [4194304];
__device__ __half g_W1Th  [4194304];
__device__ __half g_W2Th  [4194304];
__device__ float g_o1 [2097152];
__device__ float g_o2 [2097152];
__device__ float g_S  [32768];

// -------------------- helpers ----------------------------------------------
__device__ __forceinline__ void mma_f16(float* d, uint32_t a0, uint32_t a1,
                                        uint32_t a2, uint32_t a3,
                                        uint32_t b0, uint32_t b1) {
    asm volatile("mma.sync.aligned.m16n8k16.row.col.f32.f16.f16.f32 "
                 "{%0,%1,%2,%3}, {%4,%5,%6,%7}, {%8,%9}, {%0,%1,%2,%3};"
                 : "+f"(d[0]), "+f"(d[1]), "+f"(d[2]), "+f"(d[3])
                 : "r"(a0), "r"(a1), "r"(a2), "r"(a3), "r"(b0), "r"(b1));
}
#define LDSM_X4(r0, r1, r2, r3, addr) \
    asm volatile("ldmatrix.sync.aligned.m8n8.x4.shared.b16 {%0,%1,%2,%3}, [%4];" \
                 : "=r"(r0), "=r"(r1), "=r"(r2), "=r"(r3) : "r"(addr))
#define LDSM_X4_T(r0, r1, r2, r3, addr) \
    asm volatile("ldmatrix.sync.aligned.m8n8.x4.trans.shared.b16 {%0,%1,%2,%3}, [%4];" \
                 : "=r"(r0), "=r"(r1), "=r"(r2), "=r"(r3) : "r"(addr))
#define CP16(saddr, gaddr) \
    asm volatile("cp.async.cg.shared.global [%0], [%1], 16;" :: "r"(saddr), "l"(gaddr))
#define CP_COMMIT() asm volatile("cp.async.commit_group;" ::: "memory")
#define CP_WAIT1()  asm volatile("cp.async.wait_group 1;" ::: "memory")

__device__ __forceinline__ float gelu_f(float v) {
    return 0.5f * v * (1.f + erff(v * 0.70710678118654752f));
}

// -------------------- FP16 GEMM --------------------------------------------
// TRB=false: C[z] = A[z] @ B[z]^T, B stored [N,K] row-major.
// TRB=true : C[z] = A[z] @ B[z],   B stored [K,N] row-major (ldmatrix.trans).
// CTA tile 128 x BN x 32, 8 warps, 3-stage cp.async pipeline.
// EPI: 0 none, 1 +bias, 2 +bias+Cf, 3 gelu(.+bias).  OUT: 0 f32, 1 f16, 2 both
template<int BN, int EPI, int OUT, bool TRB>
__global__ void __launch_bounds__(256)
hm_gemm(const __half* __restrict__ A, const __half* __restrict__ B,
        float* __restrict__ Cf, __half* __restrict__ Ch,
        int K, int lda, int ldb, int ldc,
        long sA1, long sA2, long sB1, long sB2, long sC1, long sC2, int zmod,
        const float* __restrict__ bias, long sBias)
{
    constexpr int BM = 128, NST = 3;
    constexpr int BNB = BN * 2 + 16;                      // TRB B row pitch
    constexpr int ABY = BM * 80;
    constexpr int STGB = TRB ? (ABY + 32 * BNB) : ((BM + BN) * 80);
    constexpr int WN = (BN == 128) ? 4 : 2, WM = 8 / WN;
    constexpr int WTM = BM / WM;
    constexpr int MF = WTM / 16;
    constexpr int NBn = (BN == 128) ? 2 : 1;              // non-TRB B uint4/thread
    constexpr int NBt = (32 * (BN / 8)) / 256;            // TRB: chunks/thread

    extern __shared__ char smc[];
    uint32_t sbase;
    asm("{ .reg .u64 t; cvta.to.shared.u64 t, %1; cvt.u32.u64 %0, t; }"
        : "=r"(sbase) : "l"(smc));

    const int z = blockIdx.z, zh = z / zmod, zl = z - zh * zmod;
    A += zh * sA1 + zl * sA2;
    B += zh * sB1 + zl * sB2;
    const long coff = zh * sC1 + zl * sC2;
    if (OUT != 1) Cf += coff;
    if (OUT >= 1) Ch += coff;
    if (EPI >= 1) bias += zh * sBias;
    const int m0 = blockIdx.y * BM, n0 = blockIdx.x * BN;
    const int tid = threadIdx.x, lane = tid & 31, wid = tid >> 5;
    const int wm = wid % WM, wn = wid / WM;
    const int mbase = wm * WTM, nbase = wn * 32;

    float acc[MF][4][4];
#pragma unroll
    for (int i = 0; i < MF; i++)
#pragma unroll
        for (int j = 0; j < 4; j++)
#pragma unroll
            for (int r = 0; r < 4; r++) acc[i][j][r] = 0.f;

    const int KT = K >> 5;

    auto issue = [&](int kt, int st) {
        const int k0 = kt << 5;
        const uint32_t s0 = sbase + st * STGB;
#pragma unroll
        for (int i = 0; i < 2; i++) {                      // A: 128 rows x 64B
            int idx = tid + i * 256, r = idx >> 2, c = idx & 3;
            CP16(s0 + r * 80 + c * 16, A + (long)(m0 + r) * lda + k0 + c * 8);
        }
        if (!TRB) {
#pragma unroll
            for (int i = 0; i < NBn; i++) {
                int idx = tid + i * 256, r = idx >> 2, c = idx & 3;
                CP16(s0 + ABY + r * 80 + c * 16,
                     B + (long)(n0 + r) * ldb + k0 + c * 8);
            }
        } else {
            constexpr int CH = BN / 8;                     // 16B chunks per row
#pragma unroll
            for (int i = 0; i < NBt; i++) {
                int idx = tid + i * 256, r = idx / CH, c = idx % CH;
                CP16(s0 + ABY + r * BNB + c * 16,
                     B + (long)(k0 + r) * ldb + n0 + c * 8);
            }
        }
    };

    const int g2 = lane >> 3, t7 = lane & 7;
    const uint32_t khalf = ((g2 >> 1) << 4);
    uint32_t aoff[MF], boff[2];
#pragma unroll
    for (int mf = 0; mf < MF; mf++)
        aoff[mf] = (uint32_t)(mbase + mf * 16 + ((g2 & 1) << 3) + t7) * 80 + khalf;
    if (!TRB) {
#pragma unroll
        for (int np = 0; np < 2; np++)
            boff[np] = (uint32_t)ABY +
                       (uint32_t)(nbase + np * 16 + ((g2 & 1) << 3) + t7) * 80 + khalf;
    } else {
#pragma unroll
        for (int np = 0; np < 2; np++)
            boff[np] = (uint32_t)ABY +
                       (uint32_t)(((g2 >> 1) << 3) + t7) * BNB +
                       (uint32_t)(nbase + np * 16 + ((g2 & 1) << 3)) * 2;
    }

    auto compute = [&](int st) {
        const uint32_t s0 = sbase + st * STGB;
#pragma unroll
        for (int ks = 0; ks < 2; ks++) {
            uint32_t a[MF][4], b[2][4];
#pragma unroll
            for (int mf = 0; mf < MF; mf++)
                LDSM_X4(a[mf][0], a[mf][1], a[mf][2], a[mf][3],
                        s0 + aoff[mf] + ks * 32);
#pragma unroll
            for (int np = 0; np < 2; np++) {
                if (!TRB) {
                    LDSM_X4(b[np][0], b[np][1], b[np][2], b[np][3],
                            s0 + boff[np] + ks * 32);
                } else {
                    LDSM_X4_T(b[np][0], b[np][1], b[np][2], b[np][3],
                              s0 + boff[np] + ks * 16 * BNB);
                }
            }
#pragma unroll
            for (int mf = 0; mf < MF; mf++)
#pragma unroll
                for (int np = 0; np < 2; np++) {
                    mma_f16(acc[mf][2 * np],     a[mf][0], a[mf][1], a[mf][2], a[mf][3],
                            b[np][0], b[np][2]);
                    mma_f16(acc[mf][2 * np + 1], a[mf][0], a[mf][1], a[mf][2], a[mf][3],
                            b[np][1], b[np][3]);
                }
        }
    };

    int ldi = 0;
#pragma unroll
    for (int s = 0; s < NST - 1; s++) {
        if (ldi < KT) issue(ldi, s);
        CP_COMMIT();
        ldi++;
    }
    for (int kt = 0; kt < KT; kt++) {
        CP_WAIT1();
        __syncthreads();
        compute(kt % NST);
        if (ldi < KT) issue(ldi, ldi % NST);
        CP_COMMIT();
        ldi++;
    }

    // ---- epilogue ----
    const int rbase = m0 + mbase + (lane >> 2);
    const int cbase = n0 + nbase + 2 * (lane & 3);
#pragma unroll
    for (int mf = 0; mf < MF; mf++) {
#pragma unroll
        for (int nf = 0; nf < 4; nf++) {
#pragma unroll
            for (int half = 0; half < 2; half++) {
                const int m = rbase + mf * 16 + half * 8;
                const int n = cbase + nf * 8;
                float2 v = make_float2(acc[mf][nf][half * 2], acc[mf][nf][half * 2 + 1]);
                const long idx = (long)m * ldc + n;
                if (EPI >= 1) { v.x += bias[n]; v.y += bias[n + 1]; }
                if (EPI == 2) { float2 c0 = *(const float2*)(Cf + idx); v.x += c0.x; v.y += c0.y; }
                if (EPI == 3) { v.x = gelu_f(v.x); v.y = gelu_f(v.y); }
                if (OUT != 1) *(float2*)(Cf + idx) = v;
                if (OUT >= 1) *(__half2*)(Ch + idx) = __floats2half2_rn(v.x, v.y);
            }
        }
    }
}

// -------------------- weight transpose fp32 -> fp16 -------------------------
__global__ void tr_k(const float* __restrict__ in, __half* __restrict__ out,
                     int ldi, int ldo, long sI, long sO)
{
    __shared__ float t[32][33];
    in += blockIdx.z * sI; out += blockIdx.z * sO;
    const int n0 = blockIdx.x * 32, k0 = blockIdx.y * 32;
    const int tx = threadIdx.x, ty = threadIdx.y;
#pragma unroll
    for (int j = 0; j < 32; j += 8) t[ty + j][tx] = in[(long)(k0 + ty + j) * ldi + n0 + tx];
    __syncthreads();
#pragma unroll
    for (int j = 0; j < 32; j += 8)
        out[(long)(n0 + ty + j) * ldo + k0 + tx] = __float2half(t[tx][ty + j]);
}

__global__ void convt2_k(const float* __restrict__ w, __half* __restrict__ wt)
{
    long i = (long)blockIdx.x * 256 + threadIdx.x;
    if (i >= 4L * 1048576L) return;
    long l = i >> 20, r0 = i & 1048575L;
    int o = (int)(r0 >> 11), k = (int)(r0 & 2047);
    int r = k >> 9, c = k & 511;
    wt[i] = __float2half(w[l * 1048576L + ((long)o * 512 + c) * 4 + r]);
}

__global__ void cvt16_k(const float* __restrict__ in, __half* __restrict__ out, long n4)
{
    long i = (long)blockIdx.x * 256 + threadIdx.x;
    if (i >= n4) return;
    float4 v = ((const float4*)in)[i];
    ((__half2*)out)[2 * i]     = __floats2half2_rn(v.x, v.y);
    ((__half2*)out)[2 * i + 1] = __floats2half2_rn(v.z, v.w);
}

// -------------------- layernorm --------------------------------------------
__global__ void ln_k(const float* __restrict__ x, const float* __restrict__ g,
                     const float* __restrict__ b, float* __restrict__ out,
                     __half* __restrict__ outh)
{
    const long row = blockIdx.x;
    const float* xr = x + row * 512;
    const int tid = threadIdx.x;
    float v[4]; float s = 0.f;
#pragma unroll
    for (int j = 0; j < 4; j++) { v[j] = xr[tid + j * 128]; s += v[j]; }
    __shared__ float sh[4];
#pragma unroll
    for (int o = 16; o; o >>= 1) s += __shfl_xor_sync(0xffffffffu, s, o);
    if ((tid & 31) == 0) sh[tid >> 5] = s;
    __syncthreads();
    const float mu = (sh[0] + sh[1] + sh[2] + sh[3]) * (1.f / 512.f);
    float s2 = 0.f;
#pragma unroll
    for (int j = 0; j < 4; j++) { float d = v[j] - mu; s2 += d * d; }
    __syncthreads();
#pragma unroll
    for (int o = 16; o; o >>= 1) s2 += __shfl_xor_sync(0xffffffffu, s2, o);
    if ((tid & 31) == 0) sh[tid >> 5] = s2;
    __syncthreads();
    const float rs = rsqrtf((sh[0] + sh[1] + sh[2] + sh[3]) * (1.f / 512.f) + 1e-5f);
#pragma unroll
    for (int j = 0; j < 4; j++) {
        int d = tid + j * 128;
        float val = (v[j] - mu) * rs * g[d] + b[d];
        if (out)  out[row * 512 + d] = val;
        outh[row * 512 + d] = __float2half(val);
    }
}

// -------------------- softmax: fp16 logits -> fp16 probs, in place ----------
template<int L, bool SUB>
__global__ void softmax_k(__half* __restrict__ P, float scale,
                          float* __restrict__ subsum)
{
    const long row = blockIdx.x;
    __half* pr = P + row * (long)L;
    const int tid = threadIdx.x;
    constexpr int NIT = (L + 255) >> 8;
    float v[NIT]; float mx = -3.0e38f;
#pragma unroll
    for (int j = 0; j < NIT; j++) {
        int i = tid + (j << 8);
        float t = (i < L) ? __half2float(pr[i]) * scale : -3.0e38f;
        v[j] = t; mx = fmaxf(mx, t);
    }
    __shared__ float sh[8];
#pragma unroll
    for (int o = 16; o; o >>= 1) mx = fmaxf(mx, __shfl_xor_sync(0xffffffffu, mx, o));
    if ((tid & 31) == 0) sh[tid >> 5] = mx;
    __syncthreads();
    float bm = sh[0];
#pragma unroll
    for (int w = 1; w < 8; w++) bm = fmaxf(bm, sh[w]);
    float s = 0.f, ssub = 0.f;
#pragma unroll
    for (int j = 0; j < NIT; j++) {
        int i = tid + (j << 8);
        if (i < L) {
            float e = __expf(v[j] - bm); v[j] = e; s += e;
            if (SUB && i >= 128 && i < 640) ssub += e;
        }
    }
    __syncthreads();
#pragma unroll
    for (int o = 16; o; o >>= 1) s += __shfl_xor_sync(0xffffffffu, s, o);
    if ((tid & 31) == 0) sh[tid >> 5] = s;
    __syncthreads();
    float tot = 0.f;
#pragma unroll
    for (int w = 0; w < 8; w++) tot += sh[w];
    const float inv = 1.f / tot;
    if (SUB) {
        __syncthreads();
#pragma unroll
        for (int o = 16; o; o >>= 1) ssub += __shfl_xor_sync(0xffffffffu, ssub, o);
        if ((tid & 31) == 0) sh[tid >> 5] = ssub;
        __syncthreads();
        if (tid == 0) {
            float st = 0.f;
#pragma unroll
            for (int w = 0; w < 8; w++) st += sh[w];
            subsum[row] = st * inv;
        }
    }
#pragma unroll
    for (int j = 0; j < NIT; j++) {
        int i = tid + (j << 8);
        if (i < L) pr[i] = __float2half(v[j] * inv);
    }
}

// -------------------- embed / mse / attnsum / init / final ------------------
__global__ void embed_k(const int* __restrict__ seq, const float* __restrict__ emb,
                        float* __restrict__ x)
{
    long i = (long)blockIdx.x * blockDim.x + threadIdx.x;
    if (i >= 2097152L) return;
    int d = (int)(i & 511);
    long bt = i >> 9;
    int t = (int)(bt & 511);
    int tok = seq[bt];
    int j2 = d & ~1;
    float ang = (float)t * expf(-0.017988946039015984f * (float)j2);
    float pe = (d & 1) ? cosf(ang) : sinf(ang);
    x[i] = emb[(long)tok * 512 + d] + pe;
}

__global__ void mse_k(const float* __restrict__ a, const float* __restrict__ b,
                      const float* __restrict__ S, float* __restrict__ outScalar, long n)
{
    long i0 = (long)blockIdx.x * blockDim.x + threadIdx.x;
    long stride = (long)gridDim.x * blockDim.x;
    float s = 0.f;
    for (long i = i0; i < n; i += stride) {
        float d = a[i] / S[i >> 6] - b[i];
        s += d * d;
    }
    __shared__ float sh[8];
#pragma unroll
    for (int o = 16; o; o >>= 1) s += __shfl_xor_sync(0xffffffffu, s, o);
    int tid = threadIdx.x;
    if ((tid & 31) == 0) sh[tid >> 5] = s;
    __syncthreads();
    if (tid == 0) {
        float tot = 0.f;
#pragma unroll
        for (int w = 0; w < 8; w++) tot += sh[w];
        atomicAdd(outScalar, tot);
    }
}

__global__ void attnsum_k(const __half* __restrict__ dotsH, float* __restrict__ out)
{
    long i = (long)blockIdx.x * 256 + threadIdx.x;
    if (i >= 294912L) return;
    const __half2* p = (const __half2*)dotsH + i;
    float sx = 0.f, sy = 0.f;
#pragma unroll 8
    for (int sl = 0; sl < 256; sl++) {
        float2 f = __half22float2(p[(long)sl * 294912L]);
        sx += f.x; sy += f.y;
    }
    *(float2*)(out + OFF_ATTN + 2 * i) = make_float2(sx * (1.f / 256.f), sy * (1.f / 256.f));
}

__global__ void init_k(float* __restrict__ out)
{
    if (threadIdx.x == 0) { out[OFF_AUX] = 0.f; out[OFF_ZERO] = 0.f; }
}
__global__ void final_k(float* __restrict__ out)
{
    if (threadIdx.x == 0) out[OFF_AUX] *= (1.f / (4.f * 2097152.f));
}

// ---------------------------------------------------------------------------
extern "C" void kernel_launch(void* const* d_in, const int* in_sizes, int n_in,
                              void* d_out, int out_size)
{
    const int*   seq   = (const int*)  d_in[0];
    const float* mems  = (const float*)d_in[2];
    const float* cmems = (const float*)d_in[3];
    const float* emb   = (const float*)d_in[4];
    const float* ln1g  = (const float*)d_in[5];
    const float* ln1b  = (const float*)d_in[6];
    const float* Wq    = (const float*)d_in[7];
    const float* Wkv   = (const float*)d_in[8];
    const float* Wo    = (const float*)d_in[9];
    const float* bo    = (const float*)d_in[10];
    const float* convw = (const float*)d_in[11];
    const float* convb = (const float*)d_in[12];
    const float* ln2g  = (const float*)d_in[13];
    const float* ln2b  = (const float*)d_in[14];
    const float* W1    = (const float*)d_in[15];
    const float* b1    = (const float*)d_in[16];
    const float* W2    = (const float*)d_in[17];
    const float* b2    = (const float*)d_in[18];
    float* out = (float*)d_out;

    __half *hmems, *hcmems, *hxn, *hxn2, *qh, *kvh, *ckvh, *dotsH, *dots2H;
    __half *attnoh, *ffhh, *cmh;
    __half *WqTh, *WkvTh, *WoTh, *cwh, *W1Th, *W2Th;
    float *o1, *o2, *Ssub;
    cudaGetSymbolAddress((void**)&hmems, g_hmems);   cudaGetSymbolAddress((void**)&hcmems, g_hcmems);
    cudaGetSymbolAddress((void**)&hxn, g_hxn);       cudaGetSymbolAddress((void**)&hxn2, g_hxn2);
    cudaGetSymbolAddress((void**)&qh, g_qh);         cudaGetSymbolAddress((void**)&kvh, g_kvh);
    cudaGetSymbolAddress((void**)&ckvh, g_ckvh);     cudaGetSymbolAddress((void**)&dotsH, g_dotsH);
    cudaGetSymbolAddress((void**)&dots2H, g_dots2H); cudaGetSymbolAddress((void**)&attnoh, g_attnoh);
    cudaGetSymbolAddress((void**)&ffhh, g_ffhh);     cudaGetSymbolAddress((void**)&cmh, g_cmh);
    cudaGetSymbolAddress((void**)&WqTh, g_WqTh);     cudaGetSymbolAddress((void**)&WkvTh, g_WkvTh);
    cudaGetSymbolAddress((void**)&WoTh, g_WoTh);     cudaGetSymbolAddress((void**)&cwh, g_cwh);
    cudaGetSymbolAddress((void**)&W1Th, g_W1Th);     cudaGetSymbolAddress((void**)&W2Th, g_W2Th);
    cudaGetSymbolAddress((void**)&o1, g_o1);         cudaGetSymbolAddress((void**)&o2, g_o2);
    cudaGetSymbolAddress((void**)&Ssub, g_S);

    const int SM128  = 3 * (128 + 128) * 80;               // 61440
    const int SM64T  = 3 * (128 * 80 + 32 * 144);          // 44544
    cudaFuncSetAttribute(hm_gemm<128,0,1,false>, cudaFuncAttributeMaxDynamicSharedMemorySize, SM128);
    cudaFuncSetAttribute(hm_gemm<128,1,2,false>, cudaFuncAttributeMaxDynamicSharedMemorySize, SM128);
    cudaFuncSetAttribute(hm_gemm<128,2,0,false>, cudaFuncAttributeMaxDynamicSharedMemorySize, SM128);
    cudaFuncSetAttribute(hm_gemm<128,3,1,false>, cudaFuncAttributeMaxDynamicSharedMemorySize, SM128);
    cudaFuncSetAttribute(hm_gemm<64,0,1,true>,   cudaFuncAttributeMaxDynamicSharedMemorySize, SM64T);
    cudaFuncSetAttribute(hm_gemm<64,0,0,true>,   cudaFuncAttributeMaxDynamicSharedMemorySize, SM64T);

    float* x   = out;
    float* aux = out + OFF_AUX;

    init_k <<<1, 32>>>(out);
    embed_k<<<8192, 256>>>(seq, emb, x);

    // ---- one-time conversions ----
    dim3 tb(32, 8);
    tr_k<<<dim3(16,16,4), tb>>>(Wq,  WqTh,  512,  512,  262144, 262144);
    tr_k<<<dim3(32,16,4), tb>>>(Wkv, WkvTh, 1024, 512,  524288, 524288);
    tr_k<<<dim3(16,16,4), tb>>>(Wo,  WoTh,  512,  512,  262144, 262144);
    tr_k<<<dim3(64,16,4), tb>>>(W1,  W1Th,  2048, 512,  1048576, 1048576);
    tr_k<<<dim3(16,64,4), tb>>>(W2,  W2Th,  512,  2048, 1048576, 1048576);
    convt2_k<<<16384, 256>>>(convw, cwh);
    cvt16_k<<<8192, 256>>>(mems,  hmems,  2097152L);
    cvt16_k<<<2048, 256>>>(cmems, hcmems, 524288L);

    // ---- hoisted layer-input GEMMs (all 4 layers, z = l*8+b) ----
    hm_gemm<128,0,1,false><<<dim3(8,1,32),256,SM128>>>(hcmems, WkvTh, nullptr, kvh,
        512, 512,512,1024, 524288,65536, 524288,0, 9437184,1179648, 8, nullptr, 0);
    hm_gemm<128,0,1,false><<<dim3(8,4,32),256,SM128>>>(hmems, WkvTh, nullptr, kvh + 131072,
        512, 512,512,1024, 2097152,262144, 524288,0, 9437184,1179648, 8, nullptr, 0);
    hm_gemm<128,1,2,false><<<dim3(4,8,4),256,SM128>>>(hmems, cwh, out + OFF_CMEMS, cmh,
        2048, 2048,2048,512, 2097152,0, 1048576,0, 524288,0, 1, convb, 512);
    hm_gemm<128,0,1,false><<<dim3(8,1,32),256,SM128>>>(cmh, WkvTh, nullptr, ckvh,
        512, 512,512,1024, 524288,65536, 524288,0, 1048576,131072, 8, nullptr, 0);

    for (int i = 0; i < 4; i++) {
        const __half* WqTh_i  = WqTh  + (long)i * 262144;
        const __half* WkvTh_i = WkvTh + (long)i * 524288;
        const __half* WoTh_i  = WoTh  + (long)i * 262144;
        const __half* W1Th_i  = W1Th  + (long)i * 1048576;
        const __half* W2Th_i  = W2Th  + (long)i * 1048576;
        __half* kvh_l  = kvh  + (long)i * 9437184;
        __half* ckvh_l = ckvh + (long)i * 1048576;
        __half* dotsH_l = dotsH + (long)i * 37748736;
        float* xn = out + OFF_MEMS + (long)i * 2097152;

        ln_k<<<4096, 128>>>(x, ln1g + i * 512, ln1b + i * 512, xn, hxn);

        // q = xn @ Wq
        hm_gemm<128,0,1,false><<<dim3(4,32,1),256,SM128>>>(hxn, WqTh_i, nullptr, qh,
            512, 512,512,512, 0,0,0,0,0,0,1, nullptr, 0);
        // kv rows 640-1151 (xn part)
        hm_gemm<128,0,1,false><<<dim3(8,4,8),256,SM128>>>(hxn, WkvTh_i, nullptr, kvh_l + 655360,
            512, 512,512,1024, 262144,0, 0,0, 1179648,0, 1, nullptr, 0);

        // logits = q @ k^T  -> fp16 into dotsH_l   (z = b*8+h)
        hm_gemm<128,0,1,false><<<dim3(9,4,64),256,SM128>>>(qh, kvh_l, nullptr, dotsH_l,
            64, 512,1024,1152, 262144,64, 1179648,64, 4718592,589824, 8, nullptr, 0);

        // softmax in place + sub-block mass
        softmax_k<1152,true><<<32768,256>>>(dotsH_l, 0.125f, Ssub);

        // attno = P @ v   (TRB)
        hm_gemm<64,0,1,true><<<dim3(1,4,64),256,SM64T>>>(dotsH_l, kvh_l + 512, nullptr, attnoh,
            1152, 1152,1024,512, 4718592,589824, 1179648,64, 262144,64, 8, nullptr, 0);

        // x = attno @ Wo + bo + x
        hm_gemm<128,2,0,false><<<dim3(4,32,1),256,SM128>>>(attnoh, WoTh_i, x, nullptr,
            512, 512,512,512, 0,0,0,0,0,0,1, bo + i * 512, 0);

        // o1_raw = P[:,128:640] @ v_mem  (TRB)
        hm_gemm<64,0,0,true><<<dim3(1,4,64),256,SM64T>>>(dotsH_l + 128, kvh_l + 131584, o1, nullptr,
            512, 1152,1024,64, 4718592,589824, 1179648,64, 262144,32768, 8, nullptr, 0);

        // aux-cmem: logits2 = q @ ck^T -> fp16 ; softmax ; o2 = P2 @ cv (TRB)
        hm_gemm<128,0,1,false><<<dim3(1,4,64),256,SM128>>>(qh, ckvh_l, nullptr, dots2H,
            64, 512,1024,128, 262144,64, 131072,64, 524288,65536, 8, nullptr, 0);
        softmax_k<128,false><<<32768,256>>>(dots2H, 0.125f, nullptr);
        hm_gemm<64,0,0,true><<<dim3(1,4,64),256,SM64T>>>(dots2H, ckvh_l + 512, o2, nullptr,
            128, 128,1024,64, 524288,65536, 131072,64, 262144,32768, 8, nullptr, 0);

        mse_k<<<512,256>>>(o1, o2, Ssub, aux, 2097152L);

        // FFN
        ln_k<<<4096,128>>>(x, ln2g + i * 512, ln2b + i * 512, nullptr, hxn2);
        hm_gemm<128,3,1,false><<<dim3(16,32,1),256,SM128>>>(hxn2, W1Th_i, nullptr, ffhh,
            512, 512,512,2048, 0,0,0,0,0,0,1, b1 + i * 2048, 0);
        hm_gemm<128,2,0,false><<<dim3(4,32,1),256,SM128>>>(ffhh, W2Th_i, x, nullptr,
            2048, 2048,2048,512, 0,0,0,0,0,0,1, b2 + i * 512, 0);
    }

    attnsum_k<<<1152,256>>>(dotsH, out);
    final_k<<<1,32>>>(out);
}

// round 12
// speedup vs baseline: 6.3371x; 1.0398x over previous
#include <cuda_runtime.h>
#include <cuda_fp16.h>
#include <cstdint>
#include <math.h>

// ---------------------------------------------------------------------------
// CompressiveEncoder forward. FP16 mma.sync + ldmatrix(.trans) + cp.async.
// Deferred/batched aux chain; fused QKV projection.
// Output: x | new_mems | new_cmems | aux | 0 | attns_mean  (fp32)
// ---------------------------------------------------------------------------

#define OFF_MEMS   2097152L
#define OFF_CMEMS 10485760L
#define OFF_AUX   12582912L
#define OFF_ZERO  12582913L
#define OFF_ATTN  12582914L
#define ATTN_ELEMS 589824L

// -------------------- device scratch ---------------------------------------
__device__ __half g_hmems [8388608];     // [l][b][512][512]
__device__ __half g_hcmems[2097152];     // [l][b][128][512]
__device__ __half g_hxn   [2097152];
__device__ __half g_hxn2  [2097152];
__device__ __half g_qh    [8388608];     // [l][b][512][512]
__device__ __half g_kvh   [37748736];    // [l][b][1152][1024]  k|v per row
__device__ __half g_ckvh  [4194304];     // [l][b][128][1024]   ck|cv
__device__ __half g_dotsH [150994944];   // [l][64][512][1152]  logits->probs
__device__ __half g_dots2H[16777216];    // [l][64][512][128]
__device__ __half g_attnoh[2097152];
__device__ __half g_ffhh  [8388608];
__device__ __half g_cmh   [2097152];     // [l][b][128][512]
__device__ __half g_wqkvTh[3145728];     // [l][1536][512]  rows 0-511 Wq^T, 512-1535 Wkv^T
__device__ __half g_WoTh  [1048576];
__device__ __half g_cwh   [4194304];
__device__ __half g_W1Th  [4194304];
__device__ __half g_W2Th  [4194304];
__device__ float g_o1 [8388608];         // [l][64][512][64]
__device__ float g_o2 [8388608];
__device__ float g_S  [131072];          // [l][32768]

// -------------------- helpers ----------------------------------------------
__device__ __forceinline__ void mma_f16(float* d, uint32_t a0, uint32_t a1,
                                        uint32_t a2, uint32_t a3,
                                        uint32_t b0, uint32_t b1) {
    asm volatile("mma.sync.aligned.m16n8k16.row.col.f32.f16.f16.f32 "
                 "{%0,%1,%2,%3}, {%4,%5,%6,%7}, {%8,%9}, {%0,%1,%2,%3};"
                 : "+f"(d[0]), "+f"(d[1]), "+f"(d[2]), "+f"(d[3])
                 : "r"(a0), "r"(a1), "r"(a2), "r"(a3), "r"(b0), "r"(b1));
}
#define LDSM_X4(r0, r1, r2, r3, addr) \
    asm volatile("ldmatrix.sync.aligned.m8n8.x4.shared.b16 {%0,%1,%2,%3}, [%4];" \
                 : "=r"(r0), "=r"(r1), "=r"(r2), "=r"(r3) : "r"(addr))
#define LDSM_X4_T(r0, r1, r2, r3, addr) \
    asm volatile("ldmatrix.sync.aligned.m8n8.x4.trans.shared.b16 {%0,%1,%2,%3}, [%4];" \
                 : "=r"(r0), "=r"(r1), "=r"(r2), "=r"(r3) : "r"(addr))
#define CP16(saddr, gaddr) \
    asm volatile("cp.async.cg.shared.global [%0], [%1], 16;" :: "r"(saddr), "l"(gaddr))
#define CP_COMMIT() asm volatile("cp.async.commit_group;" ::: "memory")
#define CP_WAIT1()  asm volatile("cp.async.wait_group 1;" ::: "memory")

__device__ __forceinline__ float gelu_f(float v) {
    return 0.5f * v * (1.f + erff(v * 0.70710678118654752f));
}

// -------------------- FP16 GEMM --------------------------------------------
// TRB=false: C[z] = A[z] @ B[z]^T, B stored [N,K].  TRB=true: B [K,N] (.trans)
// 3-level batch: z1=z/(zm2*zm3), z2=(z/zm3)%zm2, z3=z%zm3; off=z1*s1+z2*s2+z3*s3
// EPI: 0 none, 1 +bias, 2 +bias+Cf, 3 gelu(.+bias)
// OUT: 0 f32, 1 f16, 2 both, 3 qkv-split (n<512 -> Ch ld512; else Ch2 ld1024)
template<int BN, int EPI, int OUT, bool TRB>
__global__ void __launch_bounds__(256)
hm_gemm(const __half* __restrict__ A, const __half* __restrict__ B,
        float* __restrict__ Cf, __half* __restrict__ Ch,
        int K, int lda, int ldb, int ldc,
        long sA1, long sA2, long sA3, long sB1, long sB2, long sB3,
        long sC1, long sC2, long sC3, int zm2, int zm3,
        const float* __restrict__ bias, long sBias)
{
    constexpr int BM = 128, NST = 3;
    constexpr int BNB = BN * 2 + 16;                      // TRB B row pitch
    constexpr int ABY = BM * 80;
    constexpr int STGB = TRB ? (ABY + 32 * BNB) : ((BM + BN) * 80);
    constexpr int WN = (BN == 128) ? 4 : 2, WM = 8 / WN;
    constexpr int WTM = BM / WM;
    constexpr int MF = WTM / 16;
    constexpr int NBn = (BN == 128) ? 2 : 1;
    constexpr int NBt = (32 * (BN / 8)) / 256;

    extern __shared__ char smc[];
    uint32_t sbase;
    asm("{ .reg .u64 t; cvta.to.shared.u64 t, %1; cvt.u32.u64 %0, t; }"
        : "=r"(sbase) : "l"(smc));

    const int z = blockIdx.z;
    const int z1 = z / (zm2 * zm3);
    const int z2 = (z / zm3) % zm2;
    const int z3 = z % zm3;
    A += z1 * sA1 + z2 * sA2 + z3 * sA3;
    B += z1 * sB1 + z2 * sB2 + z3 * sB3;
    __half* Ch2 = nullptr;
    if (OUT == 3) {
        Ch  += z1 * sC1;
        Ch2 = ((__half*)Cf) + z1 * sC3;
    } else {
        const long coff = z1 * sC1 + z2 * sC2 + z3 * sC3;
        if (OUT != 1) Cf += coff;
        if (OUT >= 1) Ch += coff;
    }
    if (EPI >= 1) bias += z1 * sBias;
    const int m0 = blockIdx.y * BM, n0 = blockIdx.x * BN;
    const int tid = threadIdx.x, lane = tid & 31, wid = tid >> 5;
    const int wm = wid % WM, wn = wid / WM;
    const int mbase = wm * WTM, nbase = wn * 32;

    float acc[MF][4][4];
#pragma unroll
    for (int i = 0; i < MF; i++)
#pragma unroll
        for (int j = 0; j < 4; j++)
#pragma unroll
            for (int r = 0; r < 4; r++) acc[i][j][r] = 0.f;

    const int KT = K >> 5;

    auto issue = [&](int kt, int st) {
        const int k0 = kt << 5;
        const uint32_t s0 = sbase + st * STGB;
#pragma unroll
        for (int i = 0; i < 2; i++) {
            int idx = tid + i * 256, r = idx >> 2, c = idx & 3;
            CP16(s0 + r * 80 + c * 16, A + (long)(m0 + r) * lda + k0 + c * 8);
        }
        if (!TRB) {
#pragma unroll
            for (int i = 0; i < NBn; i++) {
                int idx = tid + i * 256, r = idx >> 2, c = idx & 3;
                CP16(s0 + ABY + r * 80 + c * 16,
                     B + (long)(n0 + r) * ldb + k0 + c * 8);
            }
        } else {
            constexpr int CH = BN / 8;
#pragma unroll
            for (int i = 0; i < NBt; i++) {
                int idx = tid + i * 256, r = idx / CH, c = idx % CH;
                CP16(s0 + ABY + r * BNB + c * 16,
                     B + (long)(k0 + r) * ldb + n0 + c * 8);
            }
        }
    };

    const int g2 = lane >> 3, t7 = lane & 7;
    const uint32_t khalf = ((g2 >> 1) << 4);
    uint32_t aoff[MF], boff[2];
#pragma unroll
    for (int mf = 0; mf < MF; mf++)
        aoff[mf] = (uint32_t)(mbase + mf * 16 + ((g2 & 1) << 3) + t7) * 80 + khalf;
    if (!TRB) {
#pragma unroll
        for (int np = 0; np < 2; np++)
            boff[np] = (uint32_t)ABY +
                       (uint32_t)(nbase + np * 16 + ((g2 & 1) << 3) + t7) * 80 + khalf;
    } else {
#pragma unroll
        for (int np = 0; np < 2; np++)
            boff[np] = (uint32_t)ABY +
                       (uint32_t)(((g2 >> 1) << 3) + t7) * BNB +
                       (uint32_t)(nbase + np * 16 + ((g2 & 1) << 3)) * 2;
    }

    auto compute = [&](int st) {
        const uint32_t s0 = sbase + st * STGB;
#pragma unroll
        for (int ks = 0; ks < 2; ks++) {
            uint32_t a[MF][4], b[2][4];
#pragma unroll
            for (int mf = 0; mf < MF; mf++)
                LDSM_X4(a[mf][0], a[mf][1], a[mf][2], a[mf][3],
                        s0 + aoff[mf] + ks * 32);
#pragma unroll
            for (int np = 0; np < 2; np++) {
                if (!TRB) {
                    LDSM_X4(b[np][0], b[np][1], b[np][2], b[np][3],
                            s0 + boff[np] + ks * 32);
                } else {
                    LDSM_X4_T(b[np][0], b[np][1], b[np][2], b[np][3],
                              s0 + boff[np] + ks * 16 * BNB);
                }
            }
#pragma unroll
            for (int mf = 0; mf < MF; mf++)
#pragma unroll
                for (int np = 0; np < 2; np++) {
                    mma_f16(acc[mf][2 * np],     a[mf][0], a[mf][1], a[mf][2], a[mf][3],
                            b[np][0], b[np][2]);
                    mma_f16(acc[mf][2 * np + 1], a[mf][0], a[mf][1], a[mf][2], a[mf][3],
                            b[np][1], b[np][3]);
                }
        }
    };

    int ldi = 0;
#pragma unroll
    for (int s = 0; s < NST - 1; s++) {
        if (ldi < KT) issue(ldi, s);
        CP_COMMIT();
        ldi++;
    }
    for (int kt = 0; kt < KT; kt++) {
        CP_WAIT1();
        __syncthreads();
        compute(kt % NST);
        if (ldi < KT) issue(ldi, ldi % NST);
        CP_COMMIT();
        ldi++;
    }

    // ---- epilogue ----
    const bool qside = (n0 < 512);
    const int rbase = m0 + mbase + (lane >> 2);
    const int cbase = n0 + nbase + 2 * (lane & 3);
#pragma unroll
    for (int mf = 0; mf < MF; mf++) {
#pragma unroll
        for (int nf = 0; nf < 4; nf++) {
#pragma unroll
            for (int half = 0; half < 2; half++) {
                const int m = rbase + mf * 16 + half * 8;
                const int n = cbase + nf * 8;
                float2 v = make_float2(acc[mf][nf][half * 2], acc[mf][nf][half * 2 + 1]);
                if (EPI >= 1) { v.x += bias[n]; v.y += bias[n + 1]; }
                if (OUT == 3) {
                    __half2 h2 = __floats2half2_rn(v.x, v.y);
                    if (qside) *(__half2*)(Ch  + (long)m * 512  + n)        = h2;
                    else       *(__half2*)(Ch2 + (long)m * 1024 + (n - 512)) = h2;
                } else {
                    const long idx = (long)m * ldc + n;
                    if (EPI == 2) { float2 c0 = *(const float2*)(Cf + idx); v.x += c0.x; v.y += c0.y; }
                    if (EPI == 3) { v.x = gelu_f(v.x); v.y = gelu_f(v.y); }
                    if (OUT != 1) *(float2*)(Cf + idx) = v;
                    if (OUT == 1 || OUT == 2) *(__half2*)(Ch + idx) = __floats2half2_rn(v.x, v.y);
                }
            }
        }
    }
}

// -------------------- weight transpose fp32 -> fp16 -------------------------
__global__ void tr_k(const float* __restrict__ in, __half* __restrict__ out,
                     int ldi, int ldo, long sI, long sO)
{
    __shared__ float t[32][33];
    in += blockIdx.z * sI; out += blockIdx.z * sO;
    const int n0 = blockIdx.x * 32, k0 = blockIdx.y * 32;
    const int tx = threadIdx.x, ty = threadIdx.y;
#pragma unroll
    for (int j = 0; j < 32; j += 8) t[ty + j][tx] = in[(long)(k0 + ty + j) * ldi + n0 + tx];
    __syncthreads();
#pragma unroll
    for (int j = 0; j < 32; j += 8)
        out[(long)(n0 + ty + j) * ldo + k0 + tx] = __float2half(t[tx][ty + j]);
}

__global__ void convt2_k(const float* __restrict__ w, __half* __restrict__ wt)
{
    long i = (long)blockIdx.x * 256 + threadIdx.x;
    if (i >= 4L * 1048576L) return;
    long l = i >> 20, r0 = i & 1048575L;
    int o = (int)(r0 >> 11), k = (int)(r0 & 2047);
    int r = k >> 9, c = k & 511;
    wt[i] = __float2half(w[l * 1048576L + ((long)o * 512 + c) * 4 + r]);
}

__global__ void cvt16_k(const float* __restrict__ in, __half* __restrict__ out, long n4)
{
    long i = (long)blockIdx.x * 256 + threadIdx.x;
    if (i >= n4) return;
    float4 v = ((const float4*)in)[i];
    ((__half2*)out)[2 * i]     = __floats2half2_rn(v.x, v.y);
    ((__half2*)out)[2 * i + 1] = __floats2half2_rn(v.z, v.w);
}

// -------------------- layernorm --------------------------------------------
__global__ void ln_k(const float* __restrict__ x, const float* __restrict__ g,
                     const float* __restrict__ b, float* __restrict__ out,
                     __half* __restrict__ outh)
{
    const long row = blockIdx.x;
    const float* xr = x + row * 512;
    const int tid = threadIdx.x;
    float v[4]; float s = 0.f;
#pragma unroll
    for (int j = 0; j < 4; j++) { v[j] = xr[tid + j * 128]; s += v[j]; }
    __shared__ float sh[4];
#pragma unroll
    for (int o = 16; o; o >>= 1) s += __shfl_xor_sync(0xffffffffu, s, o);
    if ((tid & 31) == 0) sh[tid >> 5] = s;
    __syncthreads();
    const float mu = (sh[0] + sh[1] + sh[2] + sh[3]) * (1.f / 512.f);
    float s2 = 0.f;
#pragma unroll
    for (int j = 0; j < 4; j++) { float d = v[j] - mu; s2 += d * d; }
    __syncthreads();
#pragma unroll
    for (int o = 16; o; o >>= 1) s2 += __shfl_xor_sync(0xffffffffu, s2, o);
    if ((tid & 31) == 0) sh[tid >> 5] = s2;
    __syncthreads();
    const float rs = rsqrtf((sh[0] + sh[1] + sh[2] + sh[3]) * (1.f / 512.f) + 1e-5f);
#pragma unroll
    for (int j = 0; j < 4; j++) {
        int d = tid + j * 128;
        float val = (v[j] - mu) * rs * g[d] + b[d];
        if (out)  out[row * 512 + d] = val;
        outh[row * 512 + d] = __float2half(val);
    }
}

// -------------------- softmax: fp16 in place; optional sub-mass -------------
template<int L, bool SUB>
__global__ void softmax_k(__half* __restrict__ P, float scale,
                          float* __restrict__ subsum)
{
    const long row = blockIdx.x;
    __half* pr = P + row * (long)L;
    const int tid = threadIdx.x;
    constexpr int NIT = (L + 255) >> 8;
    float v[NIT]; float mx = -3.0e38f;
#pragma unroll
    for (int j = 0; j < NIT; j++) {
        int i = tid + (j << 8);
        float t = (i < L) ? __half2float(pr[i]) * scale : -3.0e38f;
        v[j] = t; mx = fmaxf(mx, t);
    }
    __shared__ float sh[8];
#pragma unroll
    for (int o = 16; o; o >>= 1) mx = fmaxf(mx, __shfl_xor_sync(0xffffffffu, mx, o));
    if ((tid & 31) == 0) sh[tid >> 5] = mx;
    __syncthreads();
    float bm = sh[0];
#pragma unroll
    for (int w = 1; w < 8; w++) bm = fmaxf(bm, sh[w]);
    float s = 0.f, ssub = 0.f;
#pragma unroll
    for (int j = 0; j < NIT; j++) {
        int i = tid + (j << 8);
        if (i < L) {
            float e = __expf(v[j] - bm); v[j] = e; s += e;
            if (SUB && i >= 128 && i < 640) ssub += e;
        }
    }
    __syncthreads();
#pragma unroll
    for (int o = 16; o; o >>= 1) s += __shfl_xor_sync(0xffffffffu, s, o);
    if ((tid & 31) == 0) sh[tid >> 5] = s;
    __syncthreads();
    float tot = 0.f;
#pragma unroll
    for (int w = 0; w < 8; w++) tot += sh[w];
    const float inv = 1.f / tot;
    if (SUB) {
        __syncthreads();
#pragma unroll
        for (int o = 16; o; o >>= 1) ssub += __shfl_xor_sync(0xffffffffu, ssub, o);
        if ((tid & 31) == 0) sh[tid >> 5] = ssub;
        __syncthreads();
        if (tid == 0) {
            float st = 0.f;
#pragma unroll
            for (int w = 0; w < 8; w++) st += sh[w];
            subsum[row] = st * inv;
        }
    }
#pragma unroll
    for (int j = 0; j < NIT; j++) {
        int i = tid + (j << 8);
        if (i < L) pr[i] = __float2half(v[j] * inv);
    }
}

// -------------------- embed / mse / attnsum / init / final ------------------
__global__ void embed_k(const int* __restrict__ seq, const float* __restrict__ emb,
                        float* __restrict__ x)
{
    long i = (long)blockIdx.x * blockDim.x + threadIdx.x;
    if (i >= 2097152L) return;
    int d = (int)(i & 511);
    long bt = i >> 9;
    int t = (int)(bt & 511);
    int tok = seq[bt];
    int j2 = d & ~1;
    float ang = (float)t * expf(-0.017988946039015984f * (float)j2);
    float pe = (d & 1) ? cosf(ang) : sinf(ang);
    x[i] = emb[(long)tok * 512 + d] + pe;
}

__global__ void mse_k(const float* __restrict__ a, const float* __restrict__ b,
                      const float* __restrict__ S, float* __restrict__ outScalar, long n)
{
    long i0 = (long)blockIdx.x * blockDim.x + threadIdx.x;
    long stride = (long)gridDim.x * blockDim.x;
    float s = 0.f;
    for (long i = i0; i < n; i += stride) {
        float d = a[i] / S[i >> 6] - b[i];
        s += d * d;
    }
    __shared__ float sh[8];
#pragma unroll
    for (int o = 16; o; o >>= 1) s += __shfl_xor_sync(0xffffffffu, s, o);
    int tid = threadIdx.x;
    if ((tid & 31) == 0) sh[tid >> 5] = s;
    __syncthreads();
    if (tid == 0) {
        float tot = 0.f;
#pragma unroll
        for (int w = 0; w < 8; w++) tot += sh[w];
        atomicAdd(outScalar, tot);
    }
}

__global__ void attnsum_k(const __half* __restrict__ dotsH, float* __restrict__ out)
{
    long i = (long)blockIdx.x * 256 + threadIdx.x;
    if (i >= 294912L) return;
    const __half2* p = (const __half2*)dotsH + i;
    float sx = 0.f, sy = 0.f;
#pragma unroll 8
    for (int sl = 0; sl < 256; sl++) {
        float2 f = __half22float2(p[(long)sl * 294912L]);
        sx += f.x; sy += f.y;
    }
    *(float2*)(out + OFF_ATTN + 2 * i) = make_float2(sx * (1.f / 256.f), sy * (1.f / 256.f));
}

__global__ void init_k(float* __restrict__ out)
{
    if (threadIdx.x == 0) { out[OFF_AUX] = 0.f; out[OFF_ZERO] = 0.f; }
}
__global__ void final_k(float* __restrict__ out)
{
    if (threadIdx.x == 0) out[OFF_AUX] *= (1.f / (4.f * 2097152.f));
}

// ---------------------------------------------------------------------------
extern "C" void kernel_launch(void* const* d_in, const int* in_sizes, int n_in,
                              void* d_out, int out_size)
{
    const int*   seq   = (const int*)  d_in[0];
    const float* mems  = (const float*)d_in[2];
    const float* cmems = (const float*)d_in[3];
    const float* emb   = (const float*)d_in[4];
    const float* ln1g  = (const float*)d_in[5];
    const float* ln1b  = (const float*)d_in[6];
    const float* Wq    = (const float*)d_in[7];
    const float* Wkv   = (const float*)d_in[8];
    const float* Wo    = (const float*)d_in[9];
    const float* bo    = (const float*)d_in[10];
    const float* convw = (const float*)d_in[11];
    const float* convb = (const float*)d_in[12];
    const float* ln2g  = (const float*)d_in[13];
    const float* ln2b  = (const float*)d_in[14];
    const float* W1    = (const float*)d_in[15];
    const float* b1    = (const float*)d_in[16];
    const float* W2    = (const float*)d_in[17];
    const float* b2    = (const float*)d_in[18];
    float* out = (float*)d_out;

    __half *hmems, *hcmems, *hxn, *hxn2, *qh, *kvh, *ckvh, *dotsH, *dots2H;
    __half *attnoh, *ffhh, *cmh;
    __half *wqkvTh, *WoTh, *cwh, *W1Th, *W2Th;
    float *o1, *o2, *Ssub;
    cudaGetSymbolAddress((void**)&hmems, g_hmems);   cudaGetSymbolAddress((void**)&hcmems, g_hcmems);
    cudaGetSymbolAddress((void**)&hxn, g_hxn);       cudaGetSymbolAddress((void**)&hxn2, g_hxn2);
    cudaGetSymbolAddress((void**)&qh, g_qh);         cudaGetSymbolAddress((void**)&kvh, g_kvh);
    cudaGetSymbolAddress((void**)&ckvh, g_ckvh);     cudaGetSymbolAddress((void**)&dotsH, g_dotsH);
    cudaGetSymbolAddress((void**)&dots2H, g_dots2H); cudaGetSymbolAddress((void**)&attnoh, g_attnoh);
    cudaGetSymbolAddress((void**)&ffhh, g_ffhh);     cudaGetSymbolAddress((void**)&cmh, g_cmh);
    cudaGetSymbolAddress((void**)&wqkvTh, g_wqkvTh); cudaGetSymbolAddress((void**)&WoTh, g_WoTh);
    cudaGetSymbolAddress((void**)&cwh, g_cwh);       cudaGetSymbolAddress((void**)&W1Th, g_W1Th);
    cudaGetSymbolAddress((void**)&W2Th, g_W2Th);
    cudaGetSymbolAddress((void**)&o1, g_o1);         cudaGetSymbolAddress((void**)&o2, g_o2);
    cudaGetSymbolAddress((void**)&Ssub, g_S);

    const int SM128  = 3 * (128 + 128) * 80;               // 61440
    const int SM64T  = 3 * (128 * 80 + 32 * 144);          // 44544
    cudaFuncSetAttribute(hm_gemm<128,0,1,false>, cudaFuncAttributeMaxDynamicSharedMemorySize, SM128);
    cudaFuncSetAttribute(hm_gemm<128,1,2,false>, cudaFuncAttributeMaxDynamicSharedMemorySize, SM128);
    cudaFuncSetAttribute(hm_gemm<128,2,0,false>, cudaFuncAttributeMaxDynamicSharedMemorySize, SM128);
    cudaFuncSetAttribute(hm_gemm<128,3,1,false>, cudaFuncAttributeMaxDynamicSharedMemorySize, SM128);
    cudaFuncSetAttribute(hm_gemm<128,0,3,false>, cudaFuncAttributeMaxDynamicSharedMemorySize, SM128);
    cudaFuncSetAttribute(hm_gemm<64,0,1,true>,   cudaFuncAttributeMaxDynamicSharedMemorySize, SM64T);
    cudaFuncSetAttribute(hm_gemm<64,0,0,true>,   cudaFuncAttributeMaxDynamicSharedMemorySize, SM64T);

    float* x   = out;
    float* aux = out + OFF_AUX;

    init_k <<<1, 32>>>(out);
    embed_k<<<8192, 256>>>(seq, emb, x);

    // ---- one-time conversions ----
    dim3 tb(32, 8);
    tr_k<<<dim3(16,16,4), tb>>>(Wq,  wqkvTh,          512,  512, 262144, 786432);
    tr_k<<<dim3(32,16,4), tb>>>(Wkv, wqkvTh + 262144, 1024, 512, 524288, 786432);
    tr_k<<<dim3(16,16,4), tb>>>(Wo,  WoTh,  512,  512,  262144, 262144);
    tr_k<<<dim3(64,16,4), tb>>>(W1,  W1Th,  2048, 512,  1048576, 1048576);
    tr_k<<<dim3(16,64,4), tb>>>(W2,  W2Th,  512,  2048, 1048576, 1048576);
    convt2_k<<<16384, 256>>>(convw, cwh);
    cvt16_k<<<8192, 256>>>(mems,  hmems,  2097152L);
    cvt16_k<<<2048, 256>>>(cmems, hcmems, 524288L);

    const __half* WkvTh = wqkvTh + 262144;   // shared with combined buffer

    // ---- hoisted layer-input GEMMs (all 4 layers, z = l*8+b) ----
    hm_gemm<128,0,1,false><<<dim3(8,1,32),256,SM128>>>(hcmems, WkvTh, nullptr, kvh,
        512, 512,512,1024, 524288,65536,0, 786432,0,0, 9437184,1179648,0, 8,1, nullptr,0);
    hm_gemm<128,0,1,false><<<dim3(8,4,32),256,SM128>>>(hmems, WkvTh, nullptr, kvh + 131072,
        512, 512,512,1024, 2097152,262144,0, 786432,0,0, 9437184,1179648,0, 8,1, nullptr,0);
    hm_gemm<128,1,2,false><<<dim3(4,8,4),256,SM128>>>(hmems, cwh, out + OFF_CMEMS, cmh,
        2048, 2048,2048,512, 2097152,0,0, 1048576,0,0, 524288,0,0, 1,1, convb,512);
    hm_gemm<128,0,1,false><<<dim3(8,1,32),256,SM128>>>(cmh, WkvTh, nullptr, ckvh,
        512, 512,512,1024, 524288,65536,0, 786432,0,0, 1048576,131072,0, 8,1, nullptr,0);

    for (int i = 0; i < 4; i++) {
        const __half* wqkvTh_i = wqkvTh + (long)i * 786432;
        const __half* WoTh_i   = WoTh   + (long)i * 262144;
        const __half* W1Th_i   = W1Th   + (long)i * 1048576;
        const __half* W2Th_i   = W2Th   + (long)i * 1048576;
        __half* qh_l    = qh    + (long)i * 2097152;
        __half* kvh_l   = kvh   + (long)i * 9437184;
        __half* dotsH_l = dotsH + (long)i * 37748736;
        float*  Ssub_l  = Ssub  + (long)i * 32768;
        float*  xn = out + OFF_MEMS + (long)i * 2097152;

        ln_k<<<4096, 128>>>(x, ln1g + i * 512, ln1b + i * 512, xn, hxn);

        // fused q|kv(xn) projection: n<512 -> qh_l, else kvh rows 640+
        hm_gemm<128,0,3,false><<<dim3(12,4,8),256,SM128>>>(hxn, wqkvTh_i,
            (float*)(kvh_l + 655360), qh_l,
            512, 512,512,512, 262144,0,0, 0,0,0, 262144,0,1179648, 1,1, nullptr,0);

        // logits = q @ k^T -> fp16 (z = b*8+h)
        hm_gemm<128,0,1,false><<<dim3(9,4,64),256,SM128>>>(qh_l, kvh_l, nullptr, dotsH_l,
            64, 512,1024,1152, 262144,64,0, 1179648,64,0, 4718592,589824,0, 8,1, nullptr,0);

        softmax_k<1152,true><<<32768,256>>>(dotsH_l, 0.125f, Ssub_l);

        // attno = P @ v  (TRB)
        hm_gemm<64,0,1,true><<<dim3(1,4,64),256,SM64T>>>(dotsH_l, kvh_l + 512, nullptr, attnoh,
            1152, 1152,1024,512, 4718592,589824,0, 1179648,64,0, 262144,64,0, 8,1, nullptr,0);

        // x = attno @ Wo + bo + x
        hm_gemm<128,2,0,false><<<dim3(4,32,1),256,SM128>>>(attnoh, WoTh_i, x, nullptr,
            512, 512,512,512, 0,0,0, 0,0,0, 0,0,0, 1,1, bo + i * 512, 0);

        // FFN
        ln_k<<<4096,128>>>(x, ln2g + i * 512, ln2b + i * 512, nullptr, hxn2);
        hm_gemm<128,3,1,false><<<dim3(16,32,1),256,SM128>>>(hxn2, W1Th_i, nullptr, ffhh,
            512, 512,512,2048, 0,0,0, 0,0,0, 0,0,0, 1,1, b1 + i * 2048, 0);
        hm_gemm<128,2,0,false><<<dim3(4,32,1),256,SM128>>>(ffhh, W2Th_i, x, nullptr,
            2048, 2048,2048,512, 0,0,0, 0,0,0, 0,0,0, 1,1, b2 + i * 512, 0);
    }

    // ---- deferred aux chain, batched over all layers (z = ((l*8+b)*8+h)) ----
    // o1_raw = P[:,128:640] @ v_mem
    hm_gemm<64,0,0,true><<<dim3(1,4,256),256,SM64T>>>(dotsH + 128, kvh + 131584, o1, nullptr,
        512, 1152,1024,64, 37748736,4718592,589824, 9437184,1179648,64,
        2097152,262144,32768, 8,8, nullptr,0);
    // logits2 = q @ ck^T
    hm_gemm<128,0,1,false><<<dim3(1,4,256),256,SM128>>>(qh, ckvh, nullptr, dots2H,
        64, 512,1024,128, 2097152,262144,64, 1048576,131072,64,
        4194304,524288,65536, 8,8, nullptr,0);
    softmax_k<128,false><<<131072,256>>>(dots2H, 0.125f, nullptr);
    // o2 = P2 @ cv
    hm_gemm<64,0,0,true><<<dim3(1,4,256),256,SM64T>>>(dots2H, ckvh + 512, o2, nullptr,
        128, 128,1024,64, 4194304,524288,65536, 1048576,131072,64,
        2097152,262144,32768, 8,8, nullptr,0);
    mse_k<<<2048,256>>>(o1, o2, Ssub, aux, 8388608L);

    attnsum_k<<<1152,256>>>(dotsH, out);
    final_k<<<1,32>>>(out);
}

// round 13
// speedup vs baseline: 6.4916x; 1.0244x over previous
#include <cuda_runtime.h>
#include <cuda_fp16.h>
#include <cstdint>
#include <math.h>

// ---------------------------------------------------------------------------
// CompressiveEncoder forward. FP16 mma.sync + ldmatrix(.trans) + cp.async.
// PV GEMM fuses aux-o1 via accumulator snapshotting.
// Output: x | new_mems | new_cmems | aux | 0 | attns_mean  (fp32)
// ---------------------------------------------------------------------------

#define OFF_MEMS   2097152L
#define OFF_CMEMS 10485760L
#define OFF_AUX   12582912L
#define OFF_ZERO  12582913L
#define OFF_ATTN  12582914L
#define ATTN_ELEMS 589824L

// -------------------- device scratch ---------------------------------------
__device__ __half g_hmems [8388608];     // [l][b][512][512]
__device__ __half g_hcmems[2097152];     // [l][b][128][512]
__device__ __half g_hxn   [2097152];
__device__ __half g_hxn2  [2097152];
__device__ __half g_qh    [8388608];     // [l][b][512][512]
__device__ __half g_kvh   [37748736];    // [l][b][1152][1024]  k|v per row
__device__ __half g_ckvh  [4194304];     // [l][b][128][1024]   ck|cv
__device__ __half g_dotsH [150994944];   // [l][64][512][1152]  logits->probs
__device__ __half g_dots2H[16777216];    // [l][64][512][128]
__device__ __half g_attnoh[2097152];
__device__ __half g_ffhh  [8388608];
__device__ __half g_cmh   [2097152];     // [l][b][128][512]
__device__ __half g_wqkvTh[3145728];     // [l][1536][512]
__device__ __half g_WoTh  [1048576];
__device__ __half g_cwh   [4194304];
__device__ __half g_W1Th  [4194304];
__device__ __half g_W2Th  [4194304];
__device__ float g_o1 [8388608];         // [l][64][512][64]
__device__ float g_o2 [8388608];
__device__ float g_S  [131072];          // [l][32768]

// -------------------- helpers ----------------------------------------------
__device__ __forceinline__ void mma_f16(float* d, uint32_t a0, uint32_t a1,
                                        uint32_t a2, uint32_t a3,
                                        uint32_t b0, uint32_t b1) {
    asm volatile("mma.sync.aligned.m16n8k16.row.col.f32.f16.f16.f32 "
                 "{%0,%1,%2,%3}, {%4,%5,%6,%7}, {%8,%9}, {%0,%1,%2,%3};"
                 : "+f"(d[0]), "+f"(d[1]), "+f"(d[2]), "+f"(d[3])
                 : "r"(a0), "r"(a1), "r"(a2), "r"(a3), "r"(b0), "r"(b1));
}
#define LDSM_X4(r0, r1, r2, r3, addr) \
    asm volatile("ldmatrix.sync.aligned.m8n8.x4.shared.b16 {%0,%1,%2,%3}, [%4];" \
                 : "=r"(r0), "=r"(r1), "=r"(r2), "=r"(r3) : "r"(addr))
#define LDSM_X4_T(r0, r1, r2, r3, addr) \
    asm volatile("ldmatrix.sync.aligned.m8n8.x4.trans.shared.b16 {%0,%1,%2,%3}, [%4];" \
                 : "=r"(r0), "=r"(r1), "=r"(r2), "=r"(r3) : "r"(addr))
#define CP16(saddr, gaddr) \
    asm volatile("cp.async.cg.shared.global [%0], [%1], 16;" :: "r"(saddr), "l"(gaddr))
#define CP_COMMIT() asm volatile("cp.async.commit_group;" ::: "memory")
#define CP_WAIT1()  asm volatile("cp.async.wait_group 1;" ::: "memory")

__device__ __forceinline__ float gelu_f(float v) {
    return 0.5f * v * (1.f + erff(v * 0.70710678118654752f));
}

// -------------------- FP16 GEMM --------------------------------------------
// TRB=false: C[z] = A[z] @ B[z]^T, B stored [N,K].  TRB=true: B [K,N] (.trans)
// 3-level batch: z1=z/(zm2*zm3), z2=(z/zm3)%zm2, z3=z%zm3; off=z1*s1+z2*s2+z3*s3
// EPI: 0 none, 1 +bias, 2 +bias+Cf, 3 gelu(.+bias)
// OUT: 0 f32, 1 f16, 2 both, 3 qkv-split (n<512 -> Ch ld512; else Cf as f16 ld1024)
// AUX: acc snapshot diff over k-tiles [4,20) -> Cf (ldc 64, off z1*sD1+z2*sD2)
template<int BN, int EPI, int OUT, bool TRB, bool AUX>
__global__ void __launch_bounds__(256)
hm_gemm(const __half* __restrict__ A, const __half* __restrict__ B,
        float* __restrict__ Cf, __half* __restrict__ Ch,
        int K, int lda, int ldb, int ldc,
        long sA1, long sA2, long sA3, long sB1, long sB2, long sB3,
        long sC1, long sC2, long sC3, int zm2, int zm3,
        const float* __restrict__ bias, long sBias, long sD1, long sD2)
{
    constexpr int BM = 128, NST = 3;
    constexpr int BNB = BN * 2 + 16;
    constexpr int ABY = BM * 80;
    constexpr int STGB = TRB ? (ABY + 32 * BNB) : ((BM + BN) * 80);
    constexpr int WN = (BN == 128) ? 4 : 2, WM = 8 / WN;
    constexpr int WTM = BM / WM;
    constexpr int MF = WTM / 16;
    constexpr int NBn = (BN == 128) ? 2 : 1;
    constexpr int NBt = (32 * (BN / 8)) / 256;

    extern __shared__ char smc[];
    uint32_t sbase;
    asm("{ .reg .u64 t; cvta.to.shared.u64 t, %1; cvt.u32.u64 %0, t; }"
        : "=r"(sbase) : "l"(smc));

    const int z = blockIdx.z;
    const int z1 = z / (zm2 * zm3);
    const int z2 = (z / zm3) % zm2;
    const int z3 = z % zm3;
    A += z1 * sA1 + z2 * sA2 + z3 * sA3;
    B += z1 * sB1 + z2 * sB2 + z3 * sB3;
    __half* Ch2 = nullptr;
    if (OUT == 3) {
        Ch  += z1 * sC1;
        Ch2 = ((__half*)Cf) + z1 * sC3;
    } else {
        const long coff = z1 * sC1 + z2 * sC2 + z3 * sC3;
        if (OUT != 1) Cf += coff;
        if (OUT >= 1) Ch += coff;
    }
    if (AUX) Cf += z1 * sD1 + z2 * sD2;
    if (EPI >= 1) bias += z1 * sBias;
    const int m0 = blockIdx.y * BM, n0 = blockIdx.x * BN;
    const int tid = threadIdx.x, lane = tid & 31, wid = tid >> 5;
    const int wm = wid % WM, wn = wid / WM;
    const int mbase = wm * WTM, nbase = wn * 32;

    float acc[MF][4][4];
    float acc2[AUX ? MF : 1][4][4];
#pragma unroll
    for (int i = 0; i < MF; i++)
#pragma unroll
        for (int j = 0; j < 4; j++)
#pragma unroll
            for (int r = 0; r < 4; r++) acc[i][j][r] = 0.f;

    const int KT = K >> 5;

    auto issue = [&](int kt, int st) {
        const int k0 = kt << 5;
        const uint32_t s0 = sbase + st * STGB;
#pragma unroll
        for (int i = 0; i < 2; i++) {
            int idx = tid + i * 256, r = idx >> 2, c = idx & 3;
            CP16(s0 + r * 80 + c * 16, A + (long)(m0 + r) * lda + k0 + c * 8);
        }
        if (!TRB) {
#pragma unroll
            for (int i = 0; i < NBn; i++) {
                int idx = tid + i * 256, r = idx >> 2, c = idx & 3;
                CP16(s0 + ABY + r * 80 + c * 16,
                     B + (long)(n0 + r) * ldb + k0 + c * 8);
            }
        } else {
            constexpr int CH = BN / 8;
#pragma unroll
            for (int i = 0; i < NBt; i++) {
                int idx = tid + i * 256, r = idx / CH, c = idx % CH;
                CP16(s0 + ABY + r * BNB + c * 16,
                     B + (long)(k0 + r) * ldb + n0 + c * 8);
            }
        }
    };

    const int g2 = lane >> 3, t7 = lane & 7;
    const uint32_t khalf = ((g2 >> 1) << 4);
    uint32_t aoff[MF], boff[2];
#pragma unroll
    for (int mf = 0; mf < MF; mf++)
        aoff[mf] = (uint32_t)(mbase + mf * 16 + ((g2 & 1) << 3) + t7) * 80 + khalf;
    if (!TRB) {
#pragma unroll
        for (int np = 0; np < 2; np++)
            boff[np] = (uint32_t)ABY +
                       (uint32_t)(nbase + np * 16 + ((g2 & 1) << 3) + t7) * 80 + khalf;
    } else {
#pragma unroll
        for (int np = 0; np < 2; np++)
            boff[np] = (uint32_t)ABY +
                       (uint32_t)(((g2 >> 1) << 3) + t7) * BNB +
                       (uint32_t)(nbase + np * 16 + ((g2 & 1) << 3)) * 2;
    }

    auto compute = [&](int st) {
        const uint32_t s0 = sbase + st * STGB;
#pragma unroll
        for (int ks = 0; ks < 2; ks++) {
            uint32_t a[MF][4], b[2][4];
#pragma unroll
            for (int mf = 0; mf < MF; mf++)
                LDSM_X4(a[mf][0], a[mf][1], a[mf][2], a[mf][3],
                        s0 + aoff[mf] + ks * 32);
#pragma unroll
            for (int np = 0; np < 2; np++) {
                if (!TRB) {
                    LDSM_X4(b[np][0], b[np][1], b[np][2], b[np][3],
                            s0 + boff[np] + ks * 32);
                } else {
                    LDSM_X4_T(b[np][0], b[np][1], b[np][2], b[np][3],
                              s0 + boff[np] + ks * 16 * BNB);
                }
            }
#pragma unroll
            for (int mf = 0; mf < MF; mf++)
#pragma unroll
                for (int np = 0; np < 2; np++) {
                    mma_f16(acc[mf][2 * np],     a[mf][0], a[mf][1], a[mf][2], a[mf][3],
                            b[np][0], b[np][2]);
                    mma_f16(acc[mf][2 * np + 1], a[mf][0], a[mf][1], a[mf][2], a[mf][3],
                            b[np][1], b[np][3]);
                }
        }
    };

    int ldi = 0;
#pragma unroll
    for (int s = 0; s < NST - 1; s++) {
        if (ldi < KT) issue(ldi, s);
        CP_COMMIT();
        ldi++;
    }
    for (int kt = 0; kt < KT; kt++) {
        if (AUX) {
            if (kt == 4) {
#pragma unroll
                for (int i = 0; i < MF; i++)
#pragma unroll
                    for (int j = 0; j < 4; j++)
#pragma unroll
                        for (int r = 0; r < 4; r++) acc2[i][j][r] = acc[i][j][r];
            }
            if (kt == 20) {
#pragma unroll
                for (int i = 0; i < MF; i++)
#pragma unroll
                    for (int j = 0; j < 4; j++)
#pragma unroll
                        for (int r = 0; r < 4; r++)
                            acc2[i][j][r] = acc[i][j][r] - acc2[i][j][r];
            }
        }
        CP_WAIT1();
        __syncthreads();
        compute(kt % NST);
        if (ldi < KT) issue(ldi, ldi % NST);
        CP_COMMIT();
        ldi++;
    }

    // ---- epilogue ----
    const bool qside = (n0 < 512);
    const int rbase = m0 + mbase + (lane >> 2);
    const int cbase = n0 + nbase + 2 * (lane & 3);
#pragma unroll
    for (int mf = 0; mf < MF; mf++) {
#pragma unroll
        for (int nf = 0; nf < 4; nf++) {
#pragma unroll
            for (int half = 0; half < 2; half++) {
                const int m = rbase + mf * 16 + half * 8;
                const int n = cbase + nf * 8;
                float2 v = make_float2(acc[mf][nf][half * 2], acc[mf][nf][half * 2 + 1]);
                if (EPI >= 1) { v.x += bias[n]; v.y += bias[n + 1]; }
                if (OUT == 3) {
                    __half2 h2 = __floats2half2_rn(v.x, v.y);
                    if (qside) *(__half2*)(Ch  + (long)m * 512  + n)        = h2;
                    else       *(__half2*)(Ch2 + (long)m * 1024 + (n - 512)) = h2;
                } else {
                    const long idx = (long)m * ldc + n;
                    if (EPI == 2) { float2 c0 = *(const float2*)(Cf + idx); v.x += c0.x; v.y += c0.y; }
                    if (EPI == 3) { v.x = gelu_f(v.x); v.y = gelu_f(v.y); }
                    if (OUT != 1) *(float2*)(Cf + idx) = v;
                    if (OUT == 1 || OUT == 2) *(__half2*)(Ch + idx) = __floats2half2_rn(v.x, v.y);
                }
                if (AUX) {
                    float2 w = make_float2(acc2[mf][nf][half * 2], acc2[mf][nf][half * 2 + 1]);
                    *(float2*)(Cf + (long)m * 64 + n) = w;
                }
            }
        }
    }
}

// -------------------- weight transpose fp32 -> fp16 -------------------------
__global__ void tr_k(const float* __restrict__ in, __half* __restrict__ out,
                     int ldi, int ldo, long sI, long sO)
{
    __shared__ float t[32][33];
    in += blockIdx.z * sI; out += blockIdx.z * sO;
    const int n0 = blockIdx.x * 32, k0 = blockIdx.y * 32;
    const int tx = threadIdx.x, ty = threadIdx.y;
#pragma unroll
    for (int j = 0; j < 32; j += 8) t[ty + j][tx] = in[(long)(k0 + ty + j) * ldi + n0 + tx];
    __syncthreads();
#pragma unroll
    for (int j = 0; j < 32; j += 8)
        out[(long)(n0 + ty + j) * ldo + k0 + tx] = __float2half(t[tx][ty + j]);
}

__global__ void convt2_k(const float* __restrict__ w, __half* __restrict__ wt)
{
    long i = (long)blockIdx.x * 256 + threadIdx.x;
    if (i >= 4L * 1048576L) return;
    long l = i >> 20, r0 = i & 1048575L;
    int o = (int)(r0 >> 11), k = (int)(r0 & 2047);
    int r = k >> 9, c = k & 511;
    wt[i] = __float2half(w[l * 1048576L + ((long)o * 512 + c) * 4 + r]);
}

__global__ void cvt16_k(const float* __restrict__ in, __half* __restrict__ out, long n4)
{
    long i = (long)blockIdx.x * 256 + threadIdx.x;
    if (i >= n4) return;
    float4 v = ((const float4*)in)[i];
    ((__half2*)out)[2 * i]     = __floats2half2_rn(v.x, v.y);
    ((__half2*)out)[2 * i + 1] = __floats2half2_rn(v.z, v.w);
}

// -------------------- layernorm --------------------------------------------
__global__ void ln_k(const float* __restrict__ x, const float* __restrict__ g,
                     const float* __restrict__ b, float* __restrict__ out,
                     __half* __restrict__ outh)
{
    const long row = blockIdx.x;
    const float* xr = x + row * 512;
    const int tid = threadIdx.x;
    float v[4]; float s = 0.f;
#pragma unroll
    for (int j = 0; j < 4; j++) { v[j] = xr[tid + j * 128]; s += v[j]; }
    __shared__ float sh[4];
#pragma unroll
    for (int o = 16; o; o >>= 1) s += __shfl_xor_sync(0xffffffffu, s, o);
    if ((tid & 31) == 0) sh[tid >> 5] = s;
    __syncthreads();
    const float mu = (sh[0] + sh[1] + sh[2] + sh[3]) * (1.f / 512.f);
    float s2 = 0.f;
#pragma unroll
    for (int j = 0; j < 4; j++) { float d = v[j] - mu; s2 += d * d; }
    __syncthreads();
#pragma unroll
    for (int o = 16; o; o >>= 1) s2 += __shfl_xor_sync(0xffffffffu, s2, o);
    if ((tid & 31) == 0) sh[tid >> 5] = s2;
    __syncthreads();
    const float rs = rsqrtf((sh[0] + sh[1] + sh[2] + sh[3]) * (1.f / 512.f) + 1e-5f);
#pragma unroll
    for (int j = 0; j < 4; j++) {
        int d = tid + j * 128;
        float val = (v[j] - mu) * rs * g[d] + b[d];
        if (out)  out[row * 512 + d] = val;
        outh[row * 512 + d] = __float2half(val);
    }
}

// -------------------- softmax: fp16 in place; optional sub-mass -------------
template<int L, bool SUB>
__global__ void softmax_k(__half* __restrict__ P, float scale,
                          float* __restrict__ subsum)
{
    const long row = blockIdx.x;
    __half* pr = P + row * (long)L;
    const int tid = threadIdx.x;
    constexpr int NIT = (L + 255) >> 8;
    float v[NIT]; float mx = -3.0e38f;
#pragma unroll
    for (int j = 0; j < NIT; j++) {
        int i = tid + (j << 8);
        float t = (i < L) ? __half2float(pr[i]) * scale : -3.0e38f;
        v[j] = t; mx = fmaxf(mx, t);
    }
    __shared__ float sh[8];
#pragma unroll
    for (int o = 16; o; o >>= 1) mx = fmaxf(mx, __shfl_xor_sync(0xffffffffu, mx, o));
    if ((tid & 31) == 0) sh[tid >> 5] = mx;
    __syncthreads();
    float bm = sh[0];
#pragma unroll
    for (int w = 1; w < 8; w++) bm = fmaxf(bm, sh[w]);
    float s = 0.f, ssub = 0.f;
#pragma unroll
    for (int j = 0; j < NIT; j++) {
        int i = tid + (j << 8);
        if (i < L) {
            float e = __expf(v[j] - bm); v[j] = e; s += e;
            if (SUB && i >= 128 && i < 640) ssub += e;
        }
    }
    __syncthreads();
#pragma unroll
    for (int o = 16; o; o >>= 1) s += __shfl_xor_sync(0xffffffffu, s, o);
    if ((tid & 31) == 0) sh[tid >> 5] = s;
    __syncthreads();
    float tot = 0.f;
#pragma unroll
    for (int w = 0; w < 8; w++) tot += sh[w];
    const float inv = 1.f / tot;
    if (SUB) {
        __syncthreads();
#pragma unroll
        for (int o = 16; o; o >>= 1) ssub += __shfl_xor_sync(0xffffffffu, ssub, o);
        if ((tid & 31) == 0) sh[tid >> 5] = ssub;
        __syncthreads();
        if (tid == 0) {
            float st = 0.f;
#pragma unroll
            for (int w = 0; w < 8; w++) st += sh[w];
            subsum[row] = st * inv;
        }
    }
#pragma unroll
    for (int j = 0; j < NIT; j++) {
        int i = tid + (j << 8);
        if (i < L) pr[i] = __float2half(v[j] * inv);
    }
}

// -------------------- embed / mse / attnsum / init / final ------------------
__global__ void embed_k(const int* __restrict__ seq, const float* __restrict__ emb,
                        float* __restrict__ x)
{
    long i = (long)blockIdx.x * blockDim.x + threadIdx.x;
    if (i >= 2097152L) return;
    int d = (int)(i & 511);
    long bt = i >> 9;
    int t = (int)(bt & 511);
    int tok = seq[bt];
    int j2 = d & ~1;
    float ang = (float)t * expf(-0.017988946039015984f * (float)j2);
    float pe = (d & 1) ? cosf(ang) : sinf(ang);
    x[i] = emb[(long)tok * 512 + d] + pe;
}

__global__ void mse_k(const float* __restrict__ a, const float* __restrict__ b,
                      const float* __restrict__ S, float* __restrict__ outScalar, long n)
{
    long i0 = (long)blockIdx.x * blockDim.x + threadIdx.x;
    long stride = (long)gridDim.x * blockDim.x;
    float s = 0.f;
    for (long i = i0; i < n; i += stride) {
        float d = a[i] / S[i >> 6] - b[i];
        s += d * d;
    }
    __shared__ float sh[8];
#pragma unroll
    for (int o = 16; o; o >>= 1) s += __shfl_xor_sync(0xffffffffu, s, o);
    int tid = threadIdx.x;
    if ((tid & 31) == 0) sh[tid >> 5] = s;
    __syncthreads();
    if (tid == 0) {
        float tot = 0.f;
#pragma unroll
        for (int w = 0; w < 8; w++) tot += sh[w];
        atomicAdd(outScalar, tot);
    }
}

__global__ void attnsum_k(const __half* __restrict__ dotsH, float* __restrict__ out)
{
    long i = (long)blockIdx.x * 256 + threadIdx.x;
    if (i >= 294912L) return;
    const __half2* p = (const __half2*)dotsH + i;
    float sx = 0.f, sy = 0.f;
#pragma unroll 8
    for (int sl = 0; sl < 256; sl++) {
        float2 f = __half22float2(p[(long)sl * 294912L]);
        sx += f.x; sy += f.y;
    }
    *(float2*)(out + OFF_ATTN + 2 * i) = make_float2(sx * (1.f / 256.f), sy * (1.f / 256.f));
}

__global__ void init_k(float* __restrict__ out)
{
    if (threadIdx.x == 0) { out[OFF_AUX] = 0.f; out[OFF_ZERO] = 0.f; }
}
__global__ void final_k(float* __restrict__ out)
{
    if (threadIdx.x == 0) out[OFF_AUX] *= (1.f / (4.f * 2097152.f));
}

// ---------------------------------------------------------------------------
extern "C" void kernel_launch(void* const* d_in, const int* in_sizes, int n_in,
                              void* d_out, int out_size)
{
    const int*   seq   = (const int*)  d_in[0];
    const float* mems  = (const float*)d_in[2];
    const float* cmems = (const float*)d_in[3];
    const float* emb   = (const float*)d_in[4];
    const float* ln1g  = (const float*)d_in[5];
    const float* ln1b  = (const float*)d_in[6];
    const float* Wq    = (const float*)d_in[7];
    const float* Wkv   = (const float*)d_in[8];
    const float* Wo    = (const float*)d_in[9];
    const float* bo    = (const float*)d_in[10];
    const float* convw = (const float*)d_in[11];
    const float* convb = (const float*)d_in[12];
    const float* ln2g  = (const float*)d_in[13];
    const float* ln2b  = (const float*)d_in[14];
    const float* W1    = (const float*)d_in[15];
    const float* b1    = (const float*)d_in[16];
    const float* W2    = (const float*)d_in[17];
    const float* b2    = (const float*)d_in[18];
    float* out = (float*)d_out;

    __half *hmems, *hcmems, *hxn, *hxn2, *qh, *kvh, *ckvh, *dotsH, *dots2H;
    __half *attnoh, *ffhh, *cmh;
    __half *wqkvTh, *WoTh, *cwh, *W1Th, *W2Th;
    float *o1, *o2, *Ssub;
    cudaGetSymbolAddress((void**)&hmems, g_hmems);   cudaGetSymbolAddress((void**)&hcmems, g_hcmems);
    cudaGetSymbolAddress((void**)&hxn, g_hxn);       cudaGetSymbolAddress((void**)&hxn2, g_hxn2);
    cudaGetSymbolAddress((void**)&qh, g_qh);         cudaGetSymbolAddress((void**)&kvh, g_kvh);
    cudaGetSymbolAddress((void**)&ckvh, g_ckvh);     cudaGetSymbolAddress((void**)&dotsH, g_dotsH);
    cudaGetSymbolAddress((void**)&dots2H, g_dots2H); cudaGetSymbolAddress((void**)&attnoh, g_attnoh);
    cudaGetSymbolAddress((void**)&ffhh, g_ffhh);     cudaGetSymbolAddress((void**)&cmh, g_cmh);
    cudaGetSymbolAddress((void**)&wqkvTh, g_wqkvTh); cudaGetSymbolAddress((void**)&WoTh, g_WoTh);
    cudaGetSymbolAddress((void**)&cwh, g_cwh);       cudaGetSymbolAddress((void**)&W1Th, g_W1Th);
    cudaGetSymbolAddress((void**)&W2Th, g_W2Th);
    cudaGetSymbolAddress((void**)&o1, g_o1);         cudaGetSymbolAddress((void**)&o2, g_o2);
    cudaGetSymbolAddress((void**)&Ssub, g_S);

    const int SM128  = 3 * (128 + 128) * 80;               // 61440
    const int SM64T  = 3 * (128 * 80 + 32 * 144);          // 44544
    cudaFuncSetAttribute(hm_gemm<128,0,1,false,false>, cudaFuncAttributeMaxDynamicSharedMemorySize, SM128);
    cudaFuncSetAttribute(hm_gemm<128,1,2,false,false>, cudaFuncAttributeMaxDynamicSharedMemorySize, SM128);
    cudaFuncSetAttribute(hm_gemm<128,2,0,false,false>, cudaFuncAttributeMaxDynamicSharedMemorySize, SM128);
    cudaFuncSetAttribute(hm_gemm<128,3,1,false,false>, cudaFuncAttributeMaxDynamicSharedMemorySize, SM128);
    cudaFuncSetAttribute(hm_gemm<128,0,3,false,false>, cudaFuncAttributeMaxDynamicSharedMemorySize, SM128);
    cudaFuncSetAttribute(hm_gemm<64,0,1,true,true>,    cudaFuncAttributeMaxDynamicSharedMemorySize, SM64T);
    cudaFuncSetAttribute(hm_gemm<64,0,0,true,false>,   cudaFuncAttributeMaxDynamicSharedMemorySize, SM64T);

    float* x   = out;
    float* aux = out + OFF_AUX;

    init_k <<<1, 32>>>(out);
    embed_k<<<8192, 256>>>(seq, emb, x);

    // ---- one-time conversions ----
    dim3 tb(32, 8);
    tr_k<<<dim3(16,16,4), tb>>>(Wq,  wqkvTh,          512,  512, 262144, 786432);
    tr_k<<<dim3(32,16,4), tb>>>(Wkv, wqkvTh + 262144, 1024, 512, 524288, 786432);
    tr_k<<<dim3(16,16,4), tb>>>(Wo,  WoTh,  512,  512,  262144, 262144);
    tr_k<<<dim3(64,16,4), tb>>>(W1,  W1Th,  2048, 512,  1048576, 1048576);
    tr_k<<<dim3(16,64,4), tb>>>(W2,  W2Th,  512,  2048, 1048576, 1048576);
    convt2_k<<<16384, 256>>>(convw, cwh);
    cvt16_k<<<8192, 256>>>(mems,  hmems,  2097152L);
    cvt16_k<<<2048, 256>>>(cmems, hcmems, 524288L);

    const __half* WkvTh = wqkvTh + 262144;

    // ---- hoisted layer-input GEMMs (all 4 layers, z = l*8+b) ----
    hm_gemm<128,0,1,false,false><<<dim3(8,1,32),256,SM128>>>(hcmems, WkvTh, nullptr, kvh,
        512, 512,512,1024, 524288,65536,0, 786432,0,0, 9437184,1179648,0, 8,1, nullptr,0,0,0);
    hm_gemm<128,0,1,false,false><<<dim3(8,4,32),256,SM128>>>(hmems, WkvTh, nullptr, kvh + 131072,
        512, 512,512,1024, 2097152,262144,0, 786432,0,0, 9437184,1179648,0, 8,1, nullptr,0,0,0);
    hm_gemm<128,1,2,false,false><<<dim3(4,8,4),256,SM128>>>(hmems, cwh, out + OFF_CMEMS, cmh,
        2048, 2048,2048,512, 2097152,0,0, 1048576,0,0, 524288,0,0, 1,1, convb,512,0,0);
    hm_gemm<128,0,1,false,false><<<dim3(8,1,32),256,SM128>>>(cmh, WkvTh, nullptr, ckvh,
        512, 512,512,1024, 524288,65536,0, 786432,0,0, 1048576,131072,0, 8,1, nullptr,0,0,0);

    for (int i = 0; i < 4; i++) {
        const __half* wqkvTh_i = wqkvTh + (long)i * 786432;
        const __half* WoTh_i   = WoTh   + (long)i * 262144;
        const __half* W1Th_i   = W1Th   + (long)i * 1048576;
        const __half* W2Th_i   = W2Th   + (long)i * 1048576;
        __half* qh_l    = qh    + (long)i * 2097152;
        __half* kvh_l   = kvh   + (long)i * 9437184;
        __half* dotsH_l = dotsH + (long)i * 37748736;
        float*  o1_l    = o1    + (long)i * 2097152;
        float*  Ssub_l  = Ssub  + (long)i * 32768;
        float*  xn = out + OFF_MEMS + (long)i * 2097152;

        ln_k<<<4096, 128>>>(x, ln1g + i * 512, ln1b + i * 512, xn, hxn);

        // fused q|kv(xn) projection
        hm_gemm<128,0,3,false,false><<<dim3(12,4,8),256,SM128>>>(hxn, wqkvTh_i,
            (float*)(kvh_l + 655360), qh_l,
            512, 512,512,512, 262144,0,0, 0,0,0, 262144,0,1179648, 1,1, nullptr,0,0,0);

        // logits = q @ k^T -> fp16
        hm_gemm<128,0,1,false,false><<<dim3(9,4,64),256,SM128>>>(qh_l, kvh_l, nullptr, dotsH_l,
            64, 512,1024,1152, 262144,64,0, 1179648,64,0, 4718592,589824,0, 8,1, nullptr,0,0,0);

        softmax_k<1152,true><<<32768,256>>>(dotsH_l, 0.125f, Ssub_l);

        // attno = P @ v (TRB), fused aux-o1 (snapshot diff over K [128,640))
        hm_gemm<64,0,1,true,true><<<dim3(1,4,64),256,SM64T>>>(dotsH_l, kvh_l + 512, o1_l, attnoh,
            1152, 1152,1024,512, 4718592,589824,0, 1179648,64,0, 262144,64,0, 8,1,
            nullptr,0, 262144,32768);

        // x = attno @ Wo + bo + x
        hm_gemm<128,2,0,false,false><<<dim3(4,32,1),256,SM128>>>(attnoh, WoTh_i, x, nullptr,
            512, 512,512,512, 0,0,0, 0,0,0, 0,0,0, 1,1, bo + i * 512, 0,0,0);

        // FFN
        ln_k<<<4096,128>>>(x, ln2g + i * 512, ln2b + i * 512, nullptr, hxn2);
        hm_gemm<128,3,1,false,false><<<dim3(16,32,1),256,SM128>>>(hxn2, W1Th_i, nullptr, ffhh,
            512, 512,512,2048, 0,0,0, 0,0,0, 0,0,0, 1,1, b1 + i * 2048, 0,0,0);
        hm_gemm<128,2,0,false,false><<<dim3(4,32,1),256,SM128>>>(ffhh, W2Th_i, x, nullptr,
            2048, 2048,2048,512, 0,0,0, 0,0,0, 0,0,0, 1,1, b2 + i * 512, 0,0,0);
    }

    // ---- deferred aux-cmem chain, batched over all layers ----
    hm_gemm<128,0,1,false,false><<<dim3(1,4,256),256,SM128>>>(qh, ckvh, nullptr, dots2H,
        64, 512,1024,128, 2097152,262144,64, 1048576,131072,64,
        4194304,524288,65536, 8,8, nullptr,0,0,0);
    softmax_k<128,false><<<131072,256>>>(dots2H, 0.125f, nullptr);
    hm_gemm<64,0,0,true,false><<<dim3(1,4,256),256,SM64T>>>(dots2H, ckvh + 512, o2, nullptr,
        128, 128,1024,64, 4194304,524288,65536, 1048576,131072,64,
        2097152,262144,32768, 8,8, nullptr,0,0,0);
    mse_k<<<2048,256>>>(o1, o2, Ssub, aux, 8388608L);

    attnsum_k<<<1152,256>>>(dotsH, out);
    final_k<<<1,32>>>(out);
}

// round 14
// speedup vs baseline: 7.2752x; 1.1207x over previous
#include <cuda_runtime.h>
#include <cuda_fp16.h>
#include <cstdint>
#include <math.h>

// ---------------------------------------------------------------------------
// CompressiveEncoder forward. FP16 mma.sync + ldmatrix(.trans) + cp.async.
// Vectorized softmax/attnsum; PV fuses aux-o1 via accumulator snapshot.
// Output: x | new_mems | new_cmems | aux | 0 | attns_mean  (fp32)
// ---------------------------------------------------------------------------

#define OFF_MEMS   2097152L
#define OFF_CMEMS 10485760L
#define OFF_AUX   12582912L
#define OFF_ZERO  12582913L
#define OFF_ATTN  12582914L
#define ATTN_ELEMS 589824L

// -------------------- device scratch ---------------------------------------
__device__ __half g_hmems [8388608];
__device__ __half g_hcmems[2097152];
__device__ __half g_hxn   [2097152];
__device__ __half g_hxn2  [2097152];
__device__ __half g_qh    [8388608];
__device__ __half g_kvh   [37748736];
__device__ __half g_ckvh  [4194304];
__device__ __half g_dotsH [150994944];
__device__ __half g_dots2H[16777216];
__device__ __half g_attnoh[2097152];
__device__ __half g_ffhh  [8388608];
__device__ __half g_cmh   [2097152];
__device__ __half g_wqkvTh[3145728];
__device__ __half g_WoTh  [1048576];
__device__ __half g_cwh   [4194304];
__device__ __half g_W1Th  [4194304];
__device__ __half g_W2Th  [4194304];
__device__ float g_o1 [8388608];
__device__ float g_o2 [8388608];
__device__ float g_S  [131072];

// -------------------- helpers ----------------------------------------------
__device__ __forceinline__ void mma_f16(float* d, uint32_t a0, uint32_t a1,
                                        uint32_t a2, uint32_t a3,
                                        uint32_t b0, uint32_t b1) {
    asm volatile("mma.sync.aligned.m16n8k16.row.col.f32.f16.f16.f32 "
                 "{%0,%1,%2,%3}, {%4,%5,%6,%7}, {%8,%9}, {%0,%1,%2,%3};"
                 : "+f"(d[0]), "+f"(d[1]), "+f"(d[2]), "+f"(d[3])
                 : "r"(a0), "r"(a1), "r"(a2), "r"(a3), "r"(b0), "r"(b1));
}
#define LDSM_X4(r0, r1, r2, r3, addr) \
    asm volatile("ldmatrix.sync.aligned.m8n8.x4.shared.b16 {%0,%1,%2,%3}, [%4];" \
                 : "=r"(r0), "=r"(r1), "=r"(r2), "=r"(r3) : "r"(addr))
#define LDSM_X4_T(r0, r1, r2, r3, addr) \
    asm volatile("ldmatrix.sync.aligned.m8n8.x4.trans.shared.b16 {%0,%1,%2,%3}, [%4];" \
                 : "=r"(r0), "=r"(r1), "=r"(r2), "=r"(r3) : "r"(addr))
#define CP16(saddr, gaddr) \
    asm volatile("cp.async.cg.shared.global [%0], [%1], 16;" :: "r"(saddr), "l"(gaddr))
#define CP_COMMIT() asm volatile("cp.async.commit_group;" ::: "memory")
#define CP_WAIT1()  asm volatile("cp.async.wait_group 1;" ::: "memory")

__device__ __forceinline__ float gelu_f(float v) {
    return 0.5f * v * (1.f + erff(v * 0.70710678118654752f));
}

// -------------------- FP16 GEMM (unchanged from R13) ------------------------
template<int BN, int EPI, int OUT, bool TRB, bool AUX>
__global__ void __launch_bounds__(256)
hm_gemm(const __half* __restrict__ A, const __half* __restrict__ B,
        float* __restrict__ Cf, __half* __restrict__ Ch,
        int K, int lda, int ldb, int ldc,
        long sA1, long sA2, long sA3, long sB1, long sB2, long sB3,
        long sC1, long sC2, long sC3, int zm2, int zm3,
        const float* __restrict__ bias, long sBias, long sD1, long sD2)
{
    constexpr int BM = 128, NST = 3;
    constexpr int BNB = BN * 2 + 16;
    constexpr int ABY = BM * 80;
    constexpr int STGB = TRB ? (ABY + 32 * BNB) : ((BM + BN) * 80);
    constexpr int WN = (BN == 128) ? 4 : 2, WM = 8 / WN;
    constexpr int WTM = BM / WM;
    constexpr int MF = WTM / 16;
    constexpr int NBn = (BN == 128) ? 2 : 1;
    constexpr int NBt = (32 * (BN / 8)) / 256;

    extern __shared__ char smc[];
    uint32_t sbase;
    asm("{ .reg .u64 t; cvta.to.shared.u64 t, %1; cvt.u32.u64 %0, t; }"
        : "=r"(sbase) : "l"(smc));

    const int z = blockIdx.z;
    const int z1 = z / (zm2 * zm3);
    const int z2 = (z / zm3) % zm2;
    const int z3 = z % zm3;
    A += z1 * sA1 + z2 * sA2 + z3 * sA3;
    B += z1 * sB1 + z2 * sB2 + z3 * sB3;
    __half* Ch2 = nullptr;
    if (OUT == 3) {
        Ch  += z1 * sC1;
        Ch2 = ((__half*)Cf) + z1 * sC3;
    } else {
        const long coff = z1 * sC1 + z2 * sC2 + z3 * sC3;
        if (OUT != 1) Cf += coff;
        if (OUT >= 1) Ch += coff;
    }
    if (AUX) Cf += z1 * sD1 + z2 * sD2;
    if (EPI >= 1) bias += z1 * sBias;
    const int m0 = blockIdx.y * BM, n0 = blockIdx.x * BN;
    const int tid = threadIdx.x, lane = tid & 31, wid = tid >> 5;
    const int wm = wid % WM, wn = wid / WM;
    const int mbase = wm * WTM, nbase = wn * 32;

    float acc[MF][4][4];
    float acc2[AUX ? MF : 1][4][4];
#pragma unroll
    for (int i = 0; i < MF; i++)
#pragma unroll
        for (int j = 0; j < 4; j++)
#pragma unroll
            for (int r = 0; r < 4; r++) acc[i][j][r] = 0.f;

    const int KT = K >> 5;

    auto issue = [&](int kt, int st) {
        const int k0 = kt << 5;
        const uint32_t s0 = sbase + st * STGB;
#pragma unroll
        for (int i = 0; i < 2; i++) {
            int idx = tid + i * 256, r = idx >> 2, c = idx & 3;
            CP16(s0 + r * 80 + c * 16, A + (long)(m0 + r) * lda + k0 + c * 8);
        }
        if (!TRB) {
#pragma unroll
            for (int i = 0; i < NBn; i++) {
                int idx = tid + i * 256, r = idx >> 2, c = idx & 3;
                CP16(s0 + ABY + r * 80 + c * 16,
                     B + (long)(n0 + r) * ldb + k0 + c * 8);
            }
        } else {
            constexpr int CH = BN / 8;
#pragma unroll
            for (int i = 0; i < NBt; i++) {
                int idx = tid + i * 256, r = idx / CH, c = idx % CH;
                CP16(s0 + ABY + r * BNB + c * 16,
                     B + (long)(k0 + r) * ldb + n0 + c * 8);
            }
        }
    };

    const int g2 = lane >> 3, t7 = lane & 7;
    const uint32_t khalf = ((g2 >> 1) << 4);
    uint32_t aoff[MF], boff[2];
#pragma unroll
    for (int mf = 0; mf < MF; mf++)
        aoff[mf] = (uint32_t)(mbase + mf * 16 + ((g2 & 1) << 3) + t7) * 80 + khalf;
    if (!TRB) {
#pragma unroll
        for (int np = 0; np < 2; np++)
            boff[np] = (uint32_t)ABY +
                       (uint32_t)(nbase + np * 16 + ((g2 & 1) << 3) + t7) * 80 + khalf;
    } else {
#pragma unroll
        for (int np = 0; np < 2; np++)
            boff[np] = (uint32_t)ABY +
                       (uint32_t)(((g2 >> 1) << 3) + t7) * BNB +
                       (uint32_t)(nbase + np * 16 + ((g2 & 1) << 3)) * 2;
    }

    auto compute = [&](int st) {
        const uint32_t s0 = sbase + st * STGB;
#pragma unroll
        for (int ks = 0; ks < 2; ks++) {
            uint32_t a[MF][4], b[2][4];
#pragma unroll
            for (int mf = 0; mf < MF; mf++)
                LDSM_X4(a[mf][0], a[mf][1], a[mf][2], a[mf][3],
                        s0 + aoff[mf] + ks * 32);
#pragma unroll
            for (int np = 0; np < 2; np++) {
                if (!TRB) {
                    LDSM_X4(b[np][0], b[np][1], b[np][2], b[np][3],
                            s0 + boff[np] + ks * 32);
                } else {
                    LDSM_X4_T(b[np][0], b[np][1], b[np][2], b[np][3],
                              s0 + boff[np] + ks * 16 * BNB);
                }
            }
#pragma unroll
            for (int mf = 0; mf < MF; mf++)
#pragma unroll
                for (int np = 0; np < 2; np++) {
                    mma_f16(acc[mf][2 * np],     a[mf][0], a[mf][1], a[mf][2], a[mf][3],
                            b[np][0], b[np][2]);
                    mma_f16(acc[mf][2 * np + 1], a[mf][0], a[mf][1], a[mf][2], a[mf][3],
                            b[np][1], b[np][3]);
                }
        }
    };

    int ldi = 0;
#pragma unroll
    for (int s = 0; s < NST - 1; s++) {
        if (ldi < KT) issue(ldi, s);
        CP_COMMIT();
        ldi++;
    }
    for (int kt = 0; kt < KT; kt++) {
        if (AUX) {
            if (kt == 4) {
#pragma unroll
                for (int i = 0; i < MF; i++)
#pragma unroll
                    for (int j = 0; j < 4; j++)
#pragma unroll
                        for (int r = 0; r < 4; r++) acc2[i][j][r] = acc[i][j][r];
            }
            if (kt == 20) {
#pragma unroll
                for (int i = 0; i < MF; i++)
#pragma unroll
                    for (int j = 0; j < 4; j++)
#pragma unroll
                        for (int r = 0; r < 4; r++)
                            acc2[i][j][r] = acc[i][j][r] - acc2[i][j][r];
            }
        }
        CP_WAIT1();
        __syncthreads();
        compute(kt % NST);
        if (ldi < KT) issue(ldi, ldi % NST);
        CP_COMMIT();
        ldi++;
    }

    const bool qside = (n0 < 512);
    const int rbase = m0 + mbase + (lane >> 2);
    const int cbase = n0 + nbase + 2 * (lane & 3);
#pragma unroll
    for (int mf = 0; mf < MF; mf++) {
#pragma unroll
        for (int nf = 0; nf < 4; nf++) {
#pragma unroll
            for (int half = 0; half < 2; half++) {
                const int m = rbase + mf * 16 + half * 8;
                const int n = cbase + nf * 8;
                float2 v = make_float2(acc[mf][nf][half * 2], acc[mf][nf][half * 2 + 1]);
                if (EPI >= 1) { v.x += bias[n]; v.y += bias[n + 1]; }
                if (OUT == 3) {
                    __half2 h2 = __floats2half2_rn(v.x, v.y);
                    if (qside) *(__half2*)(Ch  + (long)m * 512  + n)        = h2;
                    else       *(__half2*)(Ch2 + (long)m * 1024 + (n - 512)) = h2;
                } else {
                    const long idx = (long)m * ldc + n;
                    if (EPI == 2) { float2 c0 = *(const float2*)(Cf + idx); v.x += c0.x; v.y += c0.y; }
                    if (EPI == 3) { v.x = gelu_f(v.x); v.y = gelu_f(v.y); }
                    if (OUT != 1) *(float2*)(Cf + idx) = v;
                    if (OUT == 1 || OUT == 2) *(__half2*)(Ch + idx) = __floats2half2_rn(v.x, v.y);
                }
                if (AUX) {
                    float2 w = make_float2(acc2[mf][nf][half * 2], acc2[mf][nf][half * 2 + 1]);
                    *(float2*)(Cf + (long)m * 64 + n) = w;
                }
            }
        }
    }
}

// -------------------- weight transpose fp32 -> fp16 -------------------------
__global__ void tr_k(const float* __restrict__ in, __half* __restrict__ out,
                     int ldi, int ldo, long sI, long sO)
{
    __shared__ float t[32][33];
    in += blockIdx.z * sI; out += blockIdx.z * sO;
    const int n0 = blockIdx.x * 32, k0 = blockIdx.y * 32;
    const int tx = threadIdx.x, ty = threadIdx.y;
#pragma unroll
    for (int j = 0; j < 32; j += 8) t[ty + j][tx] = in[(long)(k0 + ty + j) * ldi + n0 + tx];
    __syncthreads();
#pragma unroll
    for (int j = 0; j < 32; j += 8)
        out[(long)(n0 + ty + j) * ldo + k0 + tx] = __float2half(t[tx][ty + j]);
}

__global__ void convt2_k(const float* __restrict__ w, __half* __restrict__ wt)
{
    long i = (long)blockIdx.x * 256 + threadIdx.x;
    if (i >= 4L * 1048576L) return;
    long l = i >> 20, r0 = i & 1048575L;
    int o = (int)(r0 >> 11), k = (int)(r0 & 2047);
    int r = k >> 9, c = k & 511;
    wt[i] = __float2half(w[l * 1048576L + ((long)o * 512 + c) * 4 + r]);
}

__global__ void cvt16_k(const float* __restrict__ in, __half* __restrict__ out, long n4)
{
    long i = (long)blockIdx.x * 256 + threadIdx.x;
    if (i >= n4) return;
    float4 v = ((const float4*)in)[i];
    ((__half2*)out)[2 * i]     = __floats2half2_rn(v.x, v.y);
    ((__half2*)out)[2 * i + 1] = __floats2half2_rn(v.z, v.w);
}

// -------------------- layernorm --------------------------------------------
__global__ void ln_k(const float* __restrict__ x, const float* __restrict__ g,
                     const float* __restrict__ b, float* __restrict__ out,
                     __half* __restrict__ outh)
{
    const long row = blockIdx.x;
    const float* xr = x + row * 512;
    const int tid = threadIdx.x;
    float v[4]; float s = 0.f;
#pragma unroll
    for (int j = 0; j < 4; j++) { v[j] = xr[tid + j * 128]; s += v[j]; }
    __shared__ float sh[4];
#pragma unroll
    for (int o = 16; o; o >>= 1) s += __shfl_xor_sync(0xffffffffu, s, o);
    if ((tid & 31) == 0) sh[tid >> 5] = s;
    __syncthreads();
    const float mu = (sh[0] + sh[1] + sh[2] + sh[3]) * (1.f / 512.f);
    float s2 = 0.f;
#pragma unroll
    for (int j = 0; j < 4; j++) { float d = v[j] - mu; s2 += d * d; }
    __syncthreads();
#pragma unroll
    for (int o = 16; o; o >>= 1) s2 += __shfl_xor_sync(0xffffffffu, s2, o);
    if ((tid & 31) == 0) sh[tid >> 5] = s2;
    __syncthreads();
    const float rs = rsqrtf((sh[0] + sh[1] + sh[2] + sh[3]) * (1.f / 512.f) + 1e-5f);
#pragma unroll
    for (int j = 0; j < 4; j++) {
        int d = tid + j * 128;
        float val = (v[j] - mu) * rs * g[d] + b[d];
        if (out)  out[row * 512 + d] = val;
        outh[row * 512 + d] = __float2half(val);
    }
}

// -------------------- vectorized softmax L=1152 (128 thr/row) ---------------
// thread t: uint4 (halves 8t..8t+7); threads 0-63 also tail half2 (1024+2t).
// sub-range [128,640) == full uint4 of threads 16..79.
__global__ void __launch_bounds__(128)
softmax1152_k(__half* __restrict__ P, float scale, float* __restrict__ subsum)
{
    const long row = blockIdx.x;
    __half* pr = P + row * 1152L;
    const int tid = threadIdx.x, lane = tid & 31, wid = tid >> 5;
    const bool tail = tid < 64;

    uint4 u = ((const uint4*)pr)[tid];
    __half2* hp = (__half2*)&u;
    float v[10];
#pragma unroll
    for (int j = 0; j < 4; j++) {
        float2 f = __half22float2(hp[j]);
        v[2 * j] = f.x * scale; v[2 * j + 1] = f.y * scale;
    }
    v[8] = v[9] = -3.0e38f;
    if (tail) {
        float2 f = __half22float2(((const __half2*)pr)[512 + tid]);
        v[8] = f.x * scale; v[9] = f.y * scale;
    }

    float mx = v[0];
#pragma unroll
    for (int j = 1; j < 10; j++) mx = fmaxf(mx, v[j]);
    __shared__ float sh[4];
#pragma unroll
    for (int o = 16; o; o >>= 1) mx = fmaxf(mx, __shfl_xor_sync(0xffffffffu, mx, o));
    if (lane == 0) sh[wid] = mx;
    __syncthreads();
    const float bm = fmaxf(fmaxf(sh[0], sh[1]), fmaxf(sh[2], sh[3]));

    float s = 0.f;
#pragma unroll
    for (int j = 0; j < 10; j++) { float e = __expf(v[j] - bm); v[j] = e; s += e; }
    float ssub = 0.f;
    if (tid >= 16 && tid < 80) {
#pragma unroll
        for (int j = 0; j < 8; j++) ssub += v[j];
    }
    __syncthreads();
#pragma unroll
    for (int o = 16; o; o >>= 1) s += __shfl_xor_sync(0xffffffffu, s, o);
    if (lane == 0) sh[wid] = s;
    __syncthreads();
    const float tot = sh[0] + sh[1] + sh[2] + sh[3];
    const float inv = 1.f / tot;

    __syncthreads();
#pragma unroll
    for (int o = 16; o; o >>= 1) ssub += __shfl_xor_sync(0xffffffffu, ssub, o);
    if (lane == 0) sh[wid] = ssub;
    __syncthreads();
    if (tid == 0 && subsum)
        subsum[row] = (sh[0] + sh[1] + sh[2] + sh[3]) * inv;

#pragma unroll
    for (int j = 0; j < 4; j++)
        hp[j] = __floats2half2_rn(v[2 * j] * inv, v[2 * j + 1] * inv);
    ((uint4*)pr)[tid] = u;
    if (tail)
        ((__half2*)pr)[512 + tid] = __floats2half2_rn(v[8] * inv, v[9] * inv);
}

// -------------------- warp-per-row softmax L=128 ----------------------------
__global__ void __launch_bounds__(256)
softmax128w_k(__half* __restrict__ P, float scale)
{
    const long row = (long)blockIdx.x * 8 + (threadIdx.x >> 5);
    const int lane = threadIdx.x & 31;
    __half* pr = P + row * 128L;
    uint2 u = ((const uint2*)pr)[lane];
    __half2* hp = (__half2*)&u;
    float2 f0 = __half22float2(hp[0]), f1 = __half22float2(hp[1]);
    float v0 = f0.x * scale, v1 = f0.y * scale, v2 = f1.x * scale, v3 = f1.y * scale;
    float mx = fmaxf(fmaxf(v0, v1), fmaxf(v2, v3));
#pragma unroll
    for (int o = 16; o; o >>= 1) mx = fmaxf(mx, __shfl_xor_sync(0xffffffffu, mx, o));
    float e0 = __expf(v0 - mx), e1 = __expf(v1 - mx);
    float e2 = __expf(v2 - mx), e3 = __expf(v3 - mx);
    float s = e0 + e1 + e2 + e3;
#pragma unroll
    for (int o = 16; o; o >>= 1) s += __shfl_xor_sync(0xffffffffu, s, o);
    const float inv = 1.f / s;
    hp[0] = __floats2half2_rn(e0 * inv, e1 * inv);
    hp[1] = __floats2half2_rn(e2 * inv, e3 * inv);
    ((uint2*)pr)[lane] = u;
}

// -------------------- embed / mse / attnsum / init / final ------------------
__global__ void embed_k(const int* __restrict__ seq, const float* __restrict__ emb,
                        float* __restrict__ x)
{
    long i = (long)blockIdx.x * blockDim.x + threadIdx.x;
    if (i >= 2097152L) return;
    int d = (int)(i & 511);
    long bt = i >> 9;
    int t = (int)(bt & 511);
    int tok = seq[bt];
    int j2 = d & ~1;
    float ang = (float)t * expf(-0.017988946039015984f * (float)j2);
    float pe = (d & 1) ? cosf(ang) : sinf(ang);
    x[i] = emb[(long)tok * 512 + d] + pe;
}

__global__ void mse_k(const float* __restrict__ a, const float* __restrict__ b,
                      const float* __restrict__ S, float* __restrict__ outScalar, long n)
{
    long i0 = (long)blockIdx.x * blockDim.x + threadIdx.x;
    long stride = (long)gridDim.x * blockDim.x;
    float s = 0.f;
    for (long i = i0; i < n; i += stride) {
        float d = a[i] / S[i >> 6] - b[i];
        s += d * d;
    }
    __shared__ float sh[8];
#pragma unroll
    for (int o = 16; o; o >>= 1) s += __shfl_xor_sync(0xffffffffu, s, o);
    int tid = threadIdx.x;
    if ((tid & 31) == 0) sh[tid >> 5] = s;
    __syncthreads();
    if (tid == 0) {
        float tot = 0.f;
#pragma unroll
        for (int w = 0; w < 8; w++) tot += sh[w];
        atomicAdd(outScalar, tot);
    }
}

// attns_mean: uint4 (8 halves) per thread, 256 slices
__global__ void attnsum_k(const __half* __restrict__ dotsH, float* __restrict__ out)
{
    long i = (long)blockIdx.x * 256 + threadIdx.x;   // uint4 index, 73728 total
    if (i >= 73728L) return;
    const uint4* p = (const uint4*)dotsH + i;
    float s[8];
#pragma unroll
    for (int j = 0; j < 8; j++) s[j] = 0.f;
#pragma unroll 4
    for (int sl = 0; sl < 256; sl++) {
        uint4 u = p[(long)sl * 73728L];
        const __half2* hp = (const __half2*)&u;
#pragma unroll
        for (int j = 0; j < 4; j++) {
            float2 f = __half22float2(hp[j]);
            s[2 * j] += f.x; s[2 * j + 1] += f.y;
        }
    }
    float* o = out + OFF_ATTN + 8 * i;
#pragma unroll
    for (int j = 0; j < 8; j++) o[j] = s[j] * (1.f / 256.f);
}

__global__ void init_k(float* __restrict__ out)
{
    if (threadIdx.x == 0) { out[OFF_AUX] = 0.f; out[OFF_ZERO] = 0.f; }
}
__global__ void final_k(float* __restrict__ out)
{
    if (threadIdx.x == 0) out[OFF_AUX] *= (1.f / (4.f * 2097152.f));
}

// ---------------------------------------------------------------------------
extern "C" void kernel_launch(void* const* d_in, const int* in_sizes, int n_in,
                              void* d_out, int out_size)
{
    const int*   seq   = (const int*)  d_in[0];
    const float* mems  = (const float*)d_in[2];
    const float* cmems = (const float*)d_in[3];
    const float* emb   = (const float*)d_in[4];
    const float* ln1g  = (const float*)d_in[5];
    const float* ln1b  = (const float*)d_in[6];
    const float* Wq    = (const float*)d_in[7];
    const float* Wkv   = (const float*)d_in[8];
    const float* Wo    = (const float*)d_in[9];
    const float* bo    = (const float*)d_in[10];
    const float* convw = (const float*)d_in[11];
    const float* convb = (const float*)d_in[12];
    const float* ln2g  = (const float*)d_in[13];
    const float* ln2b  = (const float*)d_in[14];
    const float* W1    = (const float*)d_in[15];
    const float* b1    = (const float*)d_in[16];
    const float* W2    = (const float*)d_in[17];
    const float* b2    = (const float*)d_in[18];
    float* out = (float*)d_out;

    __half *hmems, *hcmems, *hxn, *hxn2, *qh, *kvh, *ckvh, *dotsH, *dots2H;
    __half *attnoh, *ffhh, *cmh;
    __half *wqkvTh, *WoTh, *cwh, *W1Th, *W2Th;
    float *o1, *o2, *Ssub;
    cudaGetSymbolAddress((void**)&hmems, g_hmems);   cudaGetSymbolAddress((void**)&hcmems, g_hcmems);
    cudaGetSymbolAddress((void**)&hxn, g_hxn);       cudaGetSymbolAddress((void**)&hxn2, g_hxn2);
    cudaGetSymbolAddress((void**)&qh, g_qh);         cudaGetSymbolAddress((void**)&kvh, g_kvh);
    cudaGetSymbolAddress((void**)&ckvh, g_ckvh);     cudaGetSymbolAddress((void**)&dotsH, g_dotsH);
    cudaGetSymbolAddress((void**)&dots2H, g_dots2H); cudaGetSymbolAddress((void**)&attnoh, g_attnoh);
    cudaGetSymbolAddress((void**)&ffhh, g_ffhh);     cudaGetSymbolAddress((void**)&cmh, g_cmh);
    cudaGetSymbolAddress((void**)&wqkvTh, g_wqkvTh); cudaGetSymbolAddress((void**)&WoTh, g_WoTh);
    cudaGetSymbolAddress((void**)&cwh, g_cwh);       cudaGetSymbolAddress((void**)&W1Th, g_W1Th);
    cudaGetSymbolAddress((void**)&W2Th, g_W2Th);
    cudaGetSymbolAddress((void**)&o1, g_o1);         cudaGetSymbolAddress((void**)&o2, g_o2);
    cudaGetSymbolAddress((void**)&Ssub, g_S);

    const int SM128  = 3 * (128 + 128) * 80;
    const int SM64T  = 3 * (128 * 80 + 32 * 144);
    cudaFuncSetAttribute(hm_gemm<128,0,1,false,false>, cudaFuncAttributeMaxDynamicSharedMemorySize, SM128);
    cudaFuncSetAttribute(hm_gemm<128,1,2,false,false>, cudaFuncAttributeMaxDynamicSharedMemorySize, SM128);
    cudaFuncSetAttribute(hm_gemm<128,2,0,false,false>, cudaFuncAttributeMaxDynamicSharedMemorySize, SM128);
    cudaFuncSetAttribute(hm_gemm<128,3,1,false,false>, cudaFuncAttributeMaxDynamicSharedMemorySize, SM128);
    cudaFuncSetAttribute(hm_gemm<128,0,3,false,false>, cudaFuncAttributeMaxDynamicSharedMemorySize, SM128);
    cudaFuncSetAttribute(hm_gemm<64,0,1,true,true>,    cudaFuncAttributeMaxDynamicSharedMemorySize, SM64T);
    cudaFuncSetAttribute(hm_gemm<64,0,0,true,false>,   cudaFuncAttributeMaxDynamicSharedMemorySize, SM64T);

    float* x   = out;
    float* aux = out + OFF_AUX;

    init_k <<<1, 32>>>(out);
    embed_k<<<8192, 256>>>(seq, emb, x);

    dim3 tb(32, 8);
    tr_k<<<dim3(16,16,4), tb>>>(Wq,  wqkvTh,          512,  512, 262144, 786432);
    tr_k<<<dim3(32,16,4), tb>>>(Wkv, wqkvTh + 262144, 1024, 512, 524288, 786432);
    tr_k<<<dim3(16,16,4), tb>>>(Wo,  WoTh,  512,  512,  262144, 262144);
    tr_k<<<dim3(64,16,4), tb>>>(W1,  W1Th,  2048, 512,  1048576, 1048576);
    tr_k<<<dim3(16,64,4), tb>>>(W2,  W2Th,  512,  2048, 1048576, 1048576);
    convt2_k<<<16384, 256>>>(convw, cwh);
    cvt16_k<<<8192, 256>>>(mems,  hmems,  2097152L);
    cvt16_k<<<2048, 256>>>(cmems, hcmems, 524288L);

    const __half* WkvTh = wqkvTh + 262144;

    // ---- hoisted layer-input GEMMs ----
    hm_gemm<128,0,1,false,false><<<dim3(8,1,32),256,SM128>>>(hcmems, WkvTh, nullptr, kvh,
        512, 512,512,1024, 524288,65536,0, 786432,0,0, 9437184,1179648,0, 8,1, nullptr,0,0,0);
    hm_gemm<128,0,1,false,false><<<dim3(8,4,32),256,SM128>>>(hmems, WkvTh, nullptr, kvh + 131072,
        512, 512,512,1024, 2097152,262144,0, 786432,0,0, 9437184,1179648,0, 8,1, nullptr,0,0,0);
    hm_gemm<128,1,2,false,false><<<dim3(4,8,4),256,SM128>>>(hmems, cwh, out + OFF_CMEMS, cmh,
        2048, 2048,2048,512, 2097152,0,0, 1048576,0,0, 524288,0,0, 1,1, convb,512,0,0);
    hm_gemm<128,0,1,false,false><<<dim3(8,1,32),256,SM128>>>(cmh, WkvTh, nullptr, ckvh,
        512, 512,512,1024, 524288,65536,0, 786432,0,0, 1048576,131072,0, 8,1, nullptr,0,0,0);

    for (int i = 0; i < 4; i++) {
        const __half* wqkvTh_i = wqkvTh + (long)i * 786432;
        const __half* WoTh_i   = WoTh   + (long)i * 262144;
        const __half* W1Th_i   = W1Th   + (long)i * 1048576;
        const __half* W2Th_i   = W2Th   + (long)i * 1048576;
        __half* qh_l    = qh    + (long)i * 2097152;
        __half* kvh_l   = kvh   + (long)i * 9437184;
        __half* dotsH_l = dotsH + (long)i * 37748736;
        float*  o1_l    = o1    + (long)i * 2097152;
        float*  Ssub_l  = Ssub  + (long)i * 32768;
        float*  xn = out + OFF_MEMS + (long)i * 2097152;

        ln_k<<<4096, 128>>>(x, ln1g + i * 512, ln1b + i * 512, xn, hxn);

        hm_gemm<128,0,3,false,false><<<dim3(12,4,8),256,SM128>>>(hxn, wqkvTh_i,
            (float*)(kvh_l + 655360), qh_l,
            512, 512,512,512, 262144,0,0, 0,0,0, 262144,0,1179648, 1,1, nullptr,0,0,0);

        hm_gemm<128,0,1,false,false><<<dim3(9,4,64),256,SM128>>>(qh_l, kvh_l, nullptr, dotsH_l,
            64, 512,1024,1152, 262144,64,0, 1179648,64,0, 4718592,589824,0, 8,1, nullptr,0,0,0);

        softmax1152_k<<<32768,128>>>(dotsH_l, 0.125f, Ssub_l);

        hm_gemm<64,0,1,true,true><<<dim3(1,4,64),256,SM64T>>>(dotsH_l, kvh_l + 512, o1_l, attnoh,
            1152, 1152,1024,512, 4718592,589824,0, 1179648,64,0, 262144,64,0, 8,1,
            nullptr,0, 262144,32768);

        hm_gemm<128,2,0,false,false><<<dim3(4,32,1),256,SM128>>>(attnoh, WoTh_i, x, nullptr,
            512, 512,512,512, 0,0,0, 0,0,0, 0,0,0, 1,1, bo + i * 512, 0,0,0);

        ln_k<<<4096,128>>>(x, ln2g + i * 512, ln2b + i * 512, nullptr, hxn2);
        hm_gemm<128,3,1,false,false><<<dim3(16,32,1),256,SM128>>>(hxn2, W1Th_i, nullptr, ffhh,
            512, 512,512,2048, 0,0,0, 0,0,0, 0,0,0, 1,1, b1 + i * 2048, 0,0,0);
        hm_gemm<128,2,0,false,false><<<dim3(4,32,1),256,SM128>>>(ffhh, W2Th_i, x, nullptr,
            2048, 2048,2048,512, 0,0,0, 0,0,0, 0,0,0, 1,1, b2 + i * 512, 0,0,0);
    }

    // ---- deferred aux-cmem chain ----
    hm_gemm<128,0,1,false,false><<<dim3(1,4,256),256,SM128>>>(qh, ckvh, nullptr, dots2H,
        64, 512,1024,128, 2097152,262144,64, 1048576,131072,64,
        4194304,524288,65536, 8,8, nullptr,0,0,0);
    softmax128w_k<<<16384,256>>>(dots2H, 0.125f);
    hm_gemm<64,0,0,true,false><<<dim3(1,4,256),256,SM64T>>>(dots2H, ckvh + 512, o2, nullptr,
        128, 128,1024,64, 4194304,524288,65536, 1048576,131072,64,
        2097152,262144,32768, 8,8, nullptr,0,0,0);
    mse_k<<<2048,256>>>(o1, o2, Ssub, aux, 8388608L);

    attnsum_k<<<288,256>>>(dotsH, out);
    final_k<<<1,32>>>(out);
}

// round 15
// speedup vs baseline: 7.4251x; 1.0206x over previous
#include <cuda_runtime.h>
#include <cuda_fp16.h>
#include <cstdint>
#include <math.h>

// ---------------------------------------------------------------------------
// CompressiveEncoder forward. FP16 mma.sync + ldmatrix(.trans) + cp.async.
// All weight GEMMs consume [K,N] weights directly (TRB) — no transposes.
// Output: x | new_mems | new_cmems | aux | 0 | attns_mean  (fp32)
// ---------------------------------------------------------------------------

#define OFF_MEMS   2097152L
#define OFF_CMEMS 10485760L
#define OFF_AUX   12582912L
#define OFF_ZERO  12582913L
#define OFF_ATTN  12582914L
#define ATTN_ELEMS 589824L

// -------------------- device scratch ---------------------------------------
__device__ __half g_hmems [8388608];
__device__ __half g_hcmems[2097152];
__device__ __half g_hxn   [2097152];
__device__ __half g_hxn2  [2097152];
__device__ __half g_qh    [8388608];
__device__ __half g_kvh   [37748736];
__device__ __half g_ckvh  [4194304];
__device__ __half g_dotsH [150994944];
__device__ __half g_dots2H[16777216];
__device__ __half g_attnoh[2097152];
__device__ __half g_ffhh  [8388608];
__device__ __half g_cmh   [2097152];
__device__ __half g_wqkv16[6291456];     // [l][512][1536]: cols 0-511 Wq, 512-1535 Wkv
__device__ __half g_hWo   [1048576];     // [l][512][512]
__device__ __half g_cwh   [4194304];     // conv as B^T [N,K] (non-TRB path)
__device__ __half g_hW1   [4194304];     // [l][512][2048]
__device__ __half g_hW2   [4194304];     // [l][2048][512]
__device__ float g_o1 [8388608];
__device__ float g_o2 [8388608];
__device__ float g_S  [131072];

// -------------------- helpers ----------------------------------------------
__device__ __forceinline__ void mma_f16(float* d, uint32_t a0, uint32_t a1,
                                        uint32_t a2, uint32_t a3,
                                        uint32_t b0, uint32_t b1) {
    asm volatile("mma.sync.aligned.m16n8k16.row.col.f32.f16.f16.f32 "
                 "{%0,%1,%2,%3}, {%4,%5,%6,%7}, {%8,%9}, {%0,%1,%2,%3};"
                 : "+f"(d[0]), "+f"(d[1]), "+f"(d[2]), "+f"(d[3])
                 : "r"(a0), "r"(a1), "r"(a2), "r"(a3), "r"(b0), "r"(b1));
}
#define LDSM_X4(r0, r1, r2, r3, addr) \
    asm volatile("ldmatrix.sync.aligned.m8n8.x4.shared.b16 {%0,%1,%2,%3}, [%4];" \
                 : "=r"(r0), "=r"(r1), "=r"(r2), "=r"(r3) : "r"(addr))
#define LDSM_X4_T(r0, r1, r2, r3, addr) \
    asm volatile("ldmatrix.sync.aligned.m8n8.x4.trans.shared.b16 {%0,%1,%2,%3}, [%4];" \
                 : "=r"(r0), "=r"(r1), "=r"(r2), "=r"(r3) : "r"(addr))
#define CP16(saddr, gaddr) \
    asm volatile("cp.async.cg.shared.global [%0], [%1], 16;" :: "r"(saddr), "l"(gaddr))
#define CP_COMMIT() asm volatile("cp.async.commit_group;" ::: "memory")
#define CP_WAIT1()  asm volatile("cp.async.wait_group 1;" ::: "memory")

__device__ __forceinline__ float gelu_f(float v) {
    return 0.5f * v * (1.f + erff(v * 0.70710678118654752f));
}

// -------------------- FP16 GEMM --------------------------------------------
// TRB=false: C[z] = A[z] @ B[z]^T, B stored [N,K].  TRB=true: B [K,N] (.trans)
// 3-level batch: z1=z/(zm2*zm3), z2=(z/zm3)%zm2, z3=z%zm3; off=z1*s1+z2*s2+z3*s3
// EPI: 0 none, 1 +bias, 2 +bias+Cf, 3 gelu(.+bias)
// OUT: 0 f32, 1 f16, 2 both, 3 qkv-split (n<512 -> Ch ld512; else Cf as f16 ld1024)
// AUX: acc snapshot diff over k-tiles [4,20) -> Cf (ldc 64, off z1*sD1+z2*sD2)
template<int BN, int EPI, int OUT, bool TRB, bool AUX>
__global__ void __launch_bounds__(256)
hm_gemm(const __half* __restrict__ A, const __half* __restrict__ B,
        float* __restrict__ Cf, __half* __restrict__ Ch,
        int K, int lda, int ldb, int ldc,
        long sA1, long sA2, long sA3, long sB1, long sB2, long sB3,
        long sC1, long sC2, long sC3, int zm2, int zm3,
        const float* __restrict__ bias, long sBias, long sD1, long sD2)
{
    constexpr int BM = 128, NST = 3;
    constexpr int BNB = BN * 2 + 16;
    constexpr int ABY = BM * 80;
    constexpr int STGB = TRB ? (ABY + 32 * BNB) : ((BM + BN) * 80);
    constexpr int WN = (BN == 128) ? 4 : 2, WM = 8 / WN;
    constexpr int WTM = BM / WM;
    constexpr int MF = WTM / 16;
    constexpr int NBn = (BN == 128) ? 2 : 1;
    constexpr int NBt = (32 * (BN / 8)) / 256;

    extern __shared__ char smc[];
    uint32_t sbase;
    asm("{ .reg .u64 t; cvta.to.shared.u64 t, %1; cvt.u32.u64 %0, t; }"
        : "=r"(sbase) : "l"(smc));

    const int z = blockIdx.z;
    const int z1 = z / (zm2 * zm3);
    const int z2 = (z / zm3) % zm2;
    const int z3 = z % zm3;
    A += z1 * sA1 + z2 * sA2 + z3 * sA3;
    B += z1 * sB1 + z2 * sB2 + z3 * sB3;
    __half* Ch2 = nullptr;
    if (OUT == 3) {
        Ch  += z1 * sC1;
        Ch2 = ((__half*)Cf) + z1 * sC3;
    } else {
        const long coff = z1 * sC1 + z2 * sC2 + z3 * sC3;
        if (OUT != 1) Cf += coff;
        if (OUT >= 1) Ch += coff;
    }
    if (AUX) Cf += z1 * sD1 + z2 * sD2;
    if (EPI >= 1) bias += z1 * sBias;
    const int m0 = blockIdx.y * BM, n0 = blockIdx.x * BN;
    const int tid = threadIdx.x, lane = tid & 31, wid = tid >> 5;
    const int wm = wid % WM, wn = wid / WM;
    const int mbase = wm * WTM, nbase = wn * 32;

    float acc[MF][4][4];
    float acc2[AUX ? MF : 1][4][4];
#pragma unroll
    for (int i = 0; i < MF; i++)
#pragma unroll
        for (int j = 0; j < 4; j++)
#pragma unroll
            for (int r = 0; r < 4; r++) acc[i][j][r] = 0.f;

    const int KT = K >> 5;

    auto issue = [&](int kt, int st) {
        const int k0 = kt << 5;
        const uint32_t s0 = sbase + st * STGB;
#pragma unroll
        for (int i = 0; i < 2; i++) {
            int idx = tid + i * 256, r = idx >> 2, c = idx & 3;
            CP16(s0 + r * 80 + c * 16, A + (long)(m0 + r) * lda + k0 + c * 8);
        }
        if (!TRB) {
#pragma unroll
            for (int i = 0; i < NBn; i++) {
                int idx = tid + i * 256, r = idx >> 2, c = idx & 3;
                CP16(s0 + ABY + r * 80 + c * 16,
                     B + (long)(n0 + r) * ldb + k0 + c * 8);
            }
        } else {
            constexpr int CH = BN / 8;
#pragma unroll
            for (int i = 0; i < NBt; i++) {
                int idx = tid + i * 256, r = idx / CH, c = idx % CH;
                CP16(s0 + ABY + r * BNB + c * 16,
                     B + (long)(k0 + r) * ldb + n0 + c * 8);
            }
        }
    };

    const int g2 = lane >> 3, t7 = lane & 7;
    const uint32_t khalf = ((g2 >> 1) << 4);
    uint32_t aoff[MF], boff[2];
#pragma unroll
    for (int mf = 0; mf < MF; mf++)
        aoff[mf] = (uint32_t)(mbase + mf * 16 + ((g2 & 1) << 3) + t7) * 80 + khalf;
    if (!TRB) {
#pragma unroll
        for (int np = 0; np < 2; np++)
            boff[np] = (uint32_t)ABY +
                       (uint32_t)(nbase + np * 16 + ((g2 & 1) << 3) + t7) * 80 + khalf;
    } else {
#pragma unroll
        for (int np = 0; np < 2; np++)
            boff[np] = (uint32_t)ABY +
                       (uint32_t)(((g2 >> 1) << 3) + t7) * BNB +
                       (uint32_t)(nbase + np * 16 + ((g2 & 1) << 3)) * 2;
    }

    auto compute = [&](int st) {
        const uint32_t s0 = sbase + st * STGB;
#pragma unroll
        for (int ks = 0; ks < 2; ks++) {
            uint32_t a[MF][4], b[2][4];
#pragma unroll
            for (int mf = 0; mf < MF; mf++)
                LDSM_X4(a[mf][0], a[mf][1], a[mf][2], a[mf][3],
                        s0 + aoff[mf] + ks * 32);
#pragma unroll
            for (int np = 0; np < 2; np++) {
                if (!TRB) {
                    LDSM_X4(b[np][0], b[np][1], b[np][2], b[np][3],
                            s0 + boff[np] + ks * 32);
                } else {
                    LDSM_X4_T(b[np][0], b[np][1], b[np][2], b[np][3],
                              s0 + boff[np] + ks * 16 * BNB);
                }
            }
#pragma unroll
            for (int mf = 0; mf < MF; mf++)
#pragma unroll
                for (int np = 0; np < 2; np++) {
                    mma_f16(acc[mf][2 * np],     a[mf][0], a[mf][1], a[mf][2], a[mf][3],
                            b[np][0], b[np][2]);
                    mma_f16(acc[mf][2 * np + 1], a[mf][0], a[mf][1], a[mf][2], a[mf][3],
                            b[np][1], b[np][3]);
                }
        }
    };

    int ldi = 0;
#pragma unroll
    for (int s = 0; s < NST - 1; s++) {
        if (ldi < KT) issue(ldi, s);
        CP_COMMIT();
        ldi++;
    }
    for (int kt = 0; kt < KT; kt++) {
        if (AUX) {
            if (kt == 4) {
#pragma unroll
                for (int i = 0; i < MF; i++)
#pragma unroll
                    for (int j = 0; j < 4; j++)
#pragma unroll
                        for (int r = 0; r < 4; r++) acc2[i][j][r] = acc[i][j][r];
            }
            if (kt == 20) {
#pragma unroll
                for (int i = 0; i < MF; i++)
#pragma unroll
                    for (int j = 0; j < 4; j++)
#pragma unroll
                        for (int r = 0; r < 4; r++)
                            acc2[i][j][r] = acc[i][j][r] - acc2[i][j][r];
            }
        }
        CP_WAIT1();
        __syncthreads();
        compute(kt % NST);
        if (ldi < KT) issue(ldi, ldi % NST);
        CP_COMMIT();
        ldi++;
    }

    const bool qside = (n0 < 512);
    const int rbase = m0 + mbase + (lane >> 2);
    const int cbase = n0 + nbase + 2 * (lane & 3);
#pragma unroll
    for (int mf = 0; mf < MF; mf++) {
#pragma unroll
        for (int nf = 0; nf < 4; nf++) {
#pragma unroll
            for (int half = 0; half < 2; half++) {
                const int m = rbase + mf * 16 + half * 8;
                const int n = cbase + nf * 8;
                float2 v = make_float2(acc[mf][nf][half * 2], acc[mf][nf][half * 2 + 1]);
                if (EPI >= 1) { v.x += bias[n]; v.y += bias[n + 1]; }
                if (OUT == 3) {
                    __half2 h2 = __floats2half2_rn(v.x, v.y);
                    if (qside) *(__half2*)(Ch  + (long)m * 512  + n)        = h2;
                    else       *(__half2*)(Ch2 + (long)m * 1024 + (n - 512)) = h2;
                } else {
                    const long idx = (long)m * ldc + n;
                    if (EPI == 2) { float2 c0 = *(const float2*)(Cf + idx); v.x += c0.x; v.y += c0.y; }
                    if (EPI == 3) { v.x = gelu_f(v.x); v.y = gelu_f(v.y); }
                    if (OUT != 1) *(float2*)(Cf + idx) = v;
                    if (OUT == 1 || OUT == 2) *(__half2*)(Ch + idx) = __floats2half2_rn(v.x, v.y);
                }
                if (AUX) {
                    float2 w = make_float2(acc2[mf][nf][half * 2], acc2[mf][nf][half * 2 + 1]);
                    *(float2*)(Cf + (long)m * 64 + n) = w;
                }
            }
        }
    }
}

// -------------------- conversions ------------------------------------------
// conv weight: cwh[l][o][r*512+c] = conv_w[l][o][c][r]  (B^T layout for non-TRB)
__global__ void convt2_k(const float* __restrict__ w, __half* __restrict__ wt)
{
    long i = (long)blockIdx.x * 256 + threadIdx.x;
    if (i >= 4L * 1048576L) return;
    long l = i >> 20, r0 = i & 1048575L;
    int o = (int)(r0 >> 11), k = (int)(r0 & 2047);
    int r = k >> 9, c = k & 511;
    wt[i] = __float2half(w[l * 1048576L + ((long)o * 512 + c) * 4 + r]);
}

// fp32 -> fp16 contiguous (n4 float4 groups)
__global__ void cvt16_k(const float* __restrict__ in, __half* __restrict__ out, long n4)
{
    long i = (long)blockIdx.x * 256 + threadIdx.x;
    if (i >= n4) return;
    float4 v = ((const float4*)in)[i];
    ((__half2*)out)[2 * i]     = __floats2half2_rn(v.x, v.y);
    ((__half2*)out)[2 * i + 1] = __floats2half2_rn(v.z, v.w);
}

// fp32 [l][R][C] -> fp16 at row pitch P (halves), batched over l
__global__ void cvtpad_k(const float* __restrict__ in, __half* __restrict__ out,
                         int C4, int R, int P, long sOut, long n4)
{
    long i = (long)blockIdx.x * 256 + threadIdx.x;
    if (i >= n4) return;
    long per = (long)R * C4;
    long l = i / per, rem = i - l * per;
    int row = (int)(rem / C4), c4 = (int)(rem - (long)row * C4);
    float4 v = ((const float4*)in)[i];
    __half2* o = (__half2*)(out + l * sOut + (long)row * P + c4 * 4);
    o[0] = __floats2half2_rn(v.x, v.y);
    o[1] = __floats2half2_rn(v.z, v.w);
}

// -------------------- layernorm (float4) ------------------------------------
__global__ void ln_k(const float* __restrict__ x, const float* __restrict__ g,
                     const float* __restrict__ b, float* __restrict__ out,
                     __half* __restrict__ outh)
{
    const long row = blockIdx.x;
    const int tid = threadIdx.x;
    float4 v = ((const float4*)(x + row * 512))[tid];
    float s = v.x + v.y + v.z + v.w;
    __shared__ float sh[4];
#pragma unroll
    for (int o = 16; o; o >>= 1) s += __shfl_xor_sync(0xffffffffu, s, o);
    if ((tid & 31) == 0) sh[tid >> 5] = s;
    __syncthreads();
    const float mu = (sh[0] + sh[1] + sh[2] + sh[3]) * (1.f / 512.f);
    float dx = v.x - mu, dy = v.y - mu, dz = v.z - mu, dw = v.w - mu;
    float s2 = dx * dx + dy * dy + dz * dz + dw * dw;
    __syncthreads();
#pragma unroll
    for (int o = 16; o; o >>= 1) s2 += __shfl_xor_sync(0xffffffffu, s2, o);
    if ((tid & 31) == 0) sh[tid >> 5] = s2;
    __syncthreads();
    const float rs = rsqrtf((sh[0] + sh[1] + sh[2] + sh[3]) * (1.f / 512.f) + 1e-5f);
    const float4 gg = ((const float4*)g)[tid];
    const float4 bb = ((const float4*)b)[tid];
    float4 r;
    r.x = dx * rs * gg.x + bb.x;
    r.y = dy * rs * gg.y + bb.y;
    r.z = dz * rs * gg.z + bb.z;
    r.w = dw * rs * gg.w + bb.w;
    if (out) ((float4*)(out + row * 512))[tid] = r;
    __half2* oh = (__half2*)(outh + row * 512) + 2 * tid;
    oh[0] = __floats2half2_rn(r.x, r.y);
    oh[1] = __floats2half2_rn(r.z, r.w);
}

// -------------------- vectorized softmax L=1152 (128 thr/row) ---------------
__global__ void __launch_bounds__(128)
softmax1152_k(__half* __restrict__ P, float scale, float* __restrict__ subsum)
{
    const long row = blockIdx.x;
    __half* pr = P + row * 1152L;
    const int tid = threadIdx.x, lane = tid & 31, wid = tid >> 5;
    const bool tail = tid < 64;

    uint4 u = ((const uint4*)pr)[tid];
    __half2* hp = (__half2*)&u;
    float v[10];
#pragma unroll
    for (int j = 0; j < 4; j++) {
        float2 f = __half22float2(hp[j]);
        v[2 * j] = f.x * scale; v[2 * j + 1] = f.y * scale;
    }
    v[8] = v[9] = -3.0e38f;
    if (tail) {
        float2 f = __half22float2(((const __half2*)pr)[512 + tid]);
        v[8] = f.x * scale; v[9] = f.y * scale;
    }

    float mx = v[0];
#pragma unroll
    for (int j = 1; j < 10; j++) mx = fmaxf(mx, v[j]);
    __shared__ float sh[4];
#pragma unroll
    for (int o = 16; o; o >>= 1) mx = fmaxf(mx, __shfl_xor_sync(0xffffffffu, mx, o));
    if (lane == 0) sh[wid] = mx;
    __syncthreads();
    const float bm = fmaxf(fmaxf(sh[0], sh[1]), fmaxf(sh[2], sh[3]));

    float s = 0.f;
#pragma unroll
    for (int j = 0; j < 10; j++) { float e = __expf(v[j] - bm); v[j] = e; s += e; }
    float ssub = 0.f;
    if (tid >= 16 && tid < 80) {
#pragma unroll
        for (int j = 0; j < 8; j++) ssub += v[j];
    }
    __syncthreads();
#pragma unroll
    for (int o = 16; o; o >>= 1) s += __shfl_xor_sync(0xffffffffu, s, o);
    if (lane == 0) sh[wid] = s;
    __syncthreads();
    const float tot = sh[0] + sh[1] + sh[2] + sh[3];
    const float inv = 1.f / tot;

    __syncthreads();
#pragma unroll
    for (int o = 16; o; o >>= 1) ssub += __shfl_xor_sync(0xffffffffu, ssub, o);
    if (lane == 0) sh[wid] = ssub;
    __syncthreads();
    if (tid == 0 && subsum)
        subsum[row] = (sh[0] + sh[1] + sh[2] + sh[3]) * inv;

#pragma unroll
    for (int j = 0; j < 4; j++)
        hp[j] = __floats2half2_rn(v[2 * j] * inv, v[2 * j + 1] * inv);
    ((uint4*)pr)[tid] = u;
    if (tail)
        ((__half2*)pr)[512 + tid] = __floats2half2_rn(v[8] * inv, v[9] * inv);
}

// -------------------- warp-per-row softmax L=128 ----------------------------
__global__ void __launch_bounds__(256)
softmax128w_k(__half* __restrict__ P, float scale)
{
    const long row = (long)blockIdx.x * 8 + (threadIdx.x >> 5);
    const int lane = threadIdx.x & 31;
    __half* pr = P + row * 128L;
    uint2 u = ((const uint2*)pr)[lane];
    __half2* hp = (__half2*)&u;
    float2 f0 = __half22float2(hp[0]), f1 = __half22float2(hp[1]);
    float v0 = f0.x * scale, v1 = f0.y * scale, v2 = f1.x * scale, v3 = f1.y * scale;
    float mx = fmaxf(fmaxf(v0, v1), fmaxf(v2, v3));
#pragma unroll
    for (int o = 16; o; o >>= 1) mx = fmaxf(mx, __shfl_xor_sync(0xffffffffu, mx, o));
    float e0 = __expf(v0 - mx), e1 = __expf(v1 - mx);
    float e2 = __expf(v2 - mx), e3 = __expf(v3 - mx);
    float s = e0 + e1 + e2 + e3;
#pragma unroll
    for (int o = 16; o; o >>= 1) s += __shfl_xor_sync(0xffffffffu, s, o);
    const float inv = 1.f / s;
    hp[0] = __floats2half2_rn(e0 * inv, e1 * inv);
    hp[1] = __floats2half2_rn(e2 * inv, e3 * inv);
    ((uint2*)pr)[lane] = u;
}

// -------------------- embed / mse / attnsum / init / final ------------------
__global__ void embed_k(const int* __restrict__ seq, const float* __restrict__ emb,
                        float* __restrict__ x)
{
    long i = (long)blockIdx.x * blockDim.x + threadIdx.x;
    if (i >= 2097152L) return;
    int d = (int)(i & 511);
    long bt = i >> 9;
    int t = (int)(bt & 511);
    int tok = seq[bt];
    int j2 = d & ~1;
    float ang = (float)t * expf(-0.017988946039015984f * (float)j2);
    float pe = (d & 1) ? cosf(ang) : sinf(ang);
    x[i] = emb[(long)tok * 512 + d] + pe;
}

__global__ void mse_k(const float* __restrict__ a, const float* __restrict__ b,
                      const float* __restrict__ S, float* __restrict__ outScalar, long n)
{
    long i0 = (long)blockIdx.x * blockDim.x + threadIdx.x;
    long stride = (long)gridDim.x * blockDim.x;
    float s = 0.f;
    for (long i = i0; i < n; i += stride) {
        float d = a[i] / S[i >> 6] - b[i];
        s += d * d;
    }
    __shared__ float sh[8];
#pragma unroll
    for (int o = 16; o; o >>= 1) s += __shfl_xor_sync(0xffffffffu, s, o);
    int tid = threadIdx.x;
    if ((tid & 31) == 0) sh[tid >> 5] = s;
    __syncthreads();
    if (tid == 0) {
        float tot = 0.f;
#pragma unroll
        for (int w = 0; w < 8; w++) tot += sh[w];
        atomicAdd(outScalar, tot);
    }
}

__global__ void attnsum_k(const __half* __restrict__ dotsH, float* __restrict__ out)
{
    long i = (long)blockIdx.x * 256 + threadIdx.x;
    if (i >= 73728L) return;
    const uint4* p = (const uint4*)dotsH + i;
    float s[8];
#pragma unroll
    for (int j = 0; j < 8; j++) s[j] = 0.f;
#pragma unroll 4
    for (int sl = 0; sl < 256; sl++) {
        uint4 u = p[(long)sl * 73728L];
        const __half2* hp = (const __half2*)&u;
#pragma unroll
        for (int j = 0; j < 4; j++) {
            float2 f = __half22float2(hp[j]);
            s[2 * j] += f.x; s[2 * j + 1] += f.y;
        }
    }
    float* o = out + OFF_ATTN + 8 * i;
#pragma unroll
    for (int j = 0; j < 8; j++) o[j] = s[j] * (1.f / 256.f);
}

__global__ void init_k(float* __restrict__ out)
{
    if (threadIdx.x == 0) { out[OFF_AUX] = 0.f; out[OFF_ZERO] = 0.f; }
}
__global__ void final_k(float* __restrict__ out)
{
    if (threadIdx.x == 0) out[OFF_AUX] *= (1.f / (4.f * 2097152.f));
}

// ---------------------------------------------------------------------------
extern "C" void kernel_launch(void* const* d_in, const int* in_sizes, int n_in,
                              void* d_out, int out_size)
{
    const int*   seq   = (const int*)  d_in[0];
    const float* mems  = (const float*)d_in[2];
    const float* cmems = (const float*)d_in[3];
    const float* emb   = (const float*)d_in[4];
    const float* ln1g  = (const float*)d_in[5];
    const float* ln1b  = (const float*)d_in[6];
    const float* Wq    = (const float*)d_in[7];
    const float* Wkv   = (const float*)d_in[8];
    const float* Wo    = (const float*)d_in[9];
    const float* bo    = (const float*)d_in[10];
    const float* convw = (const float*)d_in[11];
    const float* convb = (const float*)d_in[12];
    const float* ln2g  = (const float*)d_in[13];
    const float* ln2b  = (const float*)d_in[14];
    const float* W1    = (const float*)d_in[15];
    const float* b1    = (const float*)d_in[16];
    const float* W2    = (const float*)d_in[17];
    const float* b2    = (const float*)d_in[18];
    float* out = (float*)d_out;

    __half *hmems, *hcmems, *hxn, *hxn2, *qh, *kvh, *ckvh, *dotsH, *dots2H;
    __half *attnoh, *ffhh, *cmh;
    __half *wqkv16, *hWo, *cwh, *hW1, *hW2;
    float *o1, *o2, *Ssub;
    cudaGetSymbolAddress((void**)&hmems, g_hmems);   cudaGetSymbolAddress((void**)&hcmems, g_hcmems);
    cudaGetSymbolAddress((void**)&hxn, g_hxn);       cudaGetSymbolAddress((void**)&hxn2, g_hxn2);
    cudaGetSymbolAddress((void**)&qh, g_qh);         cudaGetSymbolAddress((void**)&kvh, g_kvh);
    cudaGetSymbolAddress((void**)&ckvh, g_ckvh);     cudaGetSymbolAddress((void**)&dotsH, g_dotsH);
    cudaGetSymbolAddress((void**)&dots2H, g_dots2H); cudaGetSymbolAddress((void**)&attnoh, g_attnoh);
    cudaGetSymbolAddress((void**)&ffhh, g_ffhh);     cudaGetSymbolAddress((void**)&cmh, g_cmh);
    cudaGetSymbolAddress((void**)&wqkv16, g_wqkv16); cudaGetSymbolAddress((void**)&hWo, g_hWo);
    cudaGetSymbolAddress((void**)&cwh, g_cwh);       cudaGetSymbolAddress((void**)&hW1, g_hW1);
    cudaGetSymbolAddress((void**)&hW2, g_hW2);
    cudaGetSymbolAddress((void**)&o1, g_o1);         cudaGetSymbolAddress((void**)&o2, g_o2);
    cudaGetSymbolAddress((void**)&Ssub, g_S);

    const int SM128  = 3 * (128 + 128) * 80;               // 61440
    const int SM128T = 3 * (128 * 80 + 32 * 272);          // 56832
    const int SM64T  = 3 * (128 * 80 + 32 * 144);          // 44544
    cudaFuncSetAttribute(hm_gemm<128,0,1,false,false>, cudaFuncAttributeMaxDynamicSharedMemorySize, SM128);
    cudaFuncSetAttribute(hm_gemm<128,1,2,false,false>, cudaFuncAttributeMaxDynamicSharedMemorySize, SM128);
    cudaFuncSetAttribute(hm_gemm<128,0,1,true,false>,  cudaFuncAttributeMaxDynamicSharedMemorySize, SM128T);
    cudaFuncSetAttribute(hm_gemm<128,2,0,true,false>,  cudaFuncAttributeMaxDynamicSharedMemorySize, SM128T);
    cudaFuncSetAttribute(hm_gemm<128,3,1,true,false>,  cudaFuncAttributeMaxDynamicSharedMemorySize, SM128T);
    cudaFuncSetAttribute(hm_gemm<128,0,3,true,false>,  cudaFuncAttributeMaxDynamicSharedMemorySize, SM128T);
    cudaFuncSetAttribute(hm_gemm<64,0,1,true,true>,    cudaFuncAttributeMaxDynamicSharedMemorySize, SM64T);
    cudaFuncSetAttribute(hm_gemm<64,0,0,true,false>,   cudaFuncAttributeMaxDynamicSharedMemorySize, SM64T);

    float* x   = out;
    float* aux = out + OFF_AUX;

    init_k <<<1, 32>>>(out);
    embed_k<<<8192, 256>>>(seq, emb, x);

    // ---- one-time conversions (no transposes) ----
    cvtpad_k<<<1024, 256>>>(Wq,  wqkv16,       128, 512, 1536, 786432, 262144L);
    cvtpad_k<<<2048, 256>>>(Wkv, wqkv16 + 512, 256, 512, 1536, 786432, 524288L);
    cvt16_k<<<1024, 256>>>(Wo, hWo, 262144L);
    cvt16_k<<<4096, 256>>>(W1, hW1, 1048576L);
    cvt16_k<<<4096, 256>>>(W2, hW2, 1048576L);
    convt2_k<<<16384, 256>>>(convw, cwh);
    cvt16_k<<<8192, 256>>>(mems,  hmems,  2097152L);
    cvt16_k<<<2048, 256>>>(cmems, hcmems, 524288L);

    const __half* Wkv16 = wqkv16 + 512;   // [K=512, N=1024] at pitch 1536

    // ---- hoisted layer-input GEMMs (z = l*8+b) ----
    hm_gemm<128,0,1,true,false><<<dim3(8,1,32),256,SM128T>>>(hcmems, Wkv16, nullptr, kvh,
        512, 512,1536,1024, 524288,65536,0, 786432,0,0, 9437184,1179648,0, 8,1, nullptr,0,0,0);
    hm_gemm<128,0,1,true,false><<<dim3(8,4,32),256,SM128T>>>(hmems, Wkv16, nullptr, kvh + 131072,
        512, 512,1536,1024, 2097152,262144,0, 786432,0,0, 9437184,1179648,0, 8,1, nullptr,0,0,0);
    hm_gemm<128,1,2,false,false><<<dim3(4,8,4),256,SM128>>>(hmems, cwh, out + OFF_CMEMS, cmh,
        2048, 2048,2048,512, 2097152,0,0, 1048576,0,0, 524288,0,0, 1,1, convb,512,0,0);
    hm_gemm<128,0,1,true,false><<<dim3(8,1,32),256,SM128T>>>(cmh, Wkv16, nullptr, ckvh,
        512, 512,1536,1024, 524288,65536,0, 786432,0,0, 1048576,131072,0, 8,1, nullptr,0,0,0);

    for (int i = 0; i < 4; i++) {
        const __half* wqkv16_i = wqkv16 + (long)i * 786432;
        const __half* hWo_i    = hWo    + (long)i * 262144;
        const __half* hW1_i    = hW1    + (long)i * 1048576;
        const __half* hW2_i    = hW2    + (long)i * 1048576;
        __half* qh_l    = qh    + (long)i * 2097152;
        __half* kvh_l   = kvh   + (long)i * 9437184;
        __half* dotsH_l = dotsH + (long)i * 37748736;
        float*  o1_l    = o1    + (long)i * 2097152;
        float*  Ssub_l  = Ssub  + (long)i * 32768;
        float*  xn = out + OFF_MEMS + (long)i * 2097152;

        ln_k<<<4096, 128>>>(x, ln1g + i * 512, ln1b + i * 512, xn, hxn);

        // fused q|kv(xn) projection (TRB: B = [512,1536])
        hm_gemm<128,0,3,true,false><<<dim3(12,4,8),256,SM128T>>>(hxn, wqkv16_i,
            (float*)(kvh_l + 655360), qh_l,
            512, 512,1536,512, 262144,0,0, 0,0,0, 262144,0,1179648, 1,1, nullptr,0,0,0);

        // logits = q @ k^T -> fp16
        hm_gemm<128,0,1,false,false><<<dim3(9,4,64),256,SM128>>>(qh_l, kvh_l, nullptr, dotsH_l,
            64, 512,1024,1152, 262144,64,0, 1179648,64,0, 4718592,589824,0, 8,1, nullptr,0,0,0);

        softmax1152_k<<<32768,128>>>(dotsH_l, 0.125f, Ssub_l);

        // attno = P @ v (TRB), fused aux-o1
        hm_gemm<64,0,1,true,true><<<dim3(1,4,64),256,SM64T>>>(dotsH_l, kvh_l + 512, o1_l, attnoh,
            1152, 1152,1024,512, 4718592,589824,0, 1179648,64,0, 262144,64,0, 8,1,
            nullptr,0, 262144,32768);

        // x = attno @ Wo + bo + x  (TRB)
        hm_gemm<128,2,0,true,false><<<dim3(4,32,1),256,SM128T>>>(attnoh, hWo_i, x, nullptr,
            512, 512,512,512, 0,0,0, 0,0,0, 0,0,0, 1,1, bo + i * 512, 0,0,0);

        // FFN (TRB)
        ln_k<<<4096,128>>>(x, ln2g + i * 512, ln2b + i * 512, nullptr, hxn2);
        hm_gemm<128,3,1,true,false><<<dim3(16,32,1),256,SM128T>>>(hxn2, hW1_i, nullptr, ffhh,
            512, 512,2048,2048, 0,0,0, 0,0,0, 0,0,0, 1,1, b1 + i * 2048, 0,0,0);
        hm_gemm<128,2,0,true,false><<<dim3(4,32,1),256,SM128T>>>(ffhh, hW2_i, x, nullptr,
            2048, 2048,512,512, 0,0,0, 0,0,0, 0,0,0, 1,1, b2 + i * 512, 0,0,0);
    }

    // ---- deferred aux-cmem chain ----
    hm_gemm<128,0,1,false,false><<<dim3(1,4,256),256,SM128>>>(qh, ckvh, nullptr, dots2H,
        64, 512,1024,128, 2097152,262144,64, 1048576,131072,64,
        4194304,524288,65536, 8,8, nullptr,0,0,0);
    softmax128w_k<<<16384,256>>>(dots2H, 0.125f);
    hm_gemm<64,0,0,true,false><<<dim3(1,4,256),256,SM64T>>>(dots2H, ckvh + 512, o2, nullptr,
        128, 128,1024,64, 4194304,524288,65536, 1048576,131072,64,
        2097152,262144,32768, 8,8, nullptr,0,0,0);
    mse_k<<<2048,256>>>(o1, o2, Ssub, aux, 8388608L);

    attnsum_k<<<288,256>>>(dotsH, out);
    final_k<<<1,32>>>(out);
}